// round 1
// baseline (speedup 1.0000x reference)
#include <cuda_runtime.h>

#define HH 192
#define WW 320
#define BB 2

// -------- scratch (device globals; no allocations allowed) --------
__device__ float g_cat [BB * 130 * HH * WW];  // concat(warped, ref, flows)
__device__ float g_off1[BB *  64 * HH * WW];
__device__ float g_off2[BB *  64 * HH * WW];
__device__ float g_om  [BB * 216 * HH * WW];

// ---------------- concat ----------------
__global__ void concat_k(const float* __restrict__ warped,
                         const float* __restrict__ ref,
                         const float* __restrict__ flows)
{
    int idx = blockIdx.x * blockDim.x + threadIdx.x;
    const int total = BB * 130 * HH * WW;
    if (idx >= total) return;
    int hw = idx % (HH * WW);
    int c  = (idx / (HH * WW)) % 130;
    int b  = idx / (130 * HH * WW);
    float v;
    if (c < 64)        v = warped[(b * 64 + c)        * HH * WW + hw];
    else if (c < 128)  v = ref   [(b * 64 + (c - 64)) * HH * WW + hw];
    else               v = flows [(b * 2  + (c - 128))* HH * WW + hw];
    g_cat[idx] = v;
}

// ---------------- direct 3x3 conv, pad 1 ----------------
// block = 128 threads -> 32x4 pixel tile, 32 out-channels per thread.
// grid: (WW/32, HH/4, B * ceil(COUT/32))
template<bool LRELU>
__global__ __launch_bounds__(128)
void conv3x3_k(const float* __restrict__ in, int CIN,
               const float* __restrict__ wgt, const float* __restrict__ bias,
               int COUT, float* __restrict__ out)
{
    const int nOcB = (COUT + 31) / 32;
    const int b    = blockIdx.z / nOcB;
    const int oc0  = (blockIdx.z % nOcB) * 32;
    const int px   = threadIdx.x & 31;
    const int py   = threadIdx.x >> 5;
    const int gx   = blockIdx.x * 32 + px;
    const int gy   = blockIdx.y * 4 + py;
    const int tid  = threadIdx.x;

    __shared__ float sIn[8][6][36];     // [ci][row][col] (cols padded)
    __shared__ float sW [8][9][32];     // [ci][k][oc]

    float acc[32];
#pragma unroll
    for (int i = 0; i < 32; i++) acc[i] = 0.f;

    for (int ci0 = 0; ci0 < CIN; ci0 += 8) {
        const int cn = min(8, CIN - ci0);
        __syncthreads();
        // stage input halo tile
        for (int i = tid; i < 8 * 6 * 34; i += 128) {
            int col = i % 34;
            int row = (i / 34) % 6;
            int ci  = i / (34 * 6);
            float v = 0.f;
            if (ci < cn) {
                int yy = blockIdx.y * 4 + row - 1;
                int xx = blockIdx.x * 32 + col - 1;
                if (yy >= 0 && yy < HH && xx >= 0 && xx < WW)
                    v = in[((size_t)(b * CIN + ci0 + ci) * HH + yy) * WW + xx];
            }
            sIn[ci][row][col] = v;
        }
        // stage weight slice (zero-padded past COUT / past cn)
        for (int i = tid; i < 8 * 9 * 32; i += 128) {
            int oc = i & 31;
            int k  = (i >> 5) % 9;
            int ci = i / (32 * 9);
            float v = 0.f;
            if (ci < cn && oc0 + oc < COUT)
                v = wgt[((size_t)(oc0 + oc) * CIN + ci0 + ci) * 9 + k];
            sW[ci][k][oc] = v;
        }
        __syncthreads();

#pragma unroll
        for (int ci = 0; ci < 8; ci++) {
            float v[9];
#pragma unroll
            for (int dy = 0; dy < 3; dy++)
#pragma unroll
                for (int dx = 0; dx < 3; dx++)
                    v[dy * 3 + dx] = sIn[ci][py + dy][px + dx];
#pragma unroll
            for (int k = 0; k < 9; k++) {
                const float4* w4p = (const float4*)&sW[ci][k][0];
#pragma unroll
                for (int q = 0; q < 8; q++) {
                    float4 w4 = w4p[q];
                    acc[q * 4 + 0] += v[k] * w4.x;
                    acc[q * 4 + 1] += v[k] * w4.y;
                    acc[q * 4 + 2] += v[k] * w4.z;
                    acc[q * 4 + 3] += v[k] * w4.w;
                }
            }
        }
    }

#pragma unroll
    for (int q = 0; q < 32; q++) {
        int oc = oc0 + q;
        if (oc < COUT) {
            float r = acc[q] + bias[oc];
            if (LRELU) r = (r >= 0.f) ? r : 0.1f * r;
            out[((size_t)(b * COUT + oc) * HH + gy) * WW + gx] = r;
        }
    }
}

// ---------------- flow-guided DCN + lrelu ----------------
// block = 128 threads -> 32x4 pixel tile; each thread owns all 64 out channels.
// grid: (WW/32, HH/4, B)
__global__ __launch_bounds__(128)
void dcn_k(const float* __restrict__ x,        // nbr_fea_l
           const float* __restrict__ flows,
           const float* __restrict__ wdcn,
           const float* __restrict__ bdcn,
           float* __restrict__ out)
{
    const int b  = blockIdx.z;
    const int px = threadIdx.x & 31;
    const int py = threadIdx.x >> 5;
    const int w  = blockIdx.x * 32 + px;
    const int h  = blockIdx.y * 4 + py;
    const int tid = threadIdx.x;

    __shared__ float sW[8][9][64];   // [c][k][oc] for current group

    float acc[64];
#pragma unroll
    for (int i = 0; i < 64; i++) acc[i] = 0.f;

    // flows[:, ::-1] channel swap: y-offset gets flows ch1, x-offset gets ch0
    const float flowx = flows[((size_t)(b * 2 + 0) * HH + h) * WW + w];
    const float flowy = flows[((size_t)(b * 2 + 1) * HH + h) * WW + w];

    const float* omb = g_om + (size_t)b * 216 * HH * WW + (size_t)h * WW + w;
    const size_t CH = (size_t)HH * WW;

    for (int g = 0; g < 8; g++) {
        __syncthreads();
        for (int i = tid; i < 8 * 9 * 64; i += 128) {
            int oc = i & 63;
            int k  = (i >> 6) % 9;
            int c  = i / (64 * 9);
            sW[c][k][oc] = wdcn[((size_t)oc * 64 + g * 8 + c) * 9 + k];
        }
        __syncthreads();

        const float* xg = x + (size_t)(b * 64 + g * 8) * CH;
#pragma unroll
        for (int k = 0; k < 9; k++) {
            const int ky = k / 3 - 1;
            const int kx = k % 3 - 1;
            float oy = omb[(size_t)(2 * (g * 9 + k))     * CH] + flowy;
            float ox = omb[(size_t)(2 * (g * 9 + k) + 1) * CH] + flowx;
            float mv = omb[(size_t)(144 + g * 9 + k)     * CH];
            mv = 1.f / (1.f + __expf(-mv));

            float pyf = (float)(h + ky) + oy;
            float pxf = (float)(w + kx) + ox;
            float y0f = floorf(pyf), x0f = floorf(pxf);
            float wy = pyf - y0f, wx = pxf - x0f;
            int iy0 = (int)y0f, ix0 = (int)x0f;
            int iy1 = iy0 + 1, ix1 = ix0 + 1;
            bool vy0 = (iy0 >= 0) & (iy0 < HH);
            bool vy1 = (iy1 >= 0) & (iy1 < HH);
            bool vx0 = (ix0 >= 0) & (ix0 < WW);
            bool vx1 = (ix1 >= 0) & (ix1 < WW);
            int cy0 = min(max(iy0, 0), HH - 1), cy1 = min(max(iy1, 0), HH - 1);
            int cx0 = min(max(ix0, 0), WW - 1), cx1 = min(max(ix1, 0), WW - 1);
            float w00 = (1.f - wy) * (1.f - wx) * ((vy0 && vx0) ? 1.f : 0.f) * mv;
            float w01 = (1.f - wy) * wx         * ((vy0 && vx1) ? 1.f : 0.f) * mv;
            float w10 = wy * (1.f - wx)         * ((vy1 && vx0) ? 1.f : 0.f) * mv;
            float w11 = wy * wx                 * ((vy1 && vx1) ? 1.f : 0.f) * mv;
            int i00 = cy0 * WW + cx0, i01 = cy0 * WW + cx1;
            int i10 = cy1 * WW + cx0, i11 = cy1 * WW + cx1;

#pragma unroll
            for (int c = 0; c < 8; c++) {
                const float* xc = xg + (size_t)c * CH;
                float s = xc[i00] * w00 + xc[i01] * w01 + xc[i10] * w10 + xc[i11] * w11;
                const float4* w4p = (const float4*)&sW[c][k][0];
#pragma unroll
                for (int q = 0; q < 16; q++) {
                    float4 w4 = w4p[q];
                    acc[q * 4 + 0] += s * w4.x;
                    acc[q * 4 + 1] += s * w4.y;
                    acc[q * 4 + 2] += s * w4.z;
                    acc[q * 4 + 3] += s * w4.w;
                }
            }
        }
    }

#pragma unroll
    for (int o = 0; o < 64; o++) {
        float r = acc[o] + bdcn[o];
        r = (r >= 0.f) ? r : 0.1f * r;
        out[((size_t)(b * 64 + o) * HH + h) * WW + w] = r;
    }
}

// ---------------- launch ----------------
extern "C" void kernel_launch(void* const* d_in, const int* in_sizes, int n_in,
                              void* d_out, int out_size)
{
    const float* nbr    = (const float*)d_in[0];
    const float* warped = (const float*)d_in[1];
    const float* ref    = (const float*)d_in[2];
    const float* flows  = (const float*)d_in[3];
    const float* w1     = (const float*)d_in[4];
    const float* b1     = (const float*)d_in[5];
    const float* w2     = (const float*)d_in[6];
    const float* b2     = (const float*)d_in[7];
    const float* w_om   = (const float*)d_in[8];
    const float* b_om   = (const float*)d_in[9];
    const float* w_dcn  = (const float*)d_in[10];
    const float* b_dcn  = (const float*)d_in[11];
    float* out = (float*)d_out;

    float *p_cat, *p_off1, *p_off2, *p_om;
    cudaGetSymbolAddress((void**)&p_cat,  g_cat);
    cudaGetSymbolAddress((void**)&p_off1, g_off1);
    cudaGetSymbolAddress((void**)&p_off2, g_off2);
    cudaGetSymbolAddress((void**)&p_om,   g_om);

    // 1. concat
    {
        int total = BB * 130 * HH * WW;
        concat_k<<<(total + 255) / 256, 256>>>(warped, ref, flows);
    }
    dim3 tiles(WW / 32, HH / 4, 1);

    // 2. conv1: 130 -> 64, lrelu
    {
        dim3 grid(tiles.x, tiles.y, BB * 2);
        conv3x3_k<true><<<grid, 128>>>(p_cat, 130, w1, b1, 64, p_off1);
    }
    // 3. conv2: 64 -> 64, lrelu
    {
        dim3 grid(tiles.x, tiles.y, BB * 2);
        conv3x3_k<true><<<grid, 128>>>(p_off1, 64, w2, b2, 64, p_off2);
    }
    // 4. conv_om: 64 -> 216, linear
    {
        dim3 grid(tiles.x, tiles.y, BB * 7);
        conv3x3_k<false><<<grid, 128>>>(p_off2, 64, w_om, b_om, 216, p_om);
    }
    // 5. DCN + lrelu
    {
        dim3 grid(tiles.x, tiles.y, BB);
        dcn_k<<<grid, 128>>>(nbr, flows, w_dcn, b_dcn, out);
    }
}

// round 2
// speedup vs baseline: 1.0345x; 1.0345x over previous
#include <cuda_runtime.h>

#define HH 192
#define WW 320
#define BB 2

// -------- scratch (device globals; no allocations allowed) --------
__device__ float g_off1[BB *  64 * HH * WW];
__device__ float g_off2[BB *  64 * HH * WW];
__device__ float g_om  [BB * 216 * HH * WW];

// ---------------- direct 3x3 conv, pad 1, register-blocked ----------------
// block = 128 threads. Tile = 32 wide x 16 tall. Each thread: 4 vertical
// pixels x 16 output channels (acc[4][16]). ci chunked by 8.
// grid: (WW/32, HH/16, B * ceil(COUT/16))
template<bool LRELU, bool CAT>
__global__ __launch_bounds__(128, 4)
void conv3x3_k(const float* __restrict__ in, int CIN,
               const float* __restrict__ wgt, const float* __restrict__ bias,
               int COUT, float* __restrict__ out,
               const float* __restrict__ ref,     // CAT only
               const float* __restrict__ flows)   // CAT only
{
    const int nOcB = (COUT + 15) / 16;
    const int b    = blockIdx.z / nOcB;
    const int oc0  = (blockIdx.z % nOcB) * 16;
    const int px   = threadIdx.x & 31;
    const int py0  = (threadIdx.x >> 5) * 4;      // 0,4,8,12
    const int gx0  = blockIdx.x * 32;
    const int gy0  = blockIdx.y * 16;
    const int tid  = threadIdx.x;

    __shared__ __align__(16) float sIn[8][18][36]; // [ci][row][col], origin (-1,-1)
    __shared__ __align__(16) float sW [8][9][16];  // [ci][k][oc]

    float acc[4][16];
#pragma unroll
    for (int p = 0; p < 4; p++)
#pragma unroll
        for (int q = 0; q < 16; q++) acc[p][q] = 0.f;

    for (int ci0 = 0; ci0 < CIN; ci0 += 8) {
        __syncthreads();
        // ---- stage input halo tile (18 rows x 34 cols per ci) ----
        for (int i = tid; i < 8 * 18 * 34; i += 128) {
            int c  = i % 34;
            int r  = (i / 34) % 18;
            int ci = i / (34 * 18);
            int cig = ci0 + ci;
            float v = 0.f;
            if (cig < CIN) {
                int yy = gy0 - 1 + r;
                int xx = gx0 - 1 + c;
                if (yy >= 0 && yy < HH && xx >= 0 && xx < WW) {
                    if (!CAT) {
                        v = in[((size_t)(b * CIN + cig) * HH + yy) * WW + xx];
                    } else {
                        const float* src; int cc;
                        if (cig < 64)       { src = in;    cc = b * 64 + cig; }
                        else if (cig < 128) { src = ref;   cc = b * 64 + (cig - 64); }
                        else                { src = flows; cc = b * 2  + (cig - 128); }
                        v = src[((size_t)cc * HH + yy) * WW + xx];
                    }
                }
            }
            sIn[ci][r][c] = v;
        }
        // ---- stage weight slice (zero-pad past CIN / COUT) ----
        for (int i = tid; i < 8 * 9 * 16; i += 128) {
            int oc = i & 15;
            int k  = (i >> 4) % 9;
            int ci = i / (16 * 9);
            float v = 0.f;
            if (ci0 + ci < CIN && oc0 + oc < COUT)
                v = wgt[((size_t)(oc0 + oc) * CIN + ci0 + ci) * 9 + k];
            sW[ci][k][oc] = v;
        }
        __syncthreads();

#pragma unroll
        for (int ci = 0; ci < 8; ci++) {
            float v[6][3];
#pragma unroll
            for (int r = 0; r < 6; r++)
#pragma unroll
                for (int c = 0; c < 3; c++)
                    v[r][c] = sIn[ci][py0 + r][px + c];
#pragma unroll
            for (int k = 0; k < 9; k++) {
                const int dy = k / 3, dx = k % 3;
                const float4* w4p = (const float4*)&sW[ci][k][0];
                float4 w0 = w4p[0], w1 = w4p[1], w2 = w4p[2], w3 = w4p[3];
#pragma unroll
                for (int p = 0; p < 4; p++) {
                    float s = v[p + dy][dx];
                    acc[p][0]  += s * w0.x;  acc[p][1]  += s * w0.y;
                    acc[p][2]  += s * w0.z;  acc[p][3]  += s * w0.w;
                    acc[p][4]  += s * w1.x;  acc[p][5]  += s * w1.y;
                    acc[p][6]  += s * w1.z;  acc[p][7]  += s * w1.w;
                    acc[p][8]  += s * w2.x;  acc[p][9]  += s * w2.y;
                    acc[p][10] += s * w2.z;  acc[p][11] += s * w2.w;
                    acc[p][12] += s * w3.x;  acc[p][13] += s * w3.y;
                    acc[p][14] += s * w3.z;  acc[p][15] += s * w3.w;
                }
            }
        }
    }

#pragma unroll
    for (int q = 0; q < 16; q++) {
        int oc = oc0 + q;
        if (oc < COUT) {
            float bv = bias[oc];
#pragma unroll
            for (int p = 0; p < 4; p++) {
                float r = acc[p][q] + bv;
                if (LRELU) r = (r >= 0.f) ? r : 0.1f * r;
                out[((size_t)(b * COUT + oc) * HH + (gy0 + py0 + p)) * WW + (gx0 + px)] = r;
            }
        }
    }
}

// ---------------- flow-guided DCN + lrelu ----------------
// block = 128 threads -> 32x4 pixel tile; each thread owns all 64 out channels.
// grid: (WW/32, HH/4, B)
__global__ __launch_bounds__(128)
void dcn_k(const float* __restrict__ x,        // nbr_fea_l
           const float* __restrict__ flows,
           const float* __restrict__ wdcn,
           const float* __restrict__ bdcn,
           float* __restrict__ out)
{
    const int b  = blockIdx.z;
    const int px = threadIdx.x & 31;
    const int py = threadIdx.x >> 5;
    const int w  = blockIdx.x * 32 + px;
    const int h  = blockIdx.y * 4 + py;
    const int tid = threadIdx.x;

    __shared__ __align__(16) float sW[8][9][64];   // [c][k][oc] for current group

    float acc[64];
#pragma unroll
    for (int i = 0; i < 64; i++) acc[i] = 0.f;

    // flows[:, ::-1] channel swap: y-offset gets flows ch1, x-offset gets ch0
    const float flowx = flows[((size_t)(b * 2 + 0) * HH + h) * WW + w];
    const float flowy = flows[((size_t)(b * 2 + 1) * HH + h) * WW + w];

    const float* omb = g_om + (size_t)b * 216 * HH * WW + (size_t)h * WW + w;
    const size_t CH = (size_t)HH * WW;

    for (int g = 0; g < 8; g++) {
        __syncthreads();
        for (int i = tid; i < 8 * 9 * 64; i += 128) {
            int oc = i & 63;
            int k  = (i >> 6) % 9;
            int c  = i / (64 * 9);
            sW[c][k][oc] = wdcn[((size_t)oc * 64 + g * 8 + c) * 9 + k];
        }
        __syncthreads();

        const float* xg = x + (size_t)(b * 64 + g * 8) * CH;
#pragma unroll
        for (int k = 0; k < 9; k++) {
            const int ky = k / 3 - 1;
            const int kx = k % 3 - 1;
            float oy = omb[(size_t)(2 * (g * 9 + k))     * CH] + flowy;
            float ox = omb[(size_t)(2 * (g * 9 + k) + 1) * CH] + flowx;
            float mv = omb[(size_t)(144 + g * 9 + k)     * CH];
            mv = 1.f / (1.f + __expf(-mv));

            float pyf = (float)(h + ky) + oy;
            float pxf = (float)(w + kx) + ox;
            float y0f = floorf(pyf), x0f = floorf(pxf);
            float wy = pyf - y0f, wx = pxf - x0f;
            int iy0 = (int)y0f, ix0 = (int)x0f;
            int iy1 = iy0 + 1, ix1 = ix0 + 1;
            bool vy0 = (iy0 >= 0) & (iy0 < HH);
            bool vy1 = (iy1 >= 0) & (iy1 < HH);
            bool vx0 = (ix0 >= 0) & (ix0 < WW);
            bool vx1 = (ix1 >= 0) & (ix1 < WW);
            int cy0 = min(max(iy0, 0), HH - 1), cy1 = min(max(iy1, 0), HH - 1);
            int cx0 = min(max(ix0, 0), WW - 1), cx1 = min(max(ix1, 0), WW - 1);
            float w00 = (1.f - wy) * (1.f - wx) * ((vy0 && vx0) ? 1.f : 0.f) * mv;
            float w01 = (1.f - wy) * wx         * ((vy0 && vx1) ? 1.f : 0.f) * mv;
            float w10 = wy * (1.f - wx)         * ((vy1 && vx0) ? 1.f : 0.f) * mv;
            float w11 = wy * wx                 * ((vy1 && vx1) ? 1.f : 0.f) * mv;
            int i00 = cy0 * WW + cx0, i01 = cy0 * WW + cx1;
            int i10 = cy1 * WW + cx0, i11 = cy1 * WW + cx1;

#pragma unroll
            for (int c = 0; c < 8; c++) {
                const float* xc = xg + (size_t)c * CH;
                float s = xc[i00] * w00 + xc[i01] * w01 + xc[i10] * w10 + xc[i11] * w11;
                const float4* w4p = (const float4*)&sW[c][k][0];
#pragma unroll
                for (int q = 0; q < 16; q++) {
                    float4 w4 = w4p[q];
                    acc[q * 4 + 0] += s * w4.x;
                    acc[q * 4 + 1] += s * w4.y;
                    acc[q * 4 + 2] += s * w4.z;
                    acc[q * 4 + 3] += s * w4.w;
                }
            }
        }
    }

#pragma unroll
    for (int o = 0; o < 64; o++) {
        float r = acc[o] + bdcn[o];
        r = (r >= 0.f) ? r : 0.1f * r;
        out[((size_t)(b * 64 + o) * HH + h) * WW + w] = r;
    }
}

// ---------------- launch ----------------
extern "C" void kernel_launch(void* const* d_in, const int* in_sizes, int n_in,
                              void* d_out, int out_size)
{
    const float* nbr    = (const float*)d_in[0];
    const float* warped = (const float*)d_in[1];
    const float* ref    = (const float*)d_in[2];
    const float* flows  = (const float*)d_in[3];
    const float* w1     = (const float*)d_in[4];
    const float* b1     = (const float*)d_in[5];
    const float* w2     = (const float*)d_in[6];
    const float* b2     = (const float*)d_in[7];
    const float* w_om   = (const float*)d_in[8];
    const float* b_om   = (const float*)d_in[9];
    const float* w_dcn  = (const float*)d_in[10];
    const float* b_dcn  = (const float*)d_in[11];
    float* out = (float*)d_out;

    float *p_off1, *p_off2, *p_om;
    cudaGetSymbolAddress((void**)&p_off1, g_off1);
    cudaGetSymbolAddress((void**)&p_off2, g_off2);
    cudaGetSymbolAddress((void**)&p_om,   g_om);

    dim3 tiles(WW / 32, HH / 16, 1);

    // 1. conv1 (concat fused): 130 -> 64, lrelu
    {
        dim3 grid(tiles.x, tiles.y, BB * 4);
        conv3x3_k<true, true><<<grid, 128>>>(warped, 130, w1, b1, 64, p_off1, ref, flows);
    }
    // 2. conv2: 64 -> 64, lrelu
    {
        dim3 grid(tiles.x, tiles.y, BB * 4);
        conv3x3_k<true, false><<<grid, 128>>>(p_off1, 64, w2, b2, 64, p_off2, nullptr, nullptr);
    }
    // 3. conv_om: 64 -> 216, linear
    {
        dim3 grid(tiles.x, tiles.y, BB * 14);
        conv3x3_k<false, false><<<grid, 128>>>(p_off2, 64, w_om, b_om, 216, p_om, nullptr, nullptr);
    }
    // 4. DCN + lrelu
    {
        dim3 grid(WW / 32, HH / 4, BB);
        dcn_k<<<grid, 128>>>(nbr, flows, w_dcn, b_dcn, out);
    }
}

// round 3
// speedup vs baseline: 1.2560x; 1.2141x over previous
#include <cuda_runtime.h>

#define HH 192
#define WW 320
#define BB 2

// -------- scratch (device globals; no allocations allowed) --------
__device__ float g_off1[BB *  64 * HH * WW];
__device__ float g_off2[BB *  64 * HH * WW];
__device__ float g_om  [BB * 216 * HH * WW];

// -------- packed f32x2 helpers (Blackwell: 2x fp32 FMA per instr) --------
__device__ __forceinline__ void ffma2(unsigned long long& d,
                                      unsigned long long a,
                                      unsigned long long b) {
    asm("fma.rn.f32x2 %0, %1, %2, %0;" : "+l"(d) : "l"(a), "l"(b));
}
__device__ __forceinline__ unsigned long long pack2(float s) {
    unsigned long long r;
    asm("mov.b64 %0, {%1, %1};" : "=l"(r) : "f"(s));
    return r;
}
__device__ __forceinline__ float2 unpack2(unsigned long long v) {
    float2 f;
    asm("mov.b64 {%0, %1}, %2;" : "=f"(f.x), "=f"(f.y) : "l"(v));
    return f;
}

// ---------------- direct 3x3 conv, pad 1, register-blocked, FFMA2 ----------------
// block = 128 threads. Tile = 32 wide x 16 tall. Each thread: 4 vertical
// pixels x 16 output channels (8 f32x2 pairs). ci chunked by 8.
// grid: (WW/32, HH/16, B * ceil(COUT/16))
template<bool LRELU, bool CAT>
__global__ __launch_bounds__(128, 4)
void conv3x3_k(const float* __restrict__ in, int CIN,
               const float* __restrict__ wgt, const float* __restrict__ bias,
               int COUT, float* __restrict__ out,
               const float* __restrict__ ref,     // CAT only
               const float* __restrict__ flows)   // CAT only
{
    const int nOcB = (COUT + 15) / 16;
    const int b    = blockIdx.z / nOcB;
    const int oc0  = (blockIdx.z % nOcB) * 16;
    const int px   = threadIdx.x & 31;
    const int py0  = (threadIdx.x >> 5) * 4;      // 0,4,8,12
    const int gx0  = blockIdx.x * 32;
    const int gy0  = blockIdx.y * 16;
    const int tid  = threadIdx.x;

    __shared__ __align__(16) float sIn[8][18][36]; // [ci][row][col], origin (-1,-1)
    __shared__ __align__(16) float sW [8][9][16];  // [ci][k][oc]

    unsigned long long acc[4][8];
#pragma unroll
    for (int p = 0; p < 4; p++)
#pragma unroll
        for (int q = 0; q < 8; q++) acc[p][q] = 0ull;

    for (int ci0 = 0; ci0 < CIN; ci0 += 8) {
        __syncthreads();
        // ---- stage input halo tile (18 rows x 34 cols per ci) ----
        for (int i = tid; i < 8 * 18 * 34; i += 128) {
            int c  = i % 34;
            int r  = (i / 34) % 18;
            int ci = i / (34 * 18);
            int cig = ci0 + ci;
            float v = 0.f;
            if (cig < CIN) {
                int yy = gy0 - 1 + r;
                int xx = gx0 - 1 + c;
                if (yy >= 0 && yy < HH && xx >= 0 && xx < WW) {
                    if (!CAT) {
                        v = in[((size_t)(b * CIN + cig) * HH + yy) * WW + xx];
                    } else {
                        const float* src; int cc;
                        if (cig < 64)       { src = in;    cc = b * 64 + cig; }
                        else if (cig < 128) { src = ref;   cc = b * 64 + (cig - 64); }
                        else                { src = flows; cc = b * 2  + (cig - 128); }
                        v = src[((size_t)cc * HH + yy) * WW + xx];
                    }
                }
            }
            sIn[ci][r][c] = v;
        }
        // ---- stage weight slice (zero-pad past CIN / COUT) ----
        for (int i = tid; i < 8 * 9 * 16; i += 128) {
            int oc = i & 15;
            int k  = (i >> 4) % 9;
            int ci = i / (16 * 9);
            float v = 0.f;
            if (ci0 + ci < CIN && oc0 + oc < COUT)
                v = wgt[((size_t)(oc0 + oc) * CIN + ci0 + ci) * 9 + k];
            sW[ci][k][oc] = v;
        }
        __syncthreads();

#pragma unroll
        for (int ci = 0; ci < 8; ci++) {
            // prepack the 6x3 input window as (s,s) pairs
            unsigned long long vp[6][3];
#pragma unroll
            for (int r = 0; r < 6; r++)
#pragma unroll
                for (int c = 0; c < 3; c++)
                    vp[r][c] = pack2(sIn[ci][py0 + r][px + c]);
#pragma unroll
            for (int k = 0; k < 9; k++) {
                const int dy = k / 3, dx = k % 3;
                const ulonglong2* w2p = (const ulonglong2*)&sW[ci][k][0];
                ulonglong2 wa = w2p[0], wb = w2p[1], wc = w2p[2], wd = w2p[3];
#pragma unroll
                for (int p = 0; p < 4; p++) {
                    unsigned long long s2 = vp[p + dy][dx];
                    ffma2(acc[p][0], s2, wa.x);
                    ffma2(acc[p][1], s2, wa.y);
                    ffma2(acc[p][2], s2, wb.x);
                    ffma2(acc[p][3], s2, wb.y);
                    ffma2(acc[p][4], s2, wc.x);
                    ffma2(acc[p][5], s2, wc.y);
                    ffma2(acc[p][6], s2, wd.x);
                    ffma2(acc[p][7], s2, wd.y);
                }
            }
        }
    }

#pragma unroll
    for (int q = 0; q < 8; q++) {
        int ocA = oc0 + 2 * q;
        int ocB = ocA + 1;
#pragma unroll
        for (int p = 0; p < 4; p++) {
            float2 f = unpack2(acc[p][q]);
            int yy = gy0 + py0 + p, xx = gx0 + px;
            if (ocA < COUT) {
                float r = f.x + bias[ocA];
                if (LRELU) r = (r >= 0.f) ? r : 0.1f * r;
                out[((size_t)(b * COUT + ocA) * HH + yy) * WW + xx] = r;
            }
            if (ocB < COUT) {
                float r = f.y + bias[ocB];
                if (LRELU) r = (r >= 0.f) ? r : 0.1f * r;
                out[((size_t)(b * COUT + ocB) * HH + yy) * WW + xx] = r;
            }
        }
    }
}

// ---------------- flow-guided DCN + lrelu (FFMA2) ----------------
// block = 128 threads -> 32x4 pixel tile; each thread owns all 64 out channels
// as 32 f32x2 pairs. grid: (WW/32, HH/4, B)
__global__ __launch_bounds__(128, 4)
void dcn_k(const float* __restrict__ x,        // nbr_fea_l
           const float* __restrict__ flows,
           const float* __restrict__ wdcn,
           const float* __restrict__ bdcn,
           float* __restrict__ out)
{
    const int b  = blockIdx.z;
    const int px = threadIdx.x & 31;
    const int py = threadIdx.x >> 5;
    const int w  = blockIdx.x * 32 + px;
    const int h  = blockIdx.y * 4 + py;
    const int tid = threadIdx.x;

    __shared__ __align__(16) float sW[8][9][64];   // [c][k][oc] for current group

    unsigned long long acc[32];
#pragma unroll
    for (int i = 0; i < 32; i++) acc[i] = 0ull;

    // flows[:, ::-1] channel swap: y-offset gets flows ch1, x-offset gets ch0
    const float flowx = flows[((size_t)(b * 2 + 0) * HH + h) * WW + w];
    const float flowy = flows[((size_t)(b * 2 + 1) * HH + h) * WW + w];

    const float* omb = g_om + (size_t)b * 216 * HH * WW + (size_t)h * WW + w;
    const size_t CH = (size_t)HH * WW;

    for (int g = 0; g < 8; g++) {
        __syncthreads();
        for (int i = tid; i < 8 * 9 * 64; i += 128) {
            int oc = i & 63;
            int k  = (i >> 6) % 9;
            int c  = i / (64 * 9);
            sW[c][k][oc] = wdcn[((size_t)oc * 64 + g * 8 + c) * 9 + k];
        }
        __syncthreads();

        const float* xg = x + (size_t)(b * 64 + g * 8) * CH;
#pragma unroll
        for (int k = 0; k < 9; k++) {
            const int ky = k / 3 - 1;
            const int kx = k % 3 - 1;
            float oy = omb[(size_t)(2 * (g * 9 + k))     * CH] + flowy;
            float ox = omb[(size_t)(2 * (g * 9 + k) + 1) * CH] + flowx;
            float mv = omb[(size_t)(144 + g * 9 + k)     * CH];
            mv = 1.f / (1.f + __expf(-mv));

            float pyf = (float)(h + ky) + oy;
            float pxf = (float)(w + kx) + ox;
            float y0f = floorf(pyf), x0f = floorf(pxf);
            float wy = pyf - y0f, wx = pxf - x0f;
            int iy0 = (int)y0f, ix0 = (int)x0f;
            int iy1 = iy0 + 1, ix1 = ix0 + 1;
            bool vy0 = (iy0 >= 0) & (iy0 < HH);
            bool vy1 = (iy1 >= 0) & (iy1 < HH);
            bool vx0 = (ix0 >= 0) & (ix0 < WW);
            bool vx1 = (ix1 >= 0) & (ix1 < WW);
            int cy0 = min(max(iy0, 0), HH - 1), cy1 = min(max(iy1, 0), HH - 1);
            int cx0 = min(max(ix0, 0), WW - 1), cx1 = min(max(ix1, 0), WW - 1);
            float w00 = (1.f - wy) * (1.f - wx) * ((vy0 && vx0) ? 1.f : 0.f) * mv;
            float w01 = (1.f - wy) * wx         * ((vy0 && vx1) ? 1.f : 0.f) * mv;
            float w10 = wy * (1.f - wx)         * ((vy1 && vx0) ? 1.f : 0.f) * mv;
            float w11 = wy * wx                 * ((vy1 && vx1) ? 1.f : 0.f) * mv;
            int i00 = cy0 * WW + cx0, i01 = cy0 * WW + cx1;
            int i10 = cy1 * WW + cx0, i11 = cy1 * WW + cx1;

#pragma unroll
            for (int c = 0; c < 8; c++) {
                const float* xc = xg + (size_t)c * CH;
                float s = xc[i00] * w00 + xc[i01] * w01 + xc[i10] * w10 + xc[i11] * w11;
                unsigned long long s2 = pack2(s);
                const ulonglong2* w2p = (const ulonglong2*)&sW[c][k][0];
#pragma unroll
                for (int q = 0; q < 8; q++) {
                    ulonglong2 wp = w2p[q];
                    ffma2(acc[4 * q + 0], s2, wp.x);
                    ffma2(acc[4 * q + 1], s2, wp.y);
                    wp = w2p[q + 8];
                    ffma2(acc[4 * q + 2], s2, wp.x);
                    ffma2(acc[4 * q + 3], s2, wp.y);
                }
            }
        }
    }

#pragma unroll
    for (int q = 0; q < 8; q++) {
#pragma unroll
        for (int j = 0; j < 2; j++) {
            // acc[4q+2j] holds oc pair (4q*... ) mapping: w2p[q] -> oc {8q..8q+3}? No:
            // w2p index q covers oc {4q,4q+1,4q+2,4q+3}; w2p[q+8] covers oc {32+4q,...}
            float2 fA = unpack2(acc[4 * q + 2 * j]);     // j=0: oc 4q..; j=1: oc 32+4q..
            float2 fB = unpack2(acc[4 * q + 2 * j + 1]);
            int base = (j == 0) ? (4 * q) : (32 + 4 * q);
            float r0 = fA.x + bdcn[base + 0];
            float r1 = fA.y + bdcn[base + 1];
            float r2 = fB.x + bdcn[base + 2];
            float r3 = fB.y + bdcn[base + 3];
            r0 = (r0 >= 0.f) ? r0 : 0.1f * r0;
            r1 = (r1 >= 0.f) ? r1 : 0.1f * r1;
            r2 = (r2 >= 0.f) ? r2 : 0.1f * r2;
            r3 = (r3 >= 0.f) ? r3 : 0.1f * r3;
            out[((size_t)(b * 64 + base + 0) * HH + h) * WW + w] = r0;
            out[((size_t)(b * 64 + base + 1) * HH + h) * WW + w] = r1;
            out[((size_t)(b * 64 + base + 2) * HH + h) * WW + w] = r2;
            out[((size_t)(b * 64 + base + 3) * HH + h) * WW + w] = r3;
        }
    }
}

// ---------------- launch ----------------
extern "C" void kernel_launch(void* const* d_in, const int* in_sizes, int n_in,
                              void* d_out, int out_size)
{
    const float* nbr    = (const float*)d_in[0];
    const float* warped = (const float*)d_in[1];
    const float* ref    = (const float*)d_in[2];
    const float* flows  = (const float*)d_in[3];
    const float* w1     = (const float*)d_in[4];
    const float* b1     = (const float*)d_in[5];
    const float* w2     = (const float*)d_in[6];
    const float* b2     = (const float*)d_in[7];
    const float* w_om   = (const float*)d_in[8];
    const float* b_om   = (const float*)d_in[9];
    const float* w_dcn  = (const float*)d_in[10];
    const float* b_dcn  = (const float*)d_in[11];
    float* out = (float*)d_out;

    float *p_off1, *p_off2, *p_om;
    cudaGetSymbolAddress((void**)&p_off1, g_off1);
    cudaGetSymbolAddress((void**)&p_off2, g_off2);
    cudaGetSymbolAddress((void**)&p_om,   g_om);

    dim3 tiles(WW / 32, HH / 16, 1);

    // 1. conv1 (concat fused): 130 -> 64, lrelu
    {
        dim3 grid(tiles.x, tiles.y, BB * 4);
        conv3x3_k<true, true><<<grid, 128>>>(warped, 130, w1, b1, 64, p_off1, ref, flows);
    }
    // 2. conv2: 64 -> 64, lrelu
    {
        dim3 grid(tiles.x, tiles.y, BB * 4);
        conv3x3_k<true, false><<<grid, 128>>>(p_off1, 64, w2, b2, 64, p_off2, nullptr, nullptr);
    }
    // 3. conv_om: 64 -> 216, linear
    {
        dim3 grid(tiles.x, tiles.y, BB * 14);
        conv3x3_k<false, false><<<grid, 128>>>(p_off2, 64, w_om, b_om, 216, p_om, nullptr, nullptr);
    }
    // 4. DCN + lrelu
    {
        dim3 grid(WW / 32, HH / 4, BB);
        dcn_k<<<grid, 128>>>(nbr, flows, w_dcn, b_dcn, out);
    }
}

// round 5
// speedup vs baseline: 1.4255x; 1.1350x over previous
#include <cuda_runtime.h>
#include <cstdint>

#define HH 192
#define WW 320
#define BB 2
#define CH_ (HH * WW)

// -------- scratch (device globals; no allocations allowed) --------
__device__ float g_off1[BB *  64 * HH * WW];
__device__ float g_off2[BB *  64 * HH * WW];
__device__ float g_om  [BB * 216 * HH * WW];
__device__ float g_xt  [BB * (size_t)CH_ * 64];   // nbr features, NHWC

// -------- packed f32x2 helpers --------
__device__ __forceinline__ void ffma2(unsigned long long& d,
                                      unsigned long long a,
                                      unsigned long long b) {
    asm("fma.rn.f32x2 %0, %1, %2, %0;" : "+l"(d) : "l"(a), "l"(b));
}
__device__ __forceinline__ unsigned long long pack2(float s) {
    unsigned long long r;
    asm("mov.b64 %0, {%1, %1};" : "=l"(r) : "f"(s));
    return r;
}
__device__ __forceinline__ float2 unpack2(unsigned long long v) {
    float2 f;
    asm("mov.b64 {%0, %1}, %2;" : "=f"(f.x), "=f"(f.y) : "l"(v));
    return f;
}

// -------- cp.async helpers --------
__device__ __forceinline__ void cpa4(unsigned dst, const float* src, bool valid) {
    asm volatile("cp.async.ca.shared.global [%0], [%1], 4, %2;"
                 :: "r"(dst), "l"(src), "r"(valid ? 4u : 0u));
}
__device__ __forceinline__ void cpa_commit() {
    asm volatile("cp.async.commit_group;");
}
__device__ __forceinline__ void cpa_wait0() {
    asm volatile("cp.async.wait_group 0;");
}

// ---------------- NCHW -> NHWC repack of nbr features ----------------
// grid: (HW/32, 2, B), block: (32, 8)
__global__ void nhwc_k(const float* __restrict__ x)
{
    __shared__ float t[32][33];
    const int hw0 = blockIdx.x * 32;
    const int c0  = blockIdx.y * 32;
    const int b   = blockIdx.z;
    const int tx  = threadIdx.x, ty = threadIdx.y;
#pragma unroll
    for (int i = ty; i < 32; i += 8)
        t[i][tx] = x[((size_t)(b * 64 + c0 + i)) * CH_ + hw0 + tx];
    __syncthreads();
#pragma unroll
    for (int i = ty; i < 32; i += 8)
        g_xt[((size_t)b * CH_ + hw0 + i) * 64 + c0 + tx] = t[tx][i];
}

// ---------------- direct 3x3 conv, pad 1, FFMA2, cp.async double-buffered ----------------
// block = 128 threads. Tile 32x16. Each thread: 4 vertical px x 16 oc.
// grid: (WW/32, HH/16, B * ceil(COUT/16))
template<bool LRELU, bool CAT>
__global__ __launch_bounds__(128, 4)
void conv3x3_k(const float* __restrict__ in, int CIN,
               const float* __restrict__ wgt, const float* __restrict__ bias,
               int COUT, float* __restrict__ out,
               const float* __restrict__ ref,     // CAT only
               const float* __restrict__ flows)   // CAT only
{
    const int nOcB = (COUT + 15) / 16;
    const int b    = blockIdx.z / nOcB;
    const int oc0  = (blockIdx.z % nOcB) * 16;
    const int px   = threadIdx.x & 31;
    const int py0  = (threadIdx.x >> 5) * 4;
    const int gx0  = blockIdx.x * 32;
    const int gy0  = blockIdx.y * 16;
    const int tid  = threadIdx.x;

    __shared__ __align__(16) float sIn[2][8][18][36];
    __shared__ __align__(16) float sW [2][8][9][16];

    unsigned long long acc[4][8];
#pragma unroll
    for (int p = 0; p < 4; p++)
#pragma unroll
        for (int q = 0; q < 8; q++) acc[p][q] = 0ull;

    const int nch = (CIN + 7) / 8;

    // -------- stage one chunk into buffer `buf` via cp.async --------
    auto stage = [&](int buf, int ci0) {
        for (int i = tid; i < 8 * 18 * 34; i += 128) {
            int c  = i % 34;
            int r  = (i / 34) % 18;
            int ci = i / (34 * 18);
            int cig = ci0 + ci;
            int yy = gy0 - 1 + r;
            int xx = gx0 - 1 + c;
            bool v = (cig < CIN) && (yy >= 0) && (yy < HH) && (xx >= 0) && (xx < WW);
            const float* src;
            if (!CAT) {
                src = in + ((size_t)(b * CIN + (v ? cig : 0)) * HH + (v ? yy : 0)) * WW + (v ? xx : 0);
            } else {
                int cg = v ? cig : 0;
                const float* base; int cc;
                if (cg < 64)       { base = in;    cc = b * 64 + cg; }
                else if (cg < 128) { base = ref;   cc = b * 64 + (cg - 64); }
                else               { base = flows; cc = b * 2  + (cg - 128); }
                src = base + ((size_t)cc * HH + (v ? yy : 0)) * WW + (v ? xx : 0);
            }
            cpa4((unsigned)__cvta_generic_to_shared(&sIn[buf][ci][r][c]), src, v);
        }
        for (int i = tid; i < 8 * 9 * 16; i += 128) {
            int oc = i & 15;
            int k  = (i >> 4) % 9;
            int ci = i / (16 * 9);
            bool v = (ci0 + ci < CIN) && (oc0 + oc < COUT);
            const float* src = wgt + (v ? (((size_t)(oc0 + oc) * CIN + ci0 + ci) * 9 + k) : 0);
            cpa4((unsigned)__cvta_generic_to_shared(&sW[buf][ci][k][oc]), src, v);
        }
    };

    stage(0, 0);
    cpa_commit();

    for (int ch = 0; ch < nch; ch++) {
        cpa_wait0();
        __syncthreads();
        if (ch + 1 < nch) stage((ch + 1) & 1, (ch + 1) * 8);
        cpa_commit();
        const int buf = ch & 1;

#pragma unroll
        for (int ci = 0; ci < 8; ci++) {
            unsigned long long vp[6][3];
#pragma unroll
            for (int r = 0; r < 6; r++)
#pragma unroll
                for (int c = 0; c < 3; c++)
                    vp[r][c] = pack2(sIn[buf][ci][py0 + r][px + c]);
#pragma unroll
            for (int k = 0; k < 9; k++) {
                const int dy = k / 3, dx = k % 3;
                const ulonglong2* w2p = (const ulonglong2*)&sW[buf][ci][k][0];
                ulonglong2 wa = w2p[0], wb = w2p[1], wc = w2p[2], wd = w2p[3];
#pragma unroll
                for (int p = 0; p < 4; p++) {
                    unsigned long long s2 = vp[p + dy][dx];
                    ffma2(acc[p][0], s2, wa.x);
                    ffma2(acc[p][1], s2, wa.y);
                    ffma2(acc[p][2], s2, wb.x);
                    ffma2(acc[p][3], s2, wb.y);
                    ffma2(acc[p][4], s2, wc.x);
                    ffma2(acc[p][5], s2, wc.y);
                    ffma2(acc[p][6], s2, wd.x);
                    ffma2(acc[p][7], s2, wd.y);
                }
            }
        }
    }

#pragma unroll
    for (int q = 0; q < 8; q++) {
        int ocA = oc0 + 2 * q;
        int ocB = ocA + 1;
#pragma unroll
        for (int p = 0; p < 4; p++) {
            float2 f = unpack2(acc[p][q]);
            int yy = gy0 + py0 + p, xx = gx0 + px;
            if (ocA < COUT) {
                float r = f.x + bias[ocA];
                if (LRELU) r = (r >= 0.f) ? r : 0.1f * r;
                out[((size_t)(b * COUT + ocA) * HH + yy) * WW + xx] = r;
            }
            if (ocB < COUT) {
                float r = f.y + bias[ocB];
                if (LRELU) r = (r >= 0.f) ? r : 0.1f * r;
                out[((size_t)(b * COUT + ocB) * HH + yy) * WW + xx] = r;
            }
        }
    }
}

// ---------------- flow-guided DCN + lrelu (NHWC gather + FFMA2) ----------------
// block = 128 threads -> 32x4 pixel tile; each thread owns all 64 out channels.
// grid: (WW/32, HH/4, B)
__global__ __launch_bounds__(128, 4)
void dcn_k(const float* __restrict__ flows,
           const float* __restrict__ wdcn,
           const float* __restrict__ bdcn,
           float* __restrict__ out)
{
    const int b  = blockIdx.z;
    const int px = threadIdx.x & 31;
    const int py = threadIdx.x >> 5;
    const int w  = blockIdx.x * 32 + px;
    const int h  = blockIdx.y * 4 + py;
    const int tid = threadIdx.x;

    __shared__ __align__(16) float sW[8][9][64];   // [c][k][oc] for current group

    unsigned long long acc[32];
#pragma unroll
    for (int i = 0; i < 32; i++) acc[i] = 0ull;

    // flows[:, ::-1] channel swap
    const float flowx = flows[((size_t)(b * 2 + 0) * HH + h) * WW + w];
    const float flowy = flows[((size_t)(b * 2 + 1) * HH + h) * WW + w];

    const float* omb = g_om + (size_t)b * 216 * CH_ + (size_t)h * WW + w;
    const float* xb  = g_xt + (size_t)b * CH_ * 64;

    for (int g = 0; g < 8; g++) {
        __syncthreads();
        for (int i = tid; i < 8 * 9 * 64; i += 128) {
            int oc = i & 63;
            int k  = (i >> 6) % 9;
            int c  = i / (64 * 9);
            sW[c][k][oc] = wdcn[((size_t)oc * 64 + g * 8 + c) * 9 + k];
        }
        __syncthreads();

#pragma unroll
        for (int k = 0; k < 9; k++) {
            const int ky = k / 3 - 1;
            const int kx = k % 3 - 1;
            float oy = omb[(size_t)(2 * (g * 9 + k))     * CH_] + flowy;
            float ox = omb[(size_t)(2 * (g * 9 + k) + 1) * CH_] + flowx;
            float mv = omb[(size_t)(144 + g * 9 + k)     * CH_];
            mv = 1.f / (1.f + __expf(-mv));

            float pyf = (float)(h + ky) + oy;
            float pxf = (float)(w + kx) + ox;
            float y0f = floorf(pyf), x0f = floorf(pxf);
            float wy = pyf - y0f, wx = pxf - x0f;
            int iy0 = (int)y0f, ix0 = (int)x0f;
            int iy1 = iy0 + 1, ix1 = ix0 + 1;
            bool vy0 = (iy0 >= 0) & (iy0 < HH);
            bool vy1 = (iy1 >= 0) & (iy1 < HH);
            bool vx0 = (ix0 >= 0) & (ix0 < WW);
            bool vx1 = (ix1 >= 0) & (ix1 < WW);
            int cy0 = min(max(iy0, 0), HH - 1), cy1 = min(max(iy1, 0), HH - 1);
            int cx0 = min(max(ix0, 0), WW - 1), cx1 = min(max(ix1, 0), WW - 1);
            float w00 = (1.f - wy) * (1.f - wx) * ((vy0 && vx0) ? 1.f : 0.f) * mv;
            float w01 = (1.f - wy) * wx         * ((vy0 && vx1) ? 1.f : 0.f) * mv;
            float w10 = wy * (1.f - wx)         * ((vy1 && vx0) ? 1.f : 0.f) * mv;
            float w11 = wy * wx                 * ((vy1 && vx1) ? 1.f : 0.f) * mv;
            const float* p00 = xb + (size_t)(cy0 * WW + cx0) * 64 + g * 8;
            const float* p01 = xb + (size_t)(cy0 * WW + cx1) * 64 + g * 8;
            const float* p10 = xb + (size_t)(cy1 * WW + cx0) * 64 + g * 8;
            const float* p11 = xb + (size_t)(cy1 * WW + cx1) * 64 + g * 8;

            // two 4-channel halves to limit register pressure
#pragma unroll
            for (int half = 0; half < 2; half++) {
                float4 a00 = ((const float4*)p00)[half];
                float4 a01 = ((const float4*)p01)[half];
                float4 a10 = ((const float4*)p10)[half];
                float4 a11 = ((const float4*)p11)[half];
                float s[4];
                s[0] = a00.x * w00 + a01.x * w01 + a10.x * w10 + a11.x * w11;
                s[1] = a00.y * w00 + a01.y * w01 + a10.y * w10 + a11.y * w11;
                s[2] = a00.z * w00 + a01.z * w01 + a10.z * w10 + a11.z * w11;
                s[3] = a00.w * w00 + a01.w * w01 + a10.w * w10 + a11.w * w11;
#pragma unroll
                for (int cc = 0; cc < 4; cc++) {
                    int c = half * 4 + cc;
                    unsigned long long s2 = pack2(s[cc]);
                    const ulonglong2* w2p = (const ulonglong2*)&sW[c][k][0];
#pragma unroll
                    for (int q = 0; q < 8; q++) {
                        ulonglong2 wp = w2p[q];
                        ffma2(acc[4 * q + 0], s2, wp.x);
                        ffma2(acc[4 * q + 1], s2, wp.y);
                        wp = w2p[q + 8];
                        ffma2(acc[4 * q + 2], s2, wp.x);
                        ffma2(acc[4 * q + 3], s2, wp.y);
                    }
                }
            }
        }
    }

#pragma unroll
    for (int q = 0; q < 8; q++) {
#pragma unroll
        for (int j = 0; j < 2; j++) {
            float2 fA = unpack2(acc[4 * q + 2 * j]);
            float2 fB = unpack2(acc[4 * q + 2 * j + 1]);
            int base = (j == 0) ? (4 * q) : (32 + 4 * q);
            float r0 = fA.x + bdcn[base + 0];
            float r1 = fA.y + bdcn[base + 1];
            float r2 = fB.x + bdcn[base + 2];
            float r3 = fB.y + bdcn[base + 3];
            r0 = (r0 >= 0.f) ? r0 : 0.1f * r0;
            r1 = (r1 >= 0.f) ? r1 : 0.1f * r1;
            r2 = (r2 >= 0.f) ? r2 : 0.1f * r2;
            r3 = (r3 >= 0.f) ? r3 : 0.1f * r3;
            out[((size_t)(b * 64 + base + 0) * HH + h) * WW + w] = r0;
            out[((size_t)(b * 64 + base + 1) * HH + h) * WW + w] = r1;
            out[((size_t)(b * 64 + base + 2) * HH + h) * WW + w] = r2;
            out[((size_t)(b * 64 + base + 3) * HH + h) * WW + w] = r3;
        }
    }
}

// ---------------- launch ----------------
extern "C" void kernel_launch(void* const* d_in, const int* in_sizes, int n_in,
                              void* d_out, int out_size)
{
    const float* nbr    = (const float*)d_in[0];
    const float* warped = (const float*)d_in[1];
    const float* ref    = (const float*)d_in[2];
    const float* flows  = (const float*)d_in[3];
    const float* w1     = (const float*)d_in[4];
    const float* b1     = (const float*)d_in[5];
    const float* w2     = (const float*)d_in[6];
    const float* b2     = (const float*)d_in[7];
    const float* w_om   = (const float*)d_in[8];
    const float* b_om   = (const float*)d_in[9];
    const float* w_dcn  = (const float*)d_in[10];
    const float* b_dcn  = (const float*)d_in[11];
    float* out = (float*)d_out;

    float *p_off1, *p_off2, *p_om;
    cudaGetSymbolAddress((void**)&p_off1, g_off1);
    cudaGetSymbolAddress((void**)&p_off2, g_off2);
    cudaGetSymbolAddress((void**)&p_om,   g_om);

    // 0. nbr -> NHWC (independent of conv chain; scheduler overlaps)
    {
        dim3 grid(CH_ / 32, 2, BB);
        nhwc_k<<<grid, dim3(32, 8)>>>(nbr);
    }

    dim3 tiles(WW / 32, HH / 16, 1);
    // 1. conv1 (concat fused): 130 -> 64, lrelu
    {
        dim3 grid(tiles.x, tiles.y, BB * 4);
        conv3x3_k<true, true><<<grid, 128>>>(warped, 130, w1, b1, 64, p_off1, ref, flows);
    }
    // 2. conv2: 64 -> 64, lrelu
    {
        dim3 grid(tiles.x, tiles.y, BB * 4);
        conv3x3_k<true, false><<<grid, 128>>>(p_off1, 64, w2, b2, 64, p_off2, nullptr, nullptr);
    }
    // 3. conv_om: 64 -> 216, linear
    {
        dim3 grid(tiles.x, tiles.y, BB * 14);
        conv3x3_k<false, false><<<grid, 128>>>(p_off2, 64, w_om, b_om, 216, p_om, nullptr, nullptr);
    }
    // 4. DCN + lrelu
    {
        dim3 grid(WW / 32, HH / 4, BB);
        dcn_k<<<grid, 128>>>(flows, w_dcn, b_dcn, out);
    }
}

// round 6
// speedup vs baseline: 1.8393x; 1.2902x over previous
#include <cuda_runtime.h>
#include <cstdint>

#define HH 192
#define WW 320
#define BB 2
#define CH_ (HH * WW)

// -------- scratch (device globals; no allocations allowed) --------
__device__ float g_off1[BB *  64 * HH * WW];
__device__ float g_off2[BB *  64 * HH * WW];
__device__ float g_om  [BB * 216 * HH * WW];
__device__ float g_xt  [BB * (size_t)CH_ * 64];   // nbr features, NHWC
__device__ float g_wr1 [4  * 17 * 1152];          // repacked w1
__device__ float g_wr2 [4  *  8 * 1152];          // repacked w2
__device__ float g_wrom[14 *  8 * 1152];          // repacked w_om

// -------- packed f32x2 helpers --------
__device__ __forceinline__ void ffma2(unsigned long long& d,
                                      unsigned long long a,
                                      unsigned long long b) {
    asm("fma.rn.f32x2 %0, %1, %2, %0;" : "+l"(d) : "l"(a), "l"(b));
}
__device__ __forceinline__ unsigned long long pack2(float s) {
    unsigned long long r;
    asm("mov.b64 %0, {%1, %1};" : "=l"(r) : "f"(s));
    return r;
}
__device__ __forceinline__ float2 unpack2(unsigned long long v) {
    float2 f;
    asm("mov.b64 {%0, %1}, %2;" : "=f"(f.x), "=f"(f.y) : "l"(v));
    return f;
}

// -------- cp.async helpers --------
__device__ __forceinline__ void cpa16(unsigned dst, const float* src, bool valid) {
    asm volatile("cp.async.cg.shared.global [%0], [%1], 16, %2;"
                 :: "r"(dst), "l"(src), "r"(valid ? 16u : 0u));
}
__device__ __forceinline__ void cpa_commit() {
    asm volatile("cp.async.commit_group;");
}
__device__ __forceinline__ void cpa_wait0() {
    asm volatile("cp.async.wait_group 0;");
}

// ---------------- weight repack: [oc][ci][k] -> [ocb][ch][ci][k][oc16] ----------------
__global__ void repack_k(const float* __restrict__ wgt, int CIN, int COUT,
                         int nch, float* __restrict__ dst, int total)
{
    int i = blockIdx.x * blockDim.x + threadIdx.x;
    if (i >= total) return;
    int oc  = i & 15;
    int k   = (i >> 4) % 9;
    int ci  = (i / 144) & 7;
    int ch  = (i / 1152) % nch;
    int ocb = i / (1152 * nch);
    int cig = ch * 8 + ci;
    int ocg = ocb * 16 + oc;
    float v = 0.f;
    if (cig < CIN && ocg < COUT)
        v = wgt[((size_t)ocg * CIN + cig) * 9 + k];
    dst[i] = v;
}

// ---------------- NCHW -> NHWC repack of nbr features ----------------
__global__ void nhwc_k(const float* __restrict__ x)
{
    __shared__ float t[32][33];
    const int hw0 = blockIdx.x * 32;
    const int c0  = blockIdx.y * 32;
    const int b   = blockIdx.z;
    const int tx  = threadIdx.x, ty = threadIdx.y;
#pragma unroll
    for (int i = ty; i < 32; i += 8)
        t[i][tx] = x[((size_t)(b * 64 + c0 + i)) * CH_ + hw0 + tx];
    __syncthreads();
#pragma unroll
    for (int i = ty; i < 32; i += 8)
        g_xt[((size_t)b * CH_ + hw0 + i) * 64 + c0 + tx] = t[tx][i];
}

// ---------------- direct 3x3 conv, pad 1, FFMA2, f4-cp.async double-buffered ----------------
// block = 128 threads. Tile 32x16. Each thread: 4 vertical px x 16 oc.
// smem (dynamic): sIn[2][8][18][40] + sW[2][1152]  = 55296 B
// grid: (WW/32, HH/16, B * nOcB)
template<bool LRELU, bool CAT>
__global__ __launch_bounds__(128)
void conv3x3_k(const float* __restrict__ in, int CIN, int nch,
               const float* __restrict__ wr, const float* __restrict__ bias,
               int COUT, float* __restrict__ out,
               const float* __restrict__ ref,     // CAT only
               const float* __restrict__ flows)   // CAT only
{
    extern __shared__ __align__(16) float smem[];
    float* sIn = smem;                 // [buf][ci][18][40]
    float* sW  = smem + 2 * 8 * 18 * 40; // [buf][1152]

    const int nOcB = (COUT + 15) / 16;
    const int b    = blockIdx.z / nOcB;
    const int ocb  = blockIdx.z % nOcB;
    const int oc0  = ocb * 16;
    const int px   = threadIdx.x & 31;
    const int py0  = (threadIdx.x >> 5) * 4;
    const int gx0  = blockIdx.x * 32;
    const int gy0  = blockIdx.y * 16;
    const int tid  = threadIdx.x;

    // ---- per-thread fixed staging slots (computed ONCE) ----
    // input plane = 18 rows x 10 float4; slots s in {tid, tid+128 (if tid<52)}
    const int s0 = tid;
    const int j0 = s0 % 10, r0 = s0 / 10;
    const bool has1 = (tid < 52);
    const int s1 = tid + 128;
    const int j1 = s1 % 10, r1 = s1 / 10;

    int yy0 = gy0 - 1 + r0, x00 = gx0 - 4 + 4 * j0;
    bool v0 = (yy0 >= 0) && (yy0 < HH) && (x00 >= 0) && (x00 + 3 < WW);
    const int off0 = (v0 ? yy0 : 0) * WW + (v0 ? x00 : 0);
    int yy1 = gy0 - 1 + r1, x01 = gx0 - 4 + 4 * j1;
    bool v1 = has1 && (yy1 >= 0) && (yy1 < HH) && (x01 >= 0) && (x01 + 3 < WW);
    const int off1 = (v1 ? yy1 : 0) * WW + (v1 ? x01 : 0);

    const unsigned sInB  = (unsigned)__cvta_generic_to_shared(sIn);
    const unsigned sWB   = (unsigned)__cvta_generic_to_shared(sW);
    const unsigned so0   = (unsigned)(r0 * 40 + 4 * j0) * 4u;
    const unsigned so1   = (unsigned)(r1 * 40 + 4 * j1) * 4u;

    unsigned long long acc[4][8];
#pragma unroll
    for (int p = 0; p < 4; p++)
#pragma unroll
        for (int q = 0; q < 8; q++) acc[p][q] = 0ull;

    // ---- stage one chunk into buffer `buf` ----
    auto stage = [&](int buf, int ch) {
        const int ci0 = ch * 8;
        const unsigned planeB = sInB + (unsigned)buf * 8u * 2880u;  // 18*40*4 = 2880
#pragma unroll
        for (int ci = 0; ci < 8; ci++) {
            const int cig = ci0 + ci;
            const bool cv = (cig < CIN);
            const float* basec;
            if (!CAT) {
                basec = in + (size_t)(b * CIN + (cv ? cig : 0)) * CH_;
            } else {
                int cg = cv ? cig : 0;
                if (cg < 64)       basec = in    + (size_t)(b * 64 + cg) * CH_;
                else if (cg < 128) basec = ref   + (size_t)(b * 64 + cg - 64) * CH_;
                else               basec = flows + (size_t)(b * 2  + cg - 128) * CH_;
            }
            const unsigned dc = planeB + (unsigned)ci * 2880u;
            cpa16(dc + so0, basec + off0, v0 && cv);
            if (has1) cpa16(dc + so1, basec + off1, v1 && cv);
        }
        // weights: contiguous 1152 floats = 288 f4
        const float* wsrc = wr + ((size_t)ocb * nch + ch) * 1152;
        const unsigned wdst = sWB + (unsigned)buf * 1152u * 4u;
        cpa16(wdst + tid * 16u,        wsrc + tid * 4,        true);
        cpa16(wdst + (tid + 128) * 16u, wsrc + (tid + 128) * 4, true);
        if (tid < 32) cpa16(wdst + (tid + 256) * 16u, wsrc + (tid + 256) * 4, true);
    };

    stage(0, 0);
    cpa_commit();

    for (int ch = 0; ch < nch; ch++) {
        cpa_wait0();
        __syncthreads();
        if (ch + 1 < nch) stage((ch + 1) & 1, ch + 1);
        cpa_commit();
        const int buf = ch & 1;
        const float* sInb = sIn + buf * 8 * 18 * 40;
        const float* sWb  = sW + buf * 1152;

#pragma unroll
        for (int ci = 0; ci < 8; ci++) {
            const float* plane = sInb + ci * 18 * 40 + py0 * 40 + px + 3;
            unsigned long long vp[6][3];
#pragma unroll
            for (int r = 0; r < 6; r++)
#pragma unroll
                for (int c = 0; c < 3; c++)
                    vp[r][c] = pack2(plane[r * 40 + c - 1 + 0] ); // col px+3 + (c-1+0)?  see below
            // NOTE: plane points at col px+3 (i.e. x = gx0+px-1+0 ... ). We need cols px+dx+3-? :
            // window x = gx0+px-1+dx -> smem col = px+dx+3. plane col offset = dx. Rewrite:
#pragma unroll
            for (int r = 0; r < 6; r++)
#pragma unroll
                for (int c = 0; c < 3; c++)
                    vp[r][c] = pack2(plane[r * 40 + c]);
#pragma unroll
            for (int k = 0; k < 9; k++) {
                const int dy = k / 3, dx = k % 3;
                const ulonglong2* w2p = (const ulonglong2*)(sWb + (ci * 9 + k) * 16);
                ulonglong2 wa = w2p[0], wb = w2p[1], wc = w2p[2], wd = w2p[3];
#pragma unroll
                for (int p = 0; p < 4; p++) {
                    unsigned long long s2 = vp[p + dy][dx];
                    ffma2(acc[p][0], s2, wa.x);
                    ffma2(acc[p][1], s2, wa.y);
                    ffma2(acc[p][2], s2, wb.x);
                    ffma2(acc[p][3], s2, wb.y);
                    ffma2(acc[p][4], s2, wc.x);
                    ffma2(acc[p][5], s2, wc.y);
                    ffma2(acc[p][6], s2, wd.x);
                    ffma2(acc[p][7], s2, wd.y);
                }
            }
        }
    }

#pragma unroll
    for (int q = 0; q < 8; q++) {
        int ocA = oc0 + 2 * q;
        int ocB = ocA + 1;
#pragma unroll
        for (int p = 0; p < 4; p++) {
            float2 f = unpack2(acc[p][q]);
            int yy = gy0 + py0 + p, xx = gx0 + px;
            if (ocA < COUT) {
                float r = f.x + bias[ocA];
                if (LRELU) r = (r >= 0.f) ? r : 0.1f * r;
                out[((size_t)(b * COUT + ocA) * HH + yy) * WW + xx] = r;
            }
            if (ocB < COUT) {
                float r = f.y + bias[ocB];
                if (LRELU) r = (r >= 0.f) ? r : 0.1f * r;
                out[((size_t)(b * COUT + ocB) * HH + yy) * WW + xx] = r;
            }
        }
    }
}

// ---------------- flow-guided DCN + lrelu (NHWC gather + FFMA2) ----------------
__global__ __launch_bounds__(128, 4)
void dcn_k(const float* __restrict__ flows,
           const float* __restrict__ wdcn,
           const float* __restrict__ bdcn,
           float* __restrict__ out)
{
    const int b  = blockIdx.z;
    const int px = threadIdx.x & 31;
    const int py = threadIdx.x >> 5;
    const int w  = blockIdx.x * 32 + px;
    const int h  = blockIdx.y * 4 + py;
    const int tid = threadIdx.x;

    __shared__ __align__(16) float sW[8][9][64];

    unsigned long long acc[32];
#pragma unroll
    for (int i = 0; i < 32; i++) acc[i] = 0ull;

    const float flowx = flows[((size_t)(b * 2 + 0) * HH + h) * WW + w];
    const float flowy = flows[((size_t)(b * 2 + 1) * HH + h) * WW + w];

    const float* omb = g_om + (size_t)b * 216 * CH_ + (size_t)h * WW + w;
    const float* xb  = g_xt + (size_t)b * CH_ * 64;

    for (int g = 0; g < 8; g++) {
        __syncthreads();
        for (int i = tid; i < 8 * 9 * 64; i += 128) {
            int oc = i & 63;
            int k  = (i >> 6) % 9;
            int c  = i / (64 * 9);
            sW[c][k][oc] = wdcn[((size_t)oc * 64 + g * 8 + c) * 9 + k];
        }
        __syncthreads();

#pragma unroll
        for (int k = 0; k < 9; k++) {
            const int ky = k / 3 - 1;
            const int kx = k % 3 - 1;
            float oy = omb[(size_t)(2 * (g * 9 + k))     * CH_] + flowy;
            float ox = omb[(size_t)(2 * (g * 9 + k) + 1) * CH_] + flowx;
            float mv = omb[(size_t)(144 + g * 9 + k)     * CH_];
            mv = 1.f / (1.f + __expf(-mv));

            float pyf = (float)(h + ky) + oy;
            float pxf = (float)(w + kx) + ox;
            float y0f = floorf(pyf), x0f = floorf(pxf);
            float wy = pyf - y0f, wx = pxf - x0f;
            int iy0 = (int)y0f, ix0 = (int)x0f;
            int iy1 = iy0 + 1, ix1 = ix0 + 1;
            bool vy0 = (iy0 >= 0) & (iy0 < HH);
            bool vy1 = (iy1 >= 0) & (iy1 < HH);
            bool vx0 = (ix0 >= 0) & (ix0 < WW);
            bool vx1 = (ix1 >= 0) & (ix1 < WW);
            int cy0 = min(max(iy0, 0), HH - 1), cy1 = min(max(iy1, 0), HH - 1);
            int cx0 = min(max(ix0, 0), WW - 1), cx1 = min(max(ix1, 0), WW - 1);
            float w00 = (1.f - wy) * (1.f - wx) * ((vy0 && vx0) ? 1.f : 0.f) * mv;
            float w01 = (1.f - wy) * wx         * ((vy0 && vx1) ? 1.f : 0.f) * mv;
            float w10 = wy * (1.f - wx)         * ((vy1 && vx0) ? 1.f : 0.f) * mv;
            float w11 = wy * wx                 * ((vy1 && vx1) ? 1.f : 0.f) * mv;
            const float* p00 = xb + (size_t)(cy0 * WW + cx0) * 64 + g * 8;
            const float* p01 = xb + (size_t)(cy0 * WW + cx1) * 64 + g * 8;
            const float* p10 = xb + (size_t)(cy1 * WW + cx0) * 64 + g * 8;
            const float* p11 = xb + (size_t)(cy1 * WW + cx1) * 64 + g * 8;

#pragma unroll
            for (int half = 0; half < 2; half++) {
                float4 a00 = ((const float4*)p00)[half];
                float4 a01 = ((const float4*)p01)[half];
                float4 a10 = ((const float4*)p10)[half];
                float4 a11 = ((const float4*)p11)[half];
                float s[4];
                s[0] = a00.x * w00 + a01.x * w01 + a10.x * w10 + a11.x * w11;
                s[1] = a00.y * w00 + a01.y * w01 + a10.y * w10 + a11.y * w11;
                s[2] = a00.z * w00 + a01.z * w01 + a10.z * w10 + a11.z * w11;
                s[3] = a00.w * w00 + a01.w * w01 + a10.w * w10 + a11.w * w11;
#pragma unroll
                for (int cc = 0; cc < 4; cc++) {
                    int c = half * 4 + cc;
                    unsigned long long s2 = pack2(s[cc]);
                    const ulonglong2* w2p = (const ulonglong2*)&sW[c][k][0];
#pragma unroll
                    for (int q = 0; q < 8; q++) {
                        ulonglong2 wp = w2p[q];
                        ffma2(acc[4 * q + 0], s2, wp.x);
                        ffma2(acc[4 * q + 1], s2, wp.y);
                        wp = w2p[q + 8];
                        ffma2(acc[4 * q + 2], s2, wp.x);
                        ffma2(acc[4 * q + 3], s2, wp.y);
                    }
                }
            }
        }
    }

#pragma unroll
    for (int q = 0; q < 8; q++) {
#pragma unroll
        for (int j = 0; j < 2; j++) {
            float2 fA = unpack2(acc[4 * q + 2 * j]);
            float2 fB = unpack2(acc[4 * q + 2 * j + 1]);
            int base = (j == 0) ? (4 * q) : (32 + 4 * q);
            float r0 = fA.x + bdcn[base + 0];
            float r1 = fA.y + bdcn[base + 1];
            float r2 = fB.x + bdcn[base + 2];
            float r3 = fB.y + bdcn[base + 3];
            r0 = (r0 >= 0.f) ? r0 : 0.1f * r0;
            r1 = (r1 >= 0.f) ? r1 : 0.1f * r1;
            r2 = (r2 >= 0.f) ? r2 : 0.1f * r2;
            r3 = (r3 >= 0.f) ? r3 : 0.1f * r3;
            out[((size_t)(b * 64 + base + 0) * HH + h) * WW + w] = r0;
            out[((size_t)(b * 64 + base + 1) * HH + h) * WW + w] = r1;
            out[((size_t)(b * 64 + base + 2) * HH + h) * WW + w] = r2;
            out[((size_t)(b * 64 + base + 3) * HH + h) * WW + w] = r3;
        }
    }
}

// ---------------- launch ----------------
extern "C" void kernel_launch(void* const* d_in, const int* in_sizes, int n_in,
                              void* d_out, int out_size)
{
    const float* nbr    = (const float*)d_in[0];
    const float* warped = (const float*)d_in[1];
    const float* ref    = (const float*)d_in[2];
    const float* flows  = (const float*)d_in[3];
    const float* w1     = (const float*)d_in[4];
    const float* b1     = (const float*)d_in[5];
    const float* w2     = (const float*)d_in[6];
    const float* b2     = (const float*)d_in[7];
    const float* w_om   = (const float*)d_in[8];
    const float* b_om   = (const float*)d_in[9];
    const float* w_dcn  = (const float*)d_in[10];
    const float* b_dcn  = (const float*)d_in[11];
    float* out = (float*)d_out;

    float *p_off1, *p_off2, *p_om, *p_wr1, *p_wr2, *p_wrom;
    cudaGetSymbolAddress((void**)&p_off1, g_off1);
    cudaGetSymbolAddress((void**)&p_off2, g_off2);
    cudaGetSymbolAddress((void**)&p_om,   g_om);
    cudaGetSymbolAddress((void**)&p_wr1,  g_wr1);
    cudaGetSymbolAddress((void**)&p_wr2,  g_wr2);
    cudaGetSymbolAddress((void**)&p_wrom, g_wrom);

    const int SMEM = (2 * 8 * 18 * 40 + 2 * 1152) * 4;  // 55296
    static bool attr_done = false;
    cudaFuncSetAttribute(conv3x3_k<true, true>,  cudaFuncAttributeMaxDynamicSharedMemorySize, SMEM);
    cudaFuncSetAttribute(conv3x3_k<true, false>, cudaFuncAttributeMaxDynamicSharedMemorySize, SMEM);
    cudaFuncSetAttribute(conv3x3_k<false, false>,cudaFuncAttributeMaxDynamicSharedMemorySize, SMEM);
    (void)attr_done;

    // 0a. weight repacks + NHWC repack (cheap, front of pipe)
    {
        int t1 = 4 * 17 * 1152, t2 = 4 * 8 * 1152, t3 = 14 * 8 * 1152;
        repack_k<<<(t1 + 255) / 256, 256>>>(w1,   130, 64,  17, p_wr1,  t1);
        repack_k<<<(t2 + 255) / 256, 256>>>(w2,    64, 64,   8, p_wr2,  t2);
        repack_k<<<(t3 + 255) / 256, 256>>>(w_om,  64, 216,  8, p_wrom, t3);
        dim3 grid(CH_ / 32, 2, BB);
        nhwc_k<<<grid, dim3(32, 8)>>>(nbr);
    }

    dim3 tiles(WW / 32, HH / 16, 1);
    // 1. conv1 (concat fused): 130 -> 64, lrelu
    {
        dim3 grid(tiles.x, tiles.y, BB * 4);
        conv3x3_k<true, true><<<grid, 128, SMEM>>>(warped, 130, 17, p_wr1, b1, 64, p_off1, ref, flows);
    }
    // 2. conv2: 64 -> 64, lrelu
    {
        dim3 grid(tiles.x, tiles.y, BB * 4);
        conv3x3_k<true, false><<<grid, 128, SMEM>>>(p_off1, 64, 8, p_wr2, b2, 64, p_off2, nullptr, nullptr);
    }
    // 3. conv_om: 64 -> 216, linear
    {
        dim3 grid(tiles.x, tiles.y, BB * 14);
        conv3x3_k<false, false><<<grid, 128, SMEM>>>(p_off2, 64, 8, p_wrom, b_om, 216, p_om, nullptr, nullptr);
    }
    // 4. DCN + lrelu
    {
        dim3 grid(WW / 32, HH / 4, BB);
        dcn_k<<<grid, 128>>>(flows, w_dcn, b_dcn, out);
    }
}

// round 7
// speedup vs baseline: 1.8472x; 1.0043x over previous
#include <cuda_runtime.h>
#include <cstdint>

#define HH 192
#define WW 320
#define BB 2
#define CH_ (HH * WW)

// -------- scratch (device globals; no allocations allowed) --------
__device__ float g_off1[BB *  64 * HH * WW];
__device__ float g_off2[BB *  64 * HH * WW];
__device__ float g_om  [BB * 216 * HH * WW];
__device__ float g_xt  [BB * (size_t)CH_ * 64];   // nbr features, NHWC
__device__ float g_wr1 [4  * 17 * 1152];          // repacked w1
__device__ float g_wr2 [4  *  8 * 1152];          // repacked w2
__device__ float g_wrom[14 *  8 * 1152];          // repacked w_om

// -------- packed f32x2 helpers --------
__device__ __forceinline__ void ffma2(unsigned long long& d,
                                      unsigned long long a,
                                      unsigned long long b) {
    asm("fma.rn.f32x2 %0, %1, %2, %0;" : "+l"(d) : "l"(a), "l"(b));
}
__device__ __forceinline__ unsigned long long pack2(float s) {
    unsigned long long r;
    asm("mov.b64 %0, {%1, %1};" : "=l"(r) : "f"(s));
    return r;
}
__device__ __forceinline__ float2 unpack2(unsigned long long v) {
    float2 f;
    asm("mov.b64 {%0, %1}, %2;" : "=f"(f.x), "=f"(f.y) : "l"(v));
    return f;
}

// -------- cp.async helpers --------
__device__ __forceinline__ void cpa16(unsigned dst, const float* src, bool valid) {
    asm volatile("cp.async.cg.shared.global [%0], [%1], 16, %2;"
                 :: "r"(dst), "l"(src), "r"(valid ? 16u : 0u));
}
__device__ __forceinline__ void cpa_commit() {
    asm volatile("cp.async.commit_group;");
}
__device__ __forceinline__ void cpa_wait0() {
    asm volatile("cp.async.wait_group 0;");
}

// ---------------- weight repack: [oc][ci][k] -> [ocb][ch][ci][k][oc16] ----------------
__global__ void repack_k(const float* __restrict__ wgt, int CIN, int COUT,
                         int nch, float* __restrict__ dst, int total)
{
    int i = blockIdx.x * blockDim.x + threadIdx.x;
    if (i >= total) return;
    int oc  = i & 15;
    int k   = (i >> 4) % 9;
    int ci  = (i / 144) & 7;
    int ch  = (i / 1152) % nch;
    int ocb = i / (1152 * nch);
    int cig = ch * 8 + ci;
    int ocg = ocb * 16 + oc;
    float v = 0.f;
    if (cig < CIN && ocg < COUT)
        v = wgt[((size_t)ocg * CIN + cig) * 9 + k];
    dst[i] = v;
}

// ---------------- NCHW -> NHWC repack of nbr features ----------------
__global__ void nhwc_k(const float* __restrict__ x)
{
    __shared__ float t[32][33];
    const int hw0 = blockIdx.x * 32;
    const int c0  = blockIdx.y * 32;
    const int b   = blockIdx.z;
    const int tx  = threadIdx.x, ty = threadIdx.y;
#pragma unroll
    for (int i = ty; i < 32; i += 8)
        t[i][tx] = x[((size_t)(b * 64 + c0 + i)) * CH_ + hw0 + tx];
    __syncthreads();
#pragma unroll
    for (int i = ty; i < 32; i += 8)
        g_xt[((size_t)b * CH_ + hw0 + i) * 64 + c0 + tx] = t[tx][i];
}

// ---------------- direct 3x3 conv, pad 1, FFMA2, f4-cp.async double-buffered ----------------
// block = 128 threads. Tile 32x16. Each thread: 4 vertical px x 16 oc.
// smem (dynamic): sIn[2][8][18][40] + sW[2][1152]  = 55296 B
// grid: (WW/32, HH/16, B * nOcB)
template<bool LRELU, bool CAT>
__global__ __launch_bounds__(128)
void conv3x3_k(const float* __restrict__ in, int CIN, int nch,
               const float* __restrict__ wr, const float* __restrict__ bias,
               int COUT, float* __restrict__ out,
               const float* __restrict__ ref,     // CAT only
               const float* __restrict__ flows)   // CAT only
{
    extern __shared__ __align__(16) float smem[];
    float* sIn = smem;                 // [buf][ci][18][40]
    float* sW  = smem + 2 * 8 * 18 * 40; // [buf][1152]

    const int nOcB = (COUT + 15) / 16;
    const int b    = blockIdx.z / nOcB;
    const int ocb  = blockIdx.z % nOcB;
    const int oc0  = ocb * 16;
    const int px   = threadIdx.x & 31;
    const int py0  = (threadIdx.x >> 5) * 4;
    const int gx0  = blockIdx.x * 32;
    const int gy0  = blockIdx.y * 16;
    const int tid  = threadIdx.x;

    // ---- per-thread fixed staging slots (computed ONCE) ----
    // input plane = 18 rows x 10 float4; slots s in {tid, tid+128 (if tid<52)}
    const int s0 = tid;
    const int j0 = s0 % 10, r0 = s0 / 10;
    const bool has1 = (tid < 52);
    const int s1 = tid + 128;
    const int j1 = s1 % 10, r1 = s1 / 10;

    int yy0 = gy0 - 1 + r0, x00 = gx0 - 4 + 4 * j0;
    bool v0 = (yy0 >= 0) && (yy0 < HH) && (x00 >= 0) && (x00 + 3 < WW);
    const int off0 = (v0 ? yy0 : 0) * WW + (v0 ? x00 : 0);
    int yy1 = gy0 - 1 + r1, x01 = gx0 - 4 + 4 * j1;
    bool v1 = has1 && (yy1 >= 0) && (yy1 < HH) && (x01 >= 0) && (x01 + 3 < WW);
    const int off1 = (v1 ? yy1 : 0) * WW + (v1 ? x01 : 0);

    const unsigned sInB  = (unsigned)__cvta_generic_to_shared(sIn);
    const unsigned sWB   = (unsigned)__cvta_generic_to_shared(sW);
    const unsigned so0   = (unsigned)(r0 * 40 + 4 * j0) * 4u;
    const unsigned so1   = (unsigned)(r1 * 40 + 4 * j1) * 4u;

    unsigned long long acc[4][8];
#pragma unroll
    for (int p = 0; p < 4; p++)
#pragma unroll
        for (int q = 0; q < 8; q++) acc[p][q] = 0ull;

    // ---- stage one chunk into buffer `buf` ----
    auto stage = [&](int buf, int ch) {
        const int ci0 = ch * 8;
        const unsigned planeB = sInB + (unsigned)buf * 8u * 2880u;  // 18*40*4 = 2880
#pragma unroll
        for (int ci = 0; ci < 8; ci++) {
            const int cig = ci0 + ci;
            const bool cv = (cig < CIN);
            const float* basec;
            if (!CAT) {
                basec = in + (size_t)(b * CIN + (cv ? cig : 0)) * CH_;
            } else {
                int cg = cv ? cig : 0;
                if (cg < 64)       basec = in    + (size_t)(b * 64 + cg) * CH_;
                else if (cg < 128) basec = ref   + (size_t)(b * 64 + cg - 64) * CH_;
                else               basec = flows + (size_t)(b * 2  + cg - 128) * CH_;
            }
            const unsigned dc = planeB + (unsigned)ci * 2880u;
            cpa16(dc + so0, basec + off0, v0 && cv);
            if (has1) cpa16(dc + so1, basec + off1, v1 && cv);
        }
        // weights: contiguous 1152 floats = 288 f4
        const float* wsrc = wr + ((size_t)ocb * nch + ch) * 1152;
        const unsigned wdst = sWB + (unsigned)buf * 1152u * 4u;
        cpa16(wdst + tid * 16u,        wsrc + tid * 4,        true);
        cpa16(wdst + (tid + 128) * 16u, wsrc + (tid + 128) * 4, true);
        if (tid < 32) cpa16(wdst + (tid + 256) * 16u, wsrc + (tid + 256) * 4, true);
    };

    stage(0, 0);
    cpa_commit();

    for (int ch = 0; ch < nch; ch++) {
        cpa_wait0();
        __syncthreads();
        if (ch + 1 < nch) stage((ch + 1) & 1, ch + 1);
        cpa_commit();
        const int buf = ch & 1;
        const float* sInb = sIn + buf * 8 * 18 * 40;
        const float* sWb  = sW + buf * 1152;

#pragma unroll
        for (int ci = 0; ci < 8; ci++) {
            const float* plane = sInb + ci * 18 * 40 + py0 * 40 + px + 3;
            unsigned long long vp[6][3];
#pragma unroll
            for (int r = 0; r < 6; r++)
#pragma unroll
                for (int c = 0; c < 3; c++)
                    vp[r][c] = pack2(plane[r * 40 + c - 1 + 0] ); // col px+3 + (c-1+0)?  see below
            // NOTE: plane points at col px+3 (i.e. x = gx0+px-1+0 ... ). We need cols px+dx+3-? :
            // window x = gx0+px-1+dx -> smem col = px+dx+3. plane col offset = dx. Rewrite:
#pragma unroll
            for (int r = 0; r < 6; r++)
#pragma unroll
                for (int c = 0; c < 3; c++)
                    vp[r][c] = pack2(plane[r * 40 + c]);
#pragma unroll
            for (int k = 0; k < 9; k++) {
                const int dy = k / 3, dx = k % 3;
                const ulonglong2* w2p = (const ulonglong2*)(sWb + (ci * 9 + k) * 16);
                ulonglong2 wa = w2p[0], wb = w2p[1], wc = w2p[2], wd = w2p[3];
#pragma unroll
                for (int p = 0; p < 4; p++) {
                    unsigned long long s2 = vp[p + dy][dx];
                    ffma2(acc[p][0], s2, wa.x);
                    ffma2(acc[p][1], s2, wa.y);
                    ffma2(acc[p][2], s2, wb.x);
                    ffma2(acc[p][3], s2, wb.y);
                    ffma2(acc[p][4], s2, wc.x);
                    ffma2(acc[p][5], s2, wc.y);
                    ffma2(acc[p][6], s2, wd.x);
                    ffma2(acc[p][7], s2, wd.y);
                }
            }
        }
    }

#pragma unroll
    for (int q = 0; q < 8; q++) {
        int ocA = oc0 + 2 * q;
        int ocB = ocA + 1;
#pragma unroll
        for (int p = 0; p < 4; p++) {
            float2 f = unpack2(acc[p][q]);
            int yy = gy0 + py0 + p, xx = gx0 + px;
            if (ocA < COUT) {
                float r = f.x + bias[ocA];
                if (LRELU) r = (r >= 0.f) ? r : 0.1f * r;
                out[((size_t)(b * COUT + ocA) * HH + yy) * WW + xx] = r;
            }
            if (ocB < COUT) {
                float r = f.y + bias[ocB];
                if (LRELU) r = (r >= 0.f) ? r : 0.1f * r;
                out[((size_t)(b * COUT + ocB) * HH + yy) * WW + xx] = r;
            }
        }
    }
}

// ---------------- flow-guided DCN + lrelu (NHWC gather + FFMA2) ----------------
__global__ __launch_bounds__(128, 4)
void dcn_k(const float* __restrict__ flows,
           const float* __restrict__ wdcn,
           const float* __restrict__ bdcn,
           float* __restrict__ out)
{
    const int b  = blockIdx.z;
    const int px = threadIdx.x & 31;
    const int py = threadIdx.x >> 5;
    const int w  = blockIdx.x * 32 + px;
    const int h  = blockIdx.y * 4 + py;
    const int tid = threadIdx.x;

    __shared__ __align__(16) float sW[8][9][64];

    unsigned long long acc[32];
#pragma unroll
    for (int i = 0; i < 32; i++) acc[i] = 0ull;

    const float flowx = flows[((size_t)(b * 2 + 0) * HH + h) * WW + w];
    const float flowy = flows[((size_t)(b * 2 + 1) * HH + h) * WW + w];

    const float* omb = g_om + (size_t)b * 216 * CH_ + (size_t)h * WW + w;
    const float* xb  = g_xt + (size_t)b * CH_ * 64;

    for (int g = 0; g < 8; g++) {
        __syncthreads();
        for (int i = tid; i < 8 * 9 * 64; i += 128) {
            int oc = i & 63;
            int k  = (i >> 6) % 9;
            int c  = i / (64 * 9);
            sW[c][k][oc] = wdcn[((size_t)oc * 64 + g * 8 + c) * 9 + k];
        }
        __syncthreads();

#pragma unroll
        for (int k = 0; k < 9; k++) {
            const int ky = k / 3 - 1;
            const int kx = k % 3 - 1;
            float oy = omb[(size_t)(2 * (g * 9 + k))     * CH_] + flowy;
            float ox = omb[(size_t)(2 * (g * 9 + k) + 1) * CH_] + flowx;
            float mv = omb[(size_t)(144 + g * 9 + k)     * CH_];
            mv = 1.f / (1.f + __expf(-mv));

            float pyf = (float)(h + ky) + oy;
            float pxf = (float)(w + kx) + ox;
            float y0f = floorf(pyf), x0f = floorf(pxf);
            float wy = pyf - y0f, wx = pxf - x0f;
            int iy0 = (int)y0f, ix0 = (int)x0f;
            int iy1 = iy0 + 1, ix1 = ix0 + 1;
            bool vy0 = (iy0 >= 0) & (iy0 < HH);
            bool vy1 = (iy1 >= 0) & (iy1 < HH);
            bool vx0 = (ix0 >= 0) & (ix0 < WW);
            bool vx1 = (ix1 >= 0) & (ix1 < WW);
            int cy0 = min(max(iy0, 0), HH - 1), cy1 = min(max(iy1, 0), HH - 1);
            int cx0 = min(max(ix0, 0), WW - 1), cx1 = min(max(ix1, 0), WW - 1);
            float w00 = (1.f - wy) * (1.f - wx) * ((vy0 && vx0) ? 1.f : 0.f) * mv;
            float w01 = (1.f - wy) * wx         * ((vy0 && vx1) ? 1.f : 0.f) * mv;
            float w10 = wy * (1.f - wx)         * ((vy1 && vx0) ? 1.f : 0.f) * mv;
            float w11 = wy * wx                 * ((vy1 && vx1) ? 1.f : 0.f) * mv;
            const float* p00 = xb + (size_t)(cy0 * WW + cx0) * 64 + g * 8;
            const float* p01 = xb + (size_t)(cy0 * WW + cx1) * 64 + g * 8;
            const float* p10 = xb + (size_t)(cy1 * WW + cx0) * 64 + g * 8;
            const float* p11 = xb + (size_t)(cy1 * WW + cx1) * 64 + g * 8;

#pragma unroll
            for (int half = 0; half < 2; half++) {
                float4 a00 = ((const float4*)p00)[half];
                float4 a01 = ((const float4*)p01)[half];
                float4 a10 = ((const float4*)p10)[half];
                float4 a11 = ((const float4*)p11)[half];
                float s[4];
                s[0] = a00.x * w00 + a01.x * w01 + a10.x * w10 + a11.x * w11;
                s[1] = a00.y * w00 + a01.y * w01 + a10.y * w10 + a11.y * w11;
                s[2] = a00.z * w00 + a01.z * w01 + a10.z * w10 + a11.z * w11;
                s[3] = a00.w * w00 + a01.w * w01 + a10.w * w10 + a11.w * w11;
#pragma unroll
                for (int cc = 0; cc < 4; cc++) {
                    int c = half * 4 + cc;
                    unsigned long long s2 = pack2(s[cc]);
                    const ulonglong2* w2p = (const ulonglong2*)&sW[c][k][0];
#pragma unroll
                    for (int q = 0; q < 8; q++) {
                        ulonglong2 wp = w2p[q];
                        ffma2(acc[4 * q + 0], s2, wp.x);
                        ffma2(acc[4 * q + 1], s2, wp.y);
                        wp = w2p[q + 8];
                        ffma2(acc[4 * q + 2], s2, wp.x);
                        ffma2(acc[4 * q + 3], s2, wp.y);
                    }
                }
            }
        }
    }

#pragma unroll
    for (int q = 0; q < 8; q++) {
#pragma unroll
        for (int j = 0; j < 2; j++) {
            float2 fA = unpack2(acc[4 * q + 2 * j]);
            float2 fB = unpack2(acc[4 * q + 2 * j + 1]);
            int base = (j == 0) ? (4 * q) : (32 + 4 * q);
            float r0 = fA.x + bdcn[base + 0];
            float r1 = fA.y + bdcn[base + 1];
            float r2 = fB.x + bdcn[base + 2];
            float r3 = fB.y + bdcn[base + 3];
            r0 = (r0 >= 0.f) ? r0 : 0.1f * r0;
            r1 = (r1 >= 0.f) ? r1 : 0.1f * r1;
            r2 = (r2 >= 0.f) ? r2 : 0.1f * r2;
            r3 = (r3 >= 0.f) ? r3 : 0.1f * r3;
            out[((size_t)(b * 64 + base + 0) * HH + h) * WW + w] = r0;
            out[((size_t)(b * 64 + base + 1) * HH + h) * WW + w] = r1;
            out[((size_t)(b * 64 + base + 2) * HH + h) * WW + w] = r2;
            out[((size_t)(b * 64 + base + 3) * HH + h) * WW + w] = r3;
        }
    }
}

// ---------------- launch ----------------
extern "C" void kernel_launch(void* const* d_in, const int* in_sizes, int n_in,
                              void* d_out, int out_size)
{
    const float* nbr    = (const float*)d_in[0];
    const float* warped = (const float*)d_in[1];
    const float* ref    = (const float*)d_in[2];
    const float* flows  = (const float*)d_in[3];
    const float* w1     = (const float*)d_in[4];
    const float* b1     = (const float*)d_in[5];
    const float* w2     = (const float*)d_in[6];
    const float* b2     = (const float*)d_in[7];
    const float* w_om   = (const float*)d_in[8];
    const float* b_om   = (const float*)d_in[9];
    const float* w_dcn  = (const float*)d_in[10];
    const float* b_dcn  = (const float*)d_in[11];
    float* out = (float*)d_out;

    float *p_off1, *p_off2, *p_om, *p_wr1, *p_wr2, *p_wrom;
    cudaGetSymbolAddress((void**)&p_off1, g_off1);
    cudaGetSymbolAddress((void**)&p_off2, g_off2);
    cudaGetSymbolAddress((void**)&p_om,   g_om);
    cudaGetSymbolAddress((void**)&p_wr1,  g_wr1);
    cudaGetSymbolAddress((void**)&p_wr2,  g_wr2);
    cudaGetSymbolAddress((void**)&p_wrom, g_wrom);

    const int SMEM = (2 * 8 * 18 * 40 + 2 * 1152) * 4;  // 55296
    static bool attr_done = false;
    cudaFuncSetAttribute(conv3x3_k<true, true>,  cudaFuncAttributeMaxDynamicSharedMemorySize, SMEM);
    cudaFuncSetAttribute(conv3x3_k<true, false>, cudaFuncAttributeMaxDynamicSharedMemorySize, SMEM);
    cudaFuncSetAttribute(conv3x3_k<false, false>,cudaFuncAttributeMaxDynamicSharedMemorySize, SMEM);
    (void)attr_done;

    // 0a. weight repacks + NHWC repack (cheap, front of pipe)
    {
        int t1 = 4 * 17 * 1152, t2 = 4 * 8 * 1152, t3 = 14 * 8 * 1152;
        repack_k<<<(t1 + 255) / 256, 256>>>(w1,   130, 64,  17, p_wr1,  t1);
        repack_k<<<(t2 + 255) / 256, 256>>>(w2,    64, 64,   8, p_wr2,  t2);
        repack_k<<<(t3 + 255) / 256, 256>>>(w_om,  64, 216,  8, p_wrom, t3);
        dim3 grid(CH_ / 32, 2, BB);
        nhwc_k<<<grid, dim3(32, 8)>>>(nbr);
    }

    dim3 tiles(WW / 32, HH / 16, 1);
    // 1. conv1 (concat fused): 130 -> 64, lrelu
    {
        dim3 grid(tiles.x, tiles.y, BB * 4);
        conv3x3_k<true, true><<<grid, 128, SMEM>>>(warped, 130, 17, p_wr1, b1, 64, p_off1, ref, flows);
    }
    // 2. conv2: 64 -> 64, lrelu
    {
        dim3 grid(tiles.x, tiles.y, BB * 4);
        conv3x3_k<true, false><<<grid, 128, SMEM>>>(p_off1, 64, 8, p_wr2, b2, 64, p_off2, nullptr, nullptr);
    }
    // 3. conv_om: 64 -> 216, linear
    {
        dim3 grid(tiles.x, tiles.y, BB * 14);
        conv3x3_k<false, false><<<grid, 128, SMEM>>>(p_off2, 64, 8, p_wrom, b_om, 216, p_om, nullptr, nullptr);
    }
    // 4. DCN + lrelu
    {
        dim3 grid(WW / 32, HH / 4, BB);
        dcn_k<<<grid, 128>>>(flows, w_dcn, b_dcn, out);
    }
}

// round 9
// speedup vs baseline: 2.2641x; 1.2257x over previous
#include <cuda_runtime.h>
#include <cuda_bf16.h>
#include <cstdint>

#define HH 192
#define WW 320
#define BB 2
#define CH_ (HH * WW)

// -------- scratch (device globals; no allocations allowed) --------
__device__ float g_xt  [BB * (size_t)CH_ * 64];         // nbr NHWC (dcn)
__device__ float g_wr1 [4 * 17 * 1152];                 // repacked w1
__device__ __nv_bfloat16 g_x2h[BB * (size_t)CH_ * 64];  // conv1 out hi (NHWC)
__device__ __nv_bfloat16 g_x2l[BB * (size_t)CH_ * 64];  // conv1 out lo
__device__ __nv_bfloat16 g_x3h[BB * (size_t)CH_ * 64];  // conv2 out hi
__device__ __nv_bfloat16 g_x3l[BB * (size_t)CH_ * 64];  // conv2 out lo
__device__ float g_om  [BB * (size_t)CH_ * 216];        // conv_om out (NHWC fp32)
__device__ __nv_bfloat16 g_w2h[9 * 64 * 64];            // w2 hi  [k][oc][ci]
__device__ __nv_bfloat16 g_w2l[9 * 64 * 64];
__device__ __nv_bfloat16 g_womh[9 * 216 * 64];          // w_om hi [k][oc][ci]
__device__ __nv_bfloat16 g_woml[9 * 216 * 64];

// -------- packed f32x2 helpers --------
__device__ __forceinline__ void ffma2(unsigned long long& d,
                                      unsigned long long a,
                                      unsigned long long b) {
    asm("fma.rn.f32x2 %0, %1, %2, %0;" : "+l"(d) : "l"(a), "l"(b));
}
__device__ __forceinline__ unsigned long long pack2(float s) {
    unsigned long long r;
    asm("mov.b64 %0, {%1, %1};" : "=l"(r) : "f"(s));
    return r;
}
__device__ __forceinline__ float2 unpack2(unsigned long long v) {
    float2 f;
    asm("mov.b64 {%0, %1}, %2;" : "=f"(f.x), "=f"(f.y) : "l"(v));
    return f;
}

// -------- cp.async helpers --------
__device__ __forceinline__ void cpa16(unsigned dst, const void* src, bool valid) {
    asm volatile("cp.async.cg.shared.global [%0], [%1], 16, %2;"
                 :: "r"(dst), "l"(src), "r"(valid ? 16u : 0u));
}
__device__ __forceinline__ void cpa_commit() { asm volatile("cp.async.commit_group;"); }
__device__ __forceinline__ void cpa_wait0()  { asm volatile("cp.async.wait_group 0;"); }

__device__ __forceinline__ uint32_t smem_u32(const void* p) {
    uint32_t a;
    asm("{ .reg .u64 t; cvta.to.shared.u64 t, %1; cvt.u32.u64 %0, t; }" : "=r"(a) : "l"(p));
    return a;
}

// -------- mma.sync helpers --------
#define LDSM4(r0, r1, r2, r3, a) \
    asm volatile("ldmatrix.sync.aligned.m8n8.x4.shared.b16 {%0,%1,%2,%3}, [%4];" \
                 : "=r"(r0), "=r"(r1), "=r"(r2), "=r"(r3) : "r"(a))
#define LDSM2(r0, r1, a) \
    asm volatile("ldmatrix.sync.aligned.m8n8.x2.shared.b16 {%0,%1}, [%2];" \
                 : "=r"(r0), "=r"(r1) : "r"(a))
#define MMA16816(d, a0, a1, a2, a3, b0, b1) \
    asm volatile("mma.sync.aligned.m16n8k16.row.col.f32.bf16.bf16.f32 " \
                 "{%0,%1,%2,%3}, {%4,%5,%6,%7}, {%8,%9}, {%0,%1,%2,%3};" \
                 : "+f"((d)[0]), "+f"((d)[1]), "+f"((d)[2]), "+f"((d)[3]) \
                 : "r"(a0), "r"(a1), "r"(a2), "r"(a3), "r"(b0), "r"(b1))

// ---------------- weight repack for conv1 scalar ----------------
__global__ void repack_k(const float* __restrict__ wgt, int CIN, int COUT,
                         int nch, float* __restrict__ dst, int total)
{
    int i = blockIdx.x * blockDim.x + threadIdx.x;
    if (i >= total) return;
    int oc  = i & 15;
    int k   = (i >> 4) % 9;
    int ci  = (i / 144) & 7;
    int ch  = (i / 1152) % nch;
    int ocb = i / (1152 * nch);
    int cig = ch * 8 + ci;
    int ocg = ocb * 16 + oc;
    float v = 0.f;
    if (cig < CIN && ocg < COUT)
        v = wgt[((size_t)ocg * CIN + cig) * 9 + k];
    dst[i] = v;
}

// ---------------- weight hi/lo split: [oc][ci][k] -> [k][oc][ci] bf16 ----------------
__global__ void wsplit_k(const float* __restrict__ w, int NOC,
                         __nv_bfloat16* __restrict__ wh, __nv_bfloat16* __restrict__ wl,
                         int total)
{
    int i = blockIdx.x * blockDim.x + threadIdx.x;
    if (i >= total) return;
    int ci = i & 63;
    int oc = (i >> 6) % NOC;
    int k  = i / (64 * NOC);
    float v = w[((size_t)oc * 64 + ci) * 9 + k];
    __nv_bfloat16 hi = __float2bfloat16(v);
    wh[i] = hi;
    wl[i] = __float2bfloat16(v - __bfloat162float(hi));
}

// ---------------- NCHW -> NHWC repack of nbr features (for dcn) ----------------
__global__ void nhwc_k(const float* __restrict__ x)
{
    __shared__ float t[32][33];
    const int hw0 = blockIdx.x * 32;
    const int c0  = blockIdx.y * 32;
    const int b   = blockIdx.z;
    const int tx  = threadIdx.x, ty = threadIdx.y;
#pragma unroll
    for (int i = ty; i < 32; i += 8)
        t[i][tx] = x[((size_t)(b * 64 + c0 + i)) * CH_ + hw0 + tx];
    __syncthreads();
#pragma unroll
    for (int i = ty; i < 32; i += 8)
        g_xt[((size_t)b * CH_ + hw0 + i) * 64 + c0 + tx] = t[tx][i];
}

// ---------------- conv1: 130 -> 64, lrelu, scalar FFMA2, bf16 hi/lo NHWC out ----------------
__global__ __launch_bounds__(128)
void conv1_k(const float* __restrict__ warped, const float* __restrict__ ref,
             const float* __restrict__ flows,
             const float* __restrict__ wr, const float* __restrict__ bias)
{
    const int CIN = 130, nch = 17;
    extern __shared__ __align__(128) float smem[];
    float* sIn = smem;                   // [buf][ci][18][40]
    float* sW  = smem + 2 * 8 * 18 * 40; // [buf][1152]

    const int b    = blockIdx.z >> 2;
    const int ocb  = blockIdx.z & 3;
    const int oc0  = ocb * 16;
    const int px   = threadIdx.x & 31;
    const int py0  = (threadIdx.x >> 5) * 4;
    const int gx0  = blockIdx.x * 32;
    const int gy0  = blockIdx.y * 16;
    const int tid  = threadIdx.x;

    const int j0 = tid % 10, r0 = tid / 10;
    const bool has1 = (tid < 52);
    const int s1 = tid + 128;
    const int j1 = s1 % 10, r1 = s1 / 10;

    int yy0 = gy0 - 1 + r0, x00 = gx0 - 4 + 4 * j0;
    bool v0 = (yy0 >= 0) && (yy0 < HH) && (x00 >= 0) && (x00 + 3 < WW);
    const int off0 = (v0 ? yy0 : 0) * WW + (v0 ? x00 : 0);
    int yy1 = gy0 - 1 + r1, x01 = gx0 - 4 + 4 * j1;
    bool v1 = has1 && (yy1 >= 0) && (yy1 < HH) && (x01 >= 0) && (x01 + 3 < WW);
    const int off1 = (v1 ? yy1 : 0) * WW + (v1 ? x01 : 0);

    const unsigned sInB = smem_u32(sIn);
    const unsigned sWB  = smem_u32(sW);
    const unsigned so0  = (unsigned)(r0 * 40 + 4 * j0) * 4u;
    const unsigned so1  = (unsigned)(r1 * 40 + 4 * j1) * 4u;

    unsigned long long acc[4][8];
#pragma unroll
    for (int p = 0; p < 4; p++)
#pragma unroll
        for (int q = 0; q < 8; q++) acc[p][q] = 0ull;

    auto stage = [&](int buf, int ch) {
        const int ci0 = ch * 8;
        const unsigned planeB = sInB + (unsigned)buf * 8u * 2880u;
#pragma unroll
        for (int ci = 0; ci < 8; ci++) {
            const int cig = ci0 + ci;
            const bool cv = (cig < CIN);
            int cg = cv ? cig : 0;
            const float* basec;
            if (cg < 64)       basec = warped + (size_t)(b * 64 + cg) * CH_;
            else if (cg < 128) basec = ref    + (size_t)(b * 64 + cg - 64) * CH_;
            else               basec = flows  + (size_t)(b * 2  + cg - 128) * CH_;
            const unsigned dc = planeB + (unsigned)ci * 2880u;
            cpa16(dc + so0, basec + off0, v0 && cv);
            if (has1) cpa16(dc + so1, basec + off1, v1 && cv);
        }
        const float* wsrc = wr + ((size_t)ocb * nch + ch) * 1152;
        const unsigned wdst = sWB + (unsigned)buf * 1152u * 4u;
        cpa16(wdst + tid * 16u,         wsrc + tid * 4,         true);
        cpa16(wdst + (tid + 128) * 16u, wsrc + (tid + 128) * 4, true);
        if (tid < 32) cpa16(wdst + (tid + 256) * 16u, wsrc + (tid + 256) * 4, true);
    };

    stage(0, 0);
    cpa_commit();

    for (int ch = 0; ch < nch; ch++) {
        cpa_wait0();
        __syncthreads();
        if (ch + 1 < nch) stage((ch + 1) & 1, ch + 1);
        cpa_commit();
        const int buf = ch & 1;
        const float* sInb = sIn + buf * 8 * 18 * 40;
        const float* sWb  = sW + buf * 1152;

#pragma unroll
        for (int ci = 0; ci < 8; ci++) {
            const float* plane = sInb + ci * 18 * 40 + py0 * 40 + px + 3;
            unsigned long long vp[6][3];
#pragma unroll
            for (int r = 0; r < 6; r++)
#pragma unroll
                for (int c = 0; c < 3; c++)
                    vp[r][c] = pack2(plane[r * 40 + c]);
#pragma unroll
            for (int k = 0; k < 9; k++) {
                const int dy = k / 3, dx = k % 3;
                const ulonglong2* w2p = (const ulonglong2*)(sWb + (ci * 9 + k) * 16);
                ulonglong2 wa = w2p[0], wb = w2p[1], wc = w2p[2], wd = w2p[3];
#pragma unroll
                for (int p = 0; p < 4; p++) {
                    unsigned long long s2 = vp[p + dy][dx];
                    ffma2(acc[p][0], s2, wa.x);
                    ffma2(acc[p][1], s2, wa.y);
                    ffma2(acc[p][2], s2, wb.x);
                    ffma2(acc[p][3], s2, wb.y);
                    ffma2(acc[p][4], s2, wc.x);
                    ffma2(acc[p][5], s2, wc.y);
                    ffma2(acc[p][6], s2, wd.x);
                    ffma2(acc[p][7], s2, wd.y);
                }
            }
        }
    }

#pragma unroll
    for (int q = 0; q < 8; q++) {
        int ocA = oc0 + 2 * q;
#pragma unroll
        for (int p = 0; p < 4; p++) {
            float2 f = unpack2(acc[p][q]);
            float rA = f.x + bias[ocA];
            float rB = f.y + bias[ocA + 1];
            rA = (rA >= 0.f) ? rA : 0.1f * rA;
            rB = (rB >= 0.f) ? rB : 0.1f * rB;
            int pix = (gy0 + py0 + p) * WW + (gx0 + px);
            size_t base = ((size_t)b * CH_ + pix) * 64 + ocA;
            __nv_bfloat16 hA = __float2bfloat16(rA), hB = __float2bfloat16(rB);
            __nv_bfloat16 lA = __float2bfloat16(rA - __bfloat162float(hA));
            __nv_bfloat16 lB = __float2bfloat16(rB - __bfloat162float(hB));
            uint32_t uh = (uint32_t)__bfloat16_as_ushort(hA) | ((uint32_t)__bfloat16_as_ushort(hB) << 16);
            uint32_t ul = (uint32_t)__bfloat16_as_ushort(lA) | ((uint32_t)__bfloat16_as_ushort(lB) << 16);
            ((uint32_t*)g_x2h)[base >> 1] = uh;
            ((uint32_t*)g_x2l)[base >> 1] = ul;
        }
    }
}

// ---------------- mma.sync 3x3 conv: NHWC bf16 hi/lo in, 64 ci, NOCS oc slice out ----------------
// CTA = 128 thr (4 warps), out tile 2 rows x 32 px. Patch 4x34 px staged once.
// Per tap: B slice [NOCS][64] staged, then m16n8k16 HMMA (3 split products).
// grid: (WW/32, HH/2, BB * (NOCTOT/NOCS))
template<int NOCS, int NOCTOT, bool OMOUT>
__global__ __launch_bounds__(128)
void mconv_k(const __nv_bfloat16* __restrict__ xh, const __nv_bfloat16* __restrict__ xl,
             const __nv_bfloat16* __restrict__ wh, const __nv_bfloat16* __restrict__ wl,
             const float* __restrict__ bias,
             __nv_bfloat16* __restrict__ yh, __nv_bfloat16* __restrict__ yl,
             float* __restrict__ om)
{
    constexpr int NB = NOCS / 8;
    constexpr int NSL = NOCTOT / NOCS;
    constexpr unsigned PATCH_HALF = 4 * 34 * 128;   // 17408
    constexpr unsigned B_OFF = 2 * PATCH_HALF;      // 34816

    extern __shared__ __align__(128) char smraw[];
    const unsigned sb = smem_u32(smraw);

    const int tid  = threadIdx.x;
    const int w    = tid >> 5;
    const int lane = tid & 31;
    const int b    = blockIdx.z / NSL;
    const int oc0  = (blockIdx.z % NSL) * NOCS;
    const int x0   = blockIdx.x * 32;
    const int y0   = blockIdx.y * 2;

    const __nv_bfloat16* xhb = xh + (size_t)b * CH_ * 64;
    const __nv_bfloat16* xlb = xl + (size_t)b * CH_ * 64;

    // ---- stage patch (4 rows x 34 px x 64 ci, hi+lo), once ----
    for (int i = tid; i < 2176; i += 128) {
        int c   = i & 7;
        int pxl = (i >> 3) % 136;
        int hl  = i / 1088;
        int y = y0 - 1 + pxl / 34;
        int x = x0 - 1 + pxl % 34;
        bool v = (y >= 0) && (y < HH) && (x >= 0) && (x < WW);
        const __nv_bfloat16* src = (hl ? xlb : xhb)
            + (size_t)((v ? y : 0) * WW + (v ? x : 0)) * 64 + c * 8;
        unsigned dst = sb + (unsigned)hl * PATCH_HALF + (unsigned)pxl * 128u
                     + (unsigned)((c ^ (pxl & 7)) << 4);
        cpa16(dst, src, v);
    }
    cpa_commit();

    float acc[NB][4];
#pragma unroll
    for (int nb = 0; nb < NB; nb++)
#pragma unroll
        for (int j = 0; j < 4; j++) acc[nb][j] = 0.f;

    const int gid = lane >> 2, tig = lane & 3;
    const int l16 = lane & 15;
    const int lr  = l16 & 7;          // B row-within-frag
    const int lh  = l16 >> 3;         // B chunk half
    const int ahalf = lane >> 4;      // A chunk half
    const int r = w >> 1, xbase = (w & 1) * 16;
    const int apx0 = (r + 1) * 34 + 1 + xbase + l16;  // per-lane patch pixel (tap 0,0)
    // precomputed per-lane B address pieces
    const unsigned bline = sb + B_OFF + (unsigned)lr * 128u;

    for (int tap = 0; tap < 9; tap++) {
        // ---- stage B slice for this tap ----
        for (int i = tid; i < NOCS * 16; i += 128) {
            int c   = i & 7;
            int row = (i >> 3) % NOCS;
            int hl  = i / (NOCS * 8);
            const __nv_bfloat16* src = (hl ? wl : wh)
                + ((size_t)tap * NOCTOT + oc0 + row) * 64 + c * 8;
            unsigned dst = sb + B_OFF + (unsigned)hl * (NOCS * 128u)
                         + (unsigned)row * 128u + (unsigned)((c ^ (row & 7)) << 4);
            cpa16(dst, src, true);
        }
        cpa_commit();
        cpa_wait0();
        __syncthreads();

        const int ky = tap / 3 - 1, kx = tap % 3 - 1;
        const int apx = apx0 + ky * 34 + kx;
        const unsigned aline = sb + (unsigned)apx * 128u;
        const int a7 = apx & 7;

#pragma unroll
        for (int s = 0; s < 4; s++) {
            uint32_t ah0, ah1, ah2, ah3, al0, al1, al2, al3;
            unsigned achunk = (unsigned)((s * 2 + ahalf) ^ a7) << 4;
            LDSM4(ah0, ah1, ah2, ah3, aline + achunk);
            LDSM4(al0, al1, al2, al3, aline + PATCH_HALF + achunk);
#pragma unroll
            for (int nb = 0; nb < NB; nb++) {
                uint32_t bh0, bh1, bl0, bl1;
                unsigned baddr = bline + (unsigned)nb * 1024u
                               + (unsigned)(((s * 2 + lh) ^ lr) << 4);
                LDSM2(bh0, bh1, baddr);
                LDSM2(bl0, bl1, baddr + NOCS * 128u);
                MMA16816(acc[nb], ah0, ah1, ah2, ah3, bh0, bh1);
                MMA16816(acc[nb], al0, al1, al2, al3, bh0, bh1);
                MMA16816(acc[nb], ah0, ah1, ah2, ah3, bl0, bl1);
            }
        }
        __syncthreads();
    }

    // ---- epilogue ----
    const int ya = y0 + r;
    const int xa = x0 + xbase + gid;
    const size_t pa = (size_t)b * CH_ + (size_t)ya * WW + xa;
    const size_t pb = pa + 8;
    if (!OMOUT) {
#pragma unroll
        for (int nb = 0; nb < NB; nb++) {
            int oc = nb * 8 + tig * 2;
            float b0 = bias[oc], b1 = bias[oc + 1];
#pragma unroll
            for (int hp = 0; hp < 2; hp++) {
                float v0 = acc[nb][2 * hp + 0] + b0;
                float v1 = acc[nb][2 * hp + 1] + b1;
                v0 = (v0 >= 0.f) ? v0 : 0.1f * v0;
                v1 = (v1 >= 0.f) ? v1 : 0.1f * v1;
                __nv_bfloat16 h0 = __float2bfloat16(v0), h1 = __float2bfloat16(v1);
                __nv_bfloat16 l0 = __float2bfloat16(v0 - __bfloat162float(h0));
                __nv_bfloat16 l1 = __float2bfloat16(v1 - __bfloat162float(h1));
                size_t base = ((hp ? pb : pa)) * 64 + oc;
                ((uint32_t*)yh)[base >> 1] =
                    (uint32_t)__bfloat16_as_ushort(h0) | ((uint32_t)__bfloat16_as_ushort(h1) << 16);
                ((uint32_t*)yl)[base >> 1] =
                    (uint32_t)__bfloat16_as_ushort(l0) | ((uint32_t)__bfloat16_as_ushort(l1) << 16);
            }
        }
    } else {
#pragma unroll
        for (int nb = 0; nb < NB; nb++) {
            int oc = oc0 + nb * 8 + tig * 2;
            float b0 = bias[oc], b1 = bias[oc + 1];
            om[pa * 216 + oc]     = acc[nb][0] + b0;
            om[pa * 216 + oc + 1] = acc[nb][1] + b1;
            om[pb * 216 + oc]     = acc[nb][2] + b0;
            om[pb * 216 + oc + 1] = acc[nb][3] + b1;
        }
    }
}

// ---------------- flow-guided DCN + lrelu (NHWC gather + FFMA2) ----------------
__global__ __launch_bounds__(128, 4)
void dcn_k(const float* __restrict__ flows,
           const float* __restrict__ wdcn,
           const float* __restrict__ bdcn,
           float* __restrict__ out)
{
    const int b  = blockIdx.z;
    const int px = threadIdx.x & 31;
    const int py = threadIdx.x >> 5;
    const int w  = blockIdx.x * 32 + px;
    const int h  = blockIdx.y * 4 + py;
    const int tid = threadIdx.x;

    __shared__ __align__(16) float sW[8][9][64];

    unsigned long long acc[32];
#pragma unroll
    for (int i = 0; i < 32; i++) acc[i] = 0ull;

    const float flowx = flows[((size_t)(b * 2 + 0) * HH + h) * WW + w];
    const float flowy = flows[((size_t)(b * 2 + 1) * HH + h) * WW + w];

    const float* omb = g_om + ((size_t)b * CH_ + (size_t)h * WW + w) * 216;
    const float* xb  = g_xt + (size_t)b * CH_ * 64;

    for (int g = 0; g < 8; g++) {
        __syncthreads();
        for (int i = tid; i < 8 * 9 * 64; i += 128) {
            int oc = i & 63;
            int k  = (i >> 6) % 9;
            int c  = i / (64 * 9);
            sW[c][k][oc] = wdcn[((size_t)oc * 64 + g * 8 + c) * 9 + k];
        }
        __syncthreads();

#pragma unroll
        for (int k = 0; k < 9; k++) {
            const int ky = k / 3 - 1;
            const int kx = k % 3 - 1;
            float oy = omb[2 * (g * 9 + k)]     + flowy;
            float ox = omb[2 * (g * 9 + k) + 1] + flowx;
            float mv = omb[144 + g * 9 + k];
            mv = 1.f / (1.f + __expf(-mv));

            float pyf = (float)(h + ky) + oy;
            float pxf = (float)(w + kx) + ox;
            float y0f = floorf(pyf), x0f = floorf(pxf);
            float wy = pyf - y0f, wx = pxf - x0f;
            int iy0 = (int)y0f, ix0 = (int)x0f;
            int iy1 = iy0 + 1, ix1 = ix0 + 1;
            bool vy0 = (iy0 >= 0) & (iy0 < HH);
            bool vy1 = (iy1 >= 0) & (iy1 < HH);
            bool vx0 = (ix0 >= 0) & (ix0 < WW);
            bool vx1 = (ix1 >= 0) & (ix1 < WW);
            int cy0 = min(max(iy0, 0), HH - 1), cy1 = min(max(iy1, 0), HH - 1);
            int cx0 = min(max(ix0, 0), WW - 1), cx1 = min(max(ix1, 0), WW - 1);
            float w00 = (1.f - wy) * (1.f - wx) * ((vy0 && vx0) ? 1.f : 0.f) * mv;
            float w01 = (1.f - wy) * wx         * ((vy0 && vx1) ? 1.f : 0.f) * mv;
            float w10 = wy * (1.f - wx)         * ((vy1 && vx0) ? 1.f : 0.f) * mv;
            float w11 = wy * wx                 * ((vy1 && vx1) ? 1.f : 0.f) * mv;
            const float* p00 = xb + (size_t)(cy0 * WW + cx0) * 64 + g * 8;
            const float* p01 = xb + (size_t)(cy0 * WW + cx1) * 64 + g * 8;
            const float* p10 = xb + (size_t)(cy1 * WW + cx0) * 64 + g * 8;
            const float* p11 = xb + (size_t)(cy1 * WW + cx1) * 64 + g * 8;

#pragma unroll
            for (int half = 0; half < 2; half++) {
                float4 a00 = ((const float4*)p00)[half];
                float4 a01 = ((const float4*)p01)[half];
                float4 a10 = ((const float4*)p10)[half];
                float4 a11 = ((const float4*)p11)[half];
                float s[4];
                s[0] = a00.x * w00 + a01.x * w01 + a10.x * w10 + a11.x * w11;
                s[1] = a00.y * w00 + a01.y * w01 + a10.y * w10 + a11.y * w11;
                s[2] = a00.z * w00 + a01.z * w01 + a10.z * w10 + a11.z * w11;
                s[3] = a00.w * w00 + a01.w * w01 + a10.w * w10 + a11.w * w11;
#pragma unroll
                for (int cc = 0; cc < 4; cc++) {
                    int c = half * 4 + cc;
                    unsigned long long s2 = pack2(s[cc]);
                    const ulonglong2* w2p = (const ulonglong2*)&sW[c][k][0];
#pragma unroll
                    for (int q = 0; q < 8; q++) {
                        ulonglong2 wp = w2p[q];
                        ffma2(acc[4 * q + 0], s2, wp.x);
                        ffma2(acc[4 * q + 1], s2, wp.y);
                        wp = w2p[q + 8];
                        ffma2(acc[4 * q + 2], s2, wp.x);
                        ffma2(acc[4 * q + 3], s2, wp.y);
                    }
                }
            }
        }
    }

#pragma unroll
    for (int q = 0; q < 8; q++) {
#pragma unroll
        for (int j = 0; j < 2; j++) {
            float2 fA = unpack2(acc[4 * q + 2 * j]);
            float2 fB = unpack2(acc[4 * q + 2 * j + 1]);
            int base = (j == 0) ? (4 * q) : (32 + 4 * q);
            float r0 = fA.x + bdcn[base + 0];
            float r1 = fA.y + bdcn[base + 1];
            float r2 = fB.x + bdcn[base + 2];
            float r3 = fB.y + bdcn[base + 3];
            r0 = (r0 >= 0.f) ? r0 : 0.1f * r0;
            r1 = (r1 >= 0.f) ? r1 : 0.1f * r1;
            r2 = (r2 >= 0.f) ? r2 : 0.1f * r2;
            r3 = (r3 >= 0.f) ? r3 : 0.1f * r3;
            out[((size_t)(b * 64 + base + 0) * HH + h) * WW + w] = r0;
            out[((size_t)(b * 64 + base + 1) * HH + h) * WW + w] = r1;
            out[((size_t)(b * 64 + base + 2) * HH + h) * WW + w] = r2;
            out[((size_t)(b * 64 + base + 3) * HH + h) * WW + w] = r3;
        }
    }
}

// ---------------- launch ----------------
extern "C" void kernel_launch(void* const* d_in, const int* in_sizes, int n_in,
                              void* d_out, int out_size)
{
    const float* nbr    = (const float*)d_in[0];
    const float* warped = (const float*)d_in[1];
    const float* ref    = (const float*)d_in[2];
    const float* flows  = (const float*)d_in[3];
    const float* w1     = (const float*)d_in[4];
    const float* b1     = (const float*)d_in[5];
    const float* w2     = (const float*)d_in[6];
    const float* b2     = (const float*)d_in[7];
    const float* w_om   = (const float*)d_in[8];
    const float* b_om   = (const float*)d_in[9];
    const float* w_dcn  = (const float*)d_in[10];
    const float* b_dcn  = (const float*)d_in[11];
    float* out = (float*)d_out;

    float *p_wr1, *p_om;
    __nv_bfloat16 *p_x2h, *p_x2l, *p_x3h, *p_x3l, *p_w2h, *p_w2l, *p_womh, *p_woml;
    cudaGetSymbolAddress((void**)&p_wr1,  g_wr1);
    cudaGetSymbolAddress((void**)&p_om,   g_om);
    cudaGetSymbolAddress((void**)&p_x2h,  g_x2h);
    cudaGetSymbolAddress((void**)&p_x2l,  g_x2l);
    cudaGetSymbolAddress((void**)&p_x3h,  g_x3h);
    cudaGetSymbolAddress((void**)&p_x3l,  g_x3l);
    cudaGetSymbolAddress((void**)&p_w2h,  g_w2h);
    cudaGetSymbolAddress((void**)&p_w2l,  g_w2l);
    cudaGetSymbolAddress((void**)&p_womh, g_womh);
    cudaGetSymbolAddress((void**)&p_woml, g_woml);

    const int SMEM1 = (2 * 8 * 18 * 40 + 2 * 1152) * 4;   // conv1: 55296
    const int SMEM2 = 34816 + 64 * 256;                    // 51200
    const int SMEMO = 34816 + 72 * 256;                    // 53248
    cudaFuncSetAttribute(conv1_k, cudaFuncAttributeMaxDynamicSharedMemorySize, SMEM1);
    cudaFuncSetAttribute(mconv_k<64, 64, false>,  cudaFuncAttributeMaxDynamicSharedMemorySize, SMEM2);
    cudaFuncSetAttribute(mconv_k<72, 216, true>,  cudaFuncAttributeMaxDynamicSharedMemorySize, SMEMO);

    // 0. weight prep + NHWC repack
    {
        int t1 = 4 * 17 * 1152;
        repack_k<<<(t1 + 255) / 256, 256>>>(w1, 130, 64, 17, p_wr1, t1);
        int t2 = 9 * 64 * 64;
        wsplit_k<<<(t2 + 255) / 256, 256>>>(w2, 64, p_w2h, p_w2l, t2);
        int t3 = 9 * 216 * 64;
        wsplit_k<<<(t3 + 255) / 256, 256>>>(w_om, 216, p_womh, p_woml, t3);
        dim3 grid(CH_ / 32, 2, BB);
        nhwc_k<<<grid, dim3(32, 8)>>>(nbr);
    }
    // 1. conv1 (concat fused, scalar FFMA2): 130 -> 64, lrelu, bf16 hi/lo NHWC
    {
        dim3 grid(WW / 32, HH / 16, BB * 4);
        conv1_k<<<grid, 128, SMEM1>>>(warped, ref, flows, p_wr1, b1);
    }
    // 2. conv2 (HMMA): 64 -> 64, lrelu, bf16 hi/lo NHWC
    {
        dim3 grid(WW / 32, HH / 2, BB);
        mconv_k<64, 64, false><<<grid, 128, SMEM2>>>(p_x2h, p_x2l, p_w2h, p_w2l, b2,
                                                     p_x3h, p_x3l, nullptr);
    }
    // 3. conv_om (HMMA): 64 -> 216 (3 slices of 72), linear, fp32 NHWC
    {
        dim3 grid(WW / 32, HH / 2, BB * 3);
        mconv_k<72, 216, true><<<grid, 128, SMEMO>>>(p_x3h, p_x3l, p_womh, p_woml, b_om,
                                                     nullptr, nullptr, p_om);
    }
    // 4. DCN + lrelu
    {
        dim3 grid(WW / 32, HH / 4, BB);
        dcn_k<<<grid, 128>>>(flows, w_dcn, b_dcn, out);
    }
}

// round 10
// speedup vs baseline: 2.5462x; 1.1246x over previous
#include <cuda_runtime.h>
#include <cuda_bf16.h>
#include <cstdint>

#define HH 192
#define WW 320
#define BB 2
#define CH_ (HH * WW)

// -------- scratch (device globals; no allocations allowed) --------
__device__ float g_xt  [BB * (size_t)CH_ * 64];         // nbr NHWC (dcn)
__device__ __nv_bfloat16 g_x1h[BB * (size_t)CH_ * 192]; // concat in hi (NHWC, pad 192)
__device__ __nv_bfloat16 g_x1l[BB * (size_t)CH_ * 192];
__device__ __nv_bfloat16 g_x2h[BB * (size_t)CH_ * 64];  // conv1 out hi (NHWC)
__device__ __nv_bfloat16 g_x2l[BB * (size_t)CH_ * 64];
__device__ __nv_bfloat16 g_x3h[BB * (size_t)CH_ * 64];  // conv2 out hi
__device__ __nv_bfloat16 g_x3l[BB * (size_t)CH_ * 64];
__device__ float g_om  [BB * (size_t)CH_ * 216];        // conv_om out (NHWC fp32)
__device__ __nv_bfloat16 g_w1h[9 * 64 * 192];           // w1 hi [k][oc][192]
__device__ __nv_bfloat16 g_w1l[9 * 64 * 192];
__device__ __nv_bfloat16 g_w2h[9 * 64 * 64];            // w2 hi [k][oc][64]
__device__ __nv_bfloat16 g_w2l[9 * 64 * 64];
__device__ __nv_bfloat16 g_womh[9 * 216 * 64];          // w_om hi [k][oc][64]
__device__ __nv_bfloat16 g_woml[9 * 216 * 64];

// -------- packed f32x2 helpers --------
__device__ __forceinline__ void ffma2(unsigned long long& d,
                                      unsigned long long a,
                                      unsigned long long b) {
    asm("fma.rn.f32x2 %0, %1, %2, %0;" : "+l"(d) : "l"(a), "l"(b));
}
__device__ __forceinline__ unsigned long long pack2(float s) {
    unsigned long long r;
    asm("mov.b64 %0, {%1, %1};" : "=l"(r) : "f"(s));
    return r;
}
__device__ __forceinline__ float2 unpack2(unsigned long long v) {
    float2 f;
    asm("mov.b64 {%0, %1}, %2;" : "=f"(f.x), "=f"(f.y) : "l"(v));
    return f;
}

// -------- cp.async helpers --------
__device__ __forceinline__ void cpa16(unsigned dst, const void* src, bool valid) {
    asm volatile("cp.async.cg.shared.global [%0], [%1], 16, %2;"
                 :: "r"(dst), "l"(src), "r"(valid ? 16u : 0u));
}
__device__ __forceinline__ void cpa_commit() { asm volatile("cp.async.commit_group;"); }
__device__ __forceinline__ void cpa_wait0()  { asm volatile("cp.async.wait_group 0;"); }

__device__ __forceinline__ uint32_t smem_u32(const void* p) {
    uint32_t a;
    asm("{ .reg .u64 t; cvta.to.shared.u64 t, %1; cvt.u32.u64 %0, t; }" : "=r"(a) : "l"(p));
    return a;
}

// -------- mma.sync helpers --------
#define LDSM4(r0, r1, r2, r3, a) \
    asm volatile("ldmatrix.sync.aligned.m8n8.x4.shared.b16 {%0,%1,%2,%3}, [%4];" \
                 : "=r"(r0), "=r"(r1), "=r"(r2), "=r"(r3) : "r"(a))
#define LDSM2(r0, r1, a) \
    asm volatile("ldmatrix.sync.aligned.m8n8.x2.shared.b16 {%0,%1}, [%2];" \
                 : "=r"(r0), "=r"(r1) : "r"(a))
#define MMA16816(d, a0, a1, a2, a3, b0, b1) \
    asm volatile("mma.sync.aligned.m16n8k16.row.col.f32.bf16.bf16.f32 " \
                 "{%0,%1,%2,%3}, {%4,%5,%6,%7}, {%8,%9}, {%0,%1,%2,%3};" \
                 : "+f"((d)[0]), "+f"((d)[1]), "+f"((d)[2]), "+f"((d)[3]) \
                 : "r"(a0), "r"(a1), "r"(a2), "r"(a3), "r"(b0), "r"(b1))

// ---------------- concat -> NHWC bf16 hi/lo, 192-ch padded ----------------
// grid: (CH_/32, 6, BB), block (32,8)
__global__ void cat_k(const float* __restrict__ warped, const float* __restrict__ ref,
                      const float* __restrict__ flows)
{
    __shared__ float t[32][33];
    const int hw0 = blockIdx.x * 32;
    const int c0  = blockIdx.y * 32;
    const int b   = blockIdx.z;
    const int tx  = threadIdx.x, ty = threadIdx.y;
#pragma unroll
    for (int i = ty; i < 32; i += 8) {
        int cg = c0 + i;
        float v = 0.f;
        if (cg < 64)        v = warped[((size_t)(b * 64 + cg)) * CH_ + hw0 + tx];
        else if (cg < 128)  v = ref   [((size_t)(b * 64 + cg - 64)) * CH_ + hw0 + tx];
        else if (cg < 130)  v = flows [((size_t)(b * 2  + cg - 128)) * CH_ + hw0 + tx];
        t[i][tx] = v;
    }
    __syncthreads();
#pragma unroll
    for (int i = ty; i < 32; i += 8) {
        float v = t[tx][i];
        __nv_bfloat16 hi = __float2bfloat16(v);
        __nv_bfloat16 lo = __float2bfloat16(v - __bfloat162float(hi));
        size_t o = ((size_t)b * CH_ + hw0 + i) * 192 + c0 + tx;
        g_x1h[o] = hi;
        g_x1l[o] = lo;
    }
}

// ---------------- weight hi/lo split: [oc][ci][k] -> [k][oc][CINP] bf16 ----------------
__global__ void wsplit_k(const float* __restrict__ w, int NOC, int CINR, int CINP,
                         __nv_bfloat16* __restrict__ wh, __nv_bfloat16* __restrict__ wl,
                         int total)
{
    int i = blockIdx.x * blockDim.x + threadIdx.x;
    if (i >= total) return;
    int ci = i % CINP;
    int oc = (i / CINP) % NOC;
    int k  = i / (CINP * NOC);
    float v = (ci < CINR) ? w[((size_t)oc * CINR + ci) * 9 + k] : 0.f;
    __nv_bfloat16 hi = __float2bfloat16(v);
    wh[i] = hi;
    wl[i] = __float2bfloat16(v - __bfloat162float(hi));
}

// ---------------- NCHW -> NHWC repack of nbr features (for dcn) ----------------
__global__ void nhwc_k(const float* __restrict__ x)
{
    __shared__ float t[32][33];
    const int hw0 = blockIdx.x * 32;
    const int c0  = blockIdx.y * 32;
    const int b   = blockIdx.z;
    const int tx  = threadIdx.x, ty = threadIdx.y;
#pragma unroll
    for (int i = ty; i < 32; i += 8)
        t[i][tx] = x[((size_t)(b * 64 + c0 + i)) * CH_ + hw0 + tx];
    __syncthreads();
#pragma unroll
    for (int i = ty; i < 32; i += 8)
        g_xt[((size_t)b * CH_ + hw0 + i) * 64 + c0 + tx] = t[tx][i];
}

// ---------------- mma.sync 3x3 conv ----------------
// NCI = # of 64-ci chunks; SLAST = K16-steps in last chunk (4 = full).
// CTA = 128 thr (4 warps), out tile 2 rows x 32 px. Per chunk: patch staged once,
// per tap B slice staged, m16n8k16 HMMA hi/lo split (3 products).
// grid: (WW/32, HH/2, BB * (NOCTOT/NOCS))
template<int NCI, int SLAST, int NOCS, int NOCTOT, bool OMOUT>
__global__ __launch_bounds__(128)
void mconv_k(const __nv_bfloat16* __restrict__ xh, const __nv_bfloat16* __restrict__ xl,
             const __nv_bfloat16* __restrict__ wh, const __nv_bfloat16* __restrict__ wl,
             const float* __restrict__ bias,
             __nv_bfloat16* __restrict__ yh, __nv_bfloat16* __restrict__ yl,
             float* __restrict__ om)
{
    constexpr int NB = NOCS / 8;
    constexpr int NSL = NOCTOT / NOCS;
    constexpr int XSTR = NCI * 64;                  // gmem channel stride
    constexpr unsigned PATCH_HALF = 4 * 34 * 128;   // 17408
    constexpr unsigned B_OFF = 2 * PATCH_HALF;      // 34816

    extern __shared__ __align__(128) char smraw[];
    const unsigned sb = smem_u32(smraw);

    const int tid  = threadIdx.x;
    const int w    = tid >> 5;
    const int lane = tid & 31;
    const int b    = blockIdx.z / NSL;
    const int oc0  = (blockIdx.z % NSL) * NOCS;
    const int x0   = blockIdx.x * 32;
    const int y0   = blockIdx.y * 2;

    const __nv_bfloat16* xhb = xh + (size_t)b * CH_ * XSTR;
    const __nv_bfloat16* xlb = xl + (size_t)b * CH_ * XSTR;

    float acc[NB][4];
#pragma unroll
    for (int nb = 0; nb < NB; nb++)
#pragma unroll
        for (int j = 0; j < 4; j++) acc[nb][j] = 0.f;

    const int gid = lane >> 2, tig = lane & 3;
    const int l16 = lane & 15;
    const int lr  = l16 & 7;
    const int lh  = l16 >> 3;
    const int ahalf = lane >> 4;
    const int r = w >> 1, xbase = (w & 1) * 16;
    const int apx0 = (r + 1) * 34 + 1 + xbase + l16;
    const unsigned bline = sb + B_OFF + (unsigned)lr * 128u;

    for (int ch = 0; ch < NCI; ch++) {
        // ---- stage patch chunk (4 rows x 34 px x 64 ci, hi+lo) ----
        for (int i = tid; i < 2176; i += 128) {
            int c   = i & 7;
            int pxl = (i >> 3) % 136;
            int hl  = i / 1088;
            int y = y0 - 1 + pxl / 34;
            int x = x0 - 1 + pxl % 34;
            bool v = (y >= 0) && (y < HH) && (x >= 0) && (x < WW);
            const __nv_bfloat16* src = (hl ? xlb : xhb)
                + (size_t)((v ? y : 0) * WW + (v ? x : 0)) * XSTR + ch * 64 + c * 8;
            unsigned dst = sb + (unsigned)hl * PATCH_HALF + (unsigned)pxl * 128u
                         + (unsigned)((c ^ (pxl & 7)) << 4);
            cpa16(dst, src, v);
        }
        cpa_commit();

        const int SN = (ch == NCI - 1) ? SLAST : 4;

        for (int tap = 0; tap < 9; tap++) {
            // ---- stage B slice for this tap/chunk ----
            for (int i = tid; i < NOCS * 16; i += 128) {
                int c   = i & 7;
                int row = (i >> 3) % NOCS;
                int hl  = i / (NOCS * 8);
                const __nv_bfloat16* src = (hl ? wl : wh)
                    + ((size_t)tap * NOCTOT + oc0 + row) * XSTR + ch * 64 + c * 8;
                unsigned dst = sb + B_OFF + (unsigned)hl * (NOCS * 128u)
                             + (unsigned)row * 128u + (unsigned)((c ^ (row & 7)) << 4);
                cpa16(dst, src, true);
            }
            cpa_commit();
            cpa_wait0();
            __syncthreads();

            const int ky = tap / 3 - 1, kx = tap % 3 - 1;
            const int apx = apx0 + ky * 34 + kx;
            const unsigned aline = sb + (unsigned)apx * 128u;
            const int a7 = apx & 7;

            for (int s = 0; s < SN; s++) {
                uint32_t ah0, ah1, ah2, ah3, al0, al1, al2, al3;
                unsigned achunk = (unsigned)((s * 2 + ahalf) ^ a7) << 4;
                LDSM4(ah0, ah1, ah2, ah3, aline + achunk);
                LDSM4(al0, al1, al2, al3, aline + PATCH_HALF + achunk);
#pragma unroll
                for (int nb = 0; nb < NB; nb++) {
                    uint32_t bh0, bh1, bl0, bl1;
                    unsigned baddr = bline + (unsigned)nb * 1024u
                                   + (unsigned)(((s * 2 + lh) ^ lr) << 4);
                    LDSM2(bh0, bh1, baddr);
                    LDSM2(bl0, bl1, baddr + NOCS * 128u);
                    MMA16816(acc[nb], ah0, ah1, ah2, ah3, bh0, bh1);
                    MMA16816(acc[nb], al0, al1, al2, al3, bh0, bh1);
                    MMA16816(acc[nb], ah0, ah1, ah2, ah3, bl0, bl1);
                }
            }
            __syncthreads();
        }
    }

    // ---- epilogue ----
    const int ya = y0 + r;
    const int xa = x0 + xbase + gid;
    const size_t pa = (size_t)b * CH_ + (size_t)ya * WW + xa;
    const size_t pb = pa + 8;
    if (!OMOUT) {
#pragma unroll
        for (int nb = 0; nb < NB; nb++) {
            int oc = nb * 8 + tig * 2;
            float b0 = bias[oc], b1 = bias[oc + 1];
#pragma unroll
            for (int hp = 0; hp < 2; hp++) {
                float v0 = acc[nb][2 * hp + 0] + b0;
                float v1 = acc[nb][2 * hp + 1] + b1;
                v0 = (v0 >= 0.f) ? v0 : 0.1f * v0;
                v1 = (v1 >= 0.f) ? v1 : 0.1f * v1;
                __nv_bfloat16 h0 = __float2bfloat16(v0), h1 = __float2bfloat16(v1);
                __nv_bfloat16 l0 = __float2bfloat16(v0 - __bfloat162float(h0));
                __nv_bfloat16 l1 = __float2bfloat16(v1 - __bfloat162float(h1));
                size_t base = ((hp ? pb : pa)) * 64 + oc;
                ((uint32_t*)yh)[base >> 1] =
                    (uint32_t)__bfloat16_as_ushort(h0) | ((uint32_t)__bfloat16_as_ushort(h1) << 16);
                ((uint32_t*)yl)[base >> 1] =
                    (uint32_t)__bfloat16_as_ushort(l0) | ((uint32_t)__bfloat16_as_ushort(l1) << 16);
            }
        }
    } else {
#pragma unroll
        for (int nb = 0; nb < NB; nb++) {
            int oc = oc0 + nb * 8 + tig * 2;
            float b0 = bias[oc], b1 = bias[oc + 1];
            om[pa * 216 + oc]     = acc[nb][0] + b0;
            om[pa * 216 + oc + 1] = acc[nb][1] + b1;
            om[pb * 216 + oc]     = acc[nb][2] + b0;
            om[pb * 216 + oc + 1] = acc[nb][3] + b1;
        }
    }
}

// ---------------- flow-guided DCN + lrelu (NHWC gather + FFMA2) ----------------
__global__ __launch_bounds__(128, 4)
void dcn_k(const float* __restrict__ flows,
           const float* __restrict__ wdcn,
           const float* __restrict__ bdcn,
           float* __restrict__ out)
{
    const int b  = blockIdx.z;
    const int px = threadIdx.x & 31;
    const int py = threadIdx.x >> 5;
    const int w  = blockIdx.x * 32 + px;
    const int h  = blockIdx.y * 4 + py;
    const int tid = threadIdx.x;

    __shared__ __align__(16) float sW[8][9][64];

    unsigned long long acc[32];
#pragma unroll
    for (int i = 0; i < 32; i++) acc[i] = 0ull;

    const float flowx = flows[((size_t)(b * 2 + 0) * HH + h) * WW + w];
    const float flowy = flows[((size_t)(b * 2 + 1) * HH + h) * WW + w];

    const float* omb = g_om + ((size_t)b * CH_ + (size_t)h * WW + w) * 216;
    const float* xb  = g_xt + (size_t)b * CH_ * 64;

    for (int g = 0; g < 8; g++) {
        __syncthreads();
        for (int i = tid; i < 8 * 9 * 64; i += 128) {
            int oc = i & 63;
            int k  = (i >> 6) % 9;
            int c  = i / (64 * 9);
            sW[c][k][oc] = wdcn[((size_t)oc * 64 + g * 8 + c) * 9 + k];
        }
        __syncthreads();

#pragma unroll
        for (int k = 0; k < 9; k++) {
            const int ky = k / 3 - 1;
            const int kx = k % 3 - 1;
            float oy = omb[2 * (g * 9 + k)]     + flowy;
            float ox = omb[2 * (g * 9 + k) + 1] + flowx;
            float mv = omb[144 + g * 9 + k];
            mv = 1.f / (1.f + __expf(-mv));

            float pyf = (float)(h + ky) + oy;
            float pxf = (float)(w + kx) + ox;
            float y0f = floorf(pyf), x0f = floorf(pxf);
            float wy = pyf - y0f, wx = pxf - x0f;
            int iy0 = (int)y0f, ix0 = (int)x0f;
            int iy1 = iy0 + 1, ix1 = ix0 + 1;
            bool vy0 = (iy0 >= 0) & (iy0 < HH);
            bool vy1 = (iy1 >= 0) & (iy1 < HH);
            bool vx0 = (ix0 >= 0) & (ix0 < WW);
            bool vx1 = (ix1 >= 0) & (ix1 < WW);
            int cy0 = min(max(iy0, 0), HH - 1), cy1 = min(max(iy1, 0), HH - 1);
            int cx0 = min(max(ix0, 0), WW - 1), cx1 = min(max(ix1, 0), WW - 1);
            float w00 = (1.f - wy) * (1.f - wx) * ((vy0 && vx0) ? 1.f : 0.f) * mv;
            float w01 = (1.f - wy) * wx         * ((vy0 && vx1) ? 1.f : 0.f) * mv;
            float w10 = wy * (1.f - wx)         * ((vy1 && vx0) ? 1.f : 0.f) * mv;
            float w11 = wy * wx                 * ((vy1 && vx1) ? 1.f : 0.f) * mv;
            const float* p00 = xb + (size_t)(cy0 * WW + cx0) * 64 + g * 8;
            const float* p01 = xb + (size_t)(cy0 * WW + cx1) * 64 + g * 8;
            const float* p10 = xb + (size_t)(cy1 * WW + cx0) * 64 + g * 8;
            const float* p11 = xb + (size_t)(cy1 * WW + cx1) * 64 + g * 8;

#pragma unroll
            for (int half = 0; half < 2; half++) {
                float4 a00 = ((const float4*)p00)[half];
                float4 a01 = ((const float4*)p01)[half];
                float4 a10 = ((const float4*)p10)[half];
                float4 a11 = ((const float4*)p11)[half];
                float s[4];
                s[0] = a00.x * w00 + a01.x * w01 + a10.x * w10 + a11.x * w11;
                s[1] = a00.y * w00 + a01.y * w01 + a10.y * w10 + a11.y * w11;
                s[2] = a00.z * w00 + a01.z * w01 + a10.z * w10 + a11.z * w11;
                s[3] = a00.w * w00 + a01.w * w01 + a10.w * w10 + a11.w * w11;
#pragma unroll
                for (int cc = 0; cc < 4; cc++) {
                    int c = half * 4 + cc;
                    unsigned long long s2 = pack2(s[cc]);
                    const ulonglong2* w2p = (const ulonglong2*)&sW[c][k][0];
#pragma unroll
                    for (int q = 0; q < 8; q++) {
                        ulonglong2 wp = w2p[q];
                        ffma2(acc[4 * q + 0], s2, wp.x);
                        ffma2(acc[4 * q + 1], s2, wp.y);
                        wp = w2p[q + 8];
                        ffma2(acc[4 * q + 2], s2, wp.x);
                        ffma2(acc[4 * q + 3], s2, wp.y);
                    }
                }
            }
        }
    }

#pragma unroll
    for (int q = 0; q < 8; q++) {
#pragma unroll
        for (int j = 0; j < 2; j++) {
            float2 fA = unpack2(acc[4 * q + 2 * j]);
            float2 fB = unpack2(acc[4 * q + 2 * j + 1]);
            int base = (j == 0) ? (4 * q) : (32 + 4 * q);
            float r0 = fA.x + bdcn[base + 0];
            float r1 = fA.y + bdcn[base + 1];
            float r2 = fB.x + bdcn[base + 2];
            float r3 = fB.y + bdcn[base + 3];
            r0 = (r0 >= 0.f) ? r0 : 0.1f * r0;
            r1 = (r1 >= 0.f) ? r1 : 0.1f * r1;
            r2 = (r2 >= 0.f) ? r2 : 0.1f * r2;
            r3 = (r3 >= 0.f) ? r3 : 0.1f * r3;
            out[((size_t)(b * 64 + base + 0) * HH + h) * WW + w] = r0;
            out[((size_t)(b * 64 + base + 1) * HH + h) * WW + w] = r1;
            out[((size_t)(b * 64 + base + 2) * HH + h) * WW + w] = r2;
            out[((size_t)(b * 64 + base + 3) * HH + h) * WW + w] = r3;
        }
    }
}

// ---------------- launch ----------------
extern "C" void kernel_launch(void* const* d_in, const int* in_sizes, int n_in,
                              void* d_out, int out_size)
{
    const float* nbr    = (const float*)d_in[0];
    const float* warped = (const float*)d_in[1];
    const float* ref    = (const float*)d_in[2];
    const float* flows  = (const float*)d_in[3];
    const float* w1     = (const float*)d_in[4];
    const float* b1     = (const float*)d_in[5];
    const float* w2     = (const float*)d_in[6];
    const float* b2     = (const float*)d_in[7];
    const float* w_om   = (const float*)d_in[8];
    const float* b_om   = (const float*)d_in[9];
    const float* w_dcn  = (const float*)d_in[10];
    const float* b_dcn  = (const float*)d_in[11];
    float* out = (float*)d_out;

    float *p_om;
    __nv_bfloat16 *p_x1h, *p_x1l, *p_x2h, *p_x2l, *p_x3h, *p_x3l;
    __nv_bfloat16 *p_w1h, *p_w1l, *p_w2h, *p_w2l, *p_womh, *p_woml;
    cudaGetSymbolAddress((void**)&p_om,   g_om);
    cudaGetSymbolAddress((void**)&p_x1h,  g_x1h);
    cudaGetSymbolAddress((void**)&p_x1l,  g_x1l);
    cudaGetSymbolAddress((void**)&p_x2h,  g_x2h);
    cudaGetSymbolAddress((void**)&p_x2l,  g_x2l);
    cudaGetSymbolAddress((void**)&p_x3h,  g_x3h);
    cudaGetSymbolAddress((void**)&p_x3l,  g_x3l);
    cudaGetSymbolAddress((void**)&p_w1h,  g_w1h);
    cudaGetSymbolAddress((void**)&p_w1l,  g_w1l);
    cudaGetSymbolAddress((void**)&p_w2h,  g_w2h);
    cudaGetSymbolAddress((void**)&p_w2l,  g_w2l);
    cudaGetSymbolAddress((void**)&p_womh, g_womh);
    cudaGetSymbolAddress((void**)&p_woml, g_woml);

    const int SMEMC = 34816 + 64 * 256;   // 51200 (conv1 / conv2)
    const int SMEMO = 34816 + 72 * 256;   // 53248 (conv_om)
    cudaFuncSetAttribute(mconv_k<3, 1, 64, 64,  false>, cudaFuncAttributeMaxDynamicSharedMemorySize, SMEMC);
    cudaFuncSetAttribute(mconv_k<1, 4, 64, 64,  false>, cudaFuncAttributeMaxDynamicSharedMemorySize, SMEMC);
    cudaFuncSetAttribute(mconv_k<1, 4, 72, 216, true >, cudaFuncAttributeMaxDynamicSharedMemorySize, SMEMO);

    // 0. input/weight prep
    {
        dim3 gc(CH_ / 32, 6, BB);
        cat_k<<<gc, dim3(32, 8)>>>(warped, ref, flows);
        int t1 = 9 * 64 * 192;
        wsplit_k<<<(t1 + 255) / 256, 256>>>(w1, 64, 130, 192, p_w1h, p_w1l, t1);
        int t2 = 9 * 64 * 64;
        wsplit_k<<<(t2 + 255) / 256, 256>>>(w2, 64, 64, 64, p_w2h, p_w2l, t2);
        int t3 = 9 * 216 * 64;
        wsplit_k<<<(t3 + 255) / 256, 256>>>(w_om, 216, 64, 64, p_womh, p_woml, t3);
        dim3 gn(CH_ / 32, 2, BB);
        nhwc_k<<<gn, dim3(32, 8)>>>(nbr);
    }
    // 1. conv1 (HMMA, 3 ci-chunks, last chunk 1 K16 step): 130(192) -> 64, lrelu
    {
        dim3 grid(WW / 32, HH / 2, BB);
        mconv_k<3, 1, 64, 64, false><<<grid, 128, SMEMC>>>(p_x1h, p_x1l, p_w1h, p_w1l, b1,
                                                           p_x2h, p_x2l, nullptr);
    }
    // 2. conv2 (HMMA): 64 -> 64, lrelu
    {
        dim3 grid(WW / 32, HH / 2, BB);
        mconv_k<1, 4, 64, 64, false><<<grid, 128, SMEMC>>>(p_x2h, p_x2l, p_w2h, p_w2l, b2,
                                                           p_x3h, p_x3l, nullptr);
    }
    // 3. conv_om (HMMA): 64 -> 216 (3 slices of 72), linear, fp32 NHWC
    {
        dim3 grid(WW / 32, HH / 2, BB * 3);
        mconv_k<1, 4, 72, 216, true><<<grid, 128, SMEMO>>>(p_x3h, p_x3l, p_womh, p_woml, b_om,
                                                           nullptr, nullptr, p_om);
    }
    // 4. DCN + lrelu
    {
        dim3 grid(WW / 32, HH / 4, BB);
        dcn_k<<<grid, 128>>>(flows, w_dcn, b_dcn, out);
    }
}

// round 11
// speedup vs baseline: 2.6613x; 1.0452x over previous
#include <cuda_runtime.h>
#include <cuda_bf16.h>
#include <cstdint>

#define HH 192
#define WW 320
#define BB 2
#define CH_ (HH * WW)

// -------- scratch (device globals; no allocations allowed) --------
__device__ float g_xt  [BB * (size_t)CH_ * 64];         // nbr NHWC (dcn)
__device__ __nv_bfloat16 g_x1h[BB * (size_t)CH_ * 192]; // concat in hi (NHWC, pad 192)
__device__ __nv_bfloat16 g_x1l[BB * (size_t)CH_ * 192];
__device__ __nv_bfloat16 g_x2h[BB * (size_t)CH_ * 64];  // conv1 out hi (NHWC)
__device__ __nv_bfloat16 g_x2l[BB * (size_t)CH_ * 64];
__device__ __nv_bfloat16 g_x3h[BB * (size_t)CH_ * 64];  // conv2 out hi
__device__ __nv_bfloat16 g_x3l[BB * (size_t)CH_ * 64];
__device__ float g_om  [BB * 216 * (size_t)CH_];        // conv_om out (PLANAR NCHW)
__device__ __nv_bfloat16 g_w1h[9 * 64 * 192];           // w1 hi [k][oc][192]
__device__ __nv_bfloat16 g_w1l[9 * 64 * 192];
__device__ __nv_bfloat16 g_w2h[9 * 64 * 64];            // w2 hi [k][oc][64]
__device__ __nv_bfloat16 g_w2l[9 * 64 * 64];
__device__ __nv_bfloat16 g_womh[9 * 216 * 64];          // w_om hi [k][oc][64]
__device__ __nv_bfloat16 g_woml[9 * 216 * 64];

// -------- packed f32x2 helpers --------
__device__ __forceinline__ void ffma2(unsigned long long& d,
                                      unsigned long long a,
                                      unsigned long long b) {
    asm("fma.rn.f32x2 %0, %1, %2, %0;" : "+l"(d) : "l"(a), "l"(b));
}
__device__ __forceinline__ unsigned long long pack2(float s) {
    unsigned long long r;
    asm("mov.b64 %0, {%1, %1};" : "=l"(r) : "f"(s));
    return r;
}
__device__ __forceinline__ float2 unpack2(unsigned long long v) {
    float2 f;
    asm("mov.b64 {%0, %1}, %2;" : "=f"(f.x), "=f"(f.y) : "l"(v));
    return f;
}

// -------- cp.async helpers --------
__device__ __forceinline__ void cpa16(unsigned dst, const void* src, bool valid) {
    asm volatile("cp.async.cg.shared.global [%0], [%1], 16, %2;"
                 :: "r"(dst), "l"(src), "r"(valid ? 16u : 0u));
}
__device__ __forceinline__ void cpa_commit() { asm volatile("cp.async.commit_group;"); }
__device__ __forceinline__ void cpa_wait0()  { asm volatile("cp.async.wait_group 0;"); }

__device__ __forceinline__ uint32_t smem_u32(const void* p) {
    uint32_t a;
    asm("{ .reg .u64 t; cvta.to.shared.u64 t, %1; cvt.u32.u64 %0, t; }" : "=r"(a) : "l"(p));
    return a;
}

// -------- mma.sync helpers --------
#define LDSM4(r0, r1, r2, r3, a) \
    asm volatile("ldmatrix.sync.aligned.m8n8.x4.shared.b16 {%0,%1,%2,%3}, [%4];" \
                 : "=r"(r0), "=r"(r1), "=r"(r2), "=r"(r3) : "r"(a))
#define LDSM2(r0, r1, a) \
    asm volatile("ldmatrix.sync.aligned.m8n8.x2.shared.b16 {%0,%1}, [%2];" \
                 : "=r"(r0), "=r"(r1) : "r"(a))
#define MMA16816(d, a0, a1, a2, a3, b0, b1) \
    asm volatile("mma.sync.aligned.m16n8k16.row.col.f32.bf16.bf16.f32 " \
                 "{%0,%1,%2,%3}, {%4,%5,%6,%7}, {%8,%9}, {%0,%1,%2,%3};" \
                 : "+f"((d)[0]), "+f"((d)[1]), "+f"((d)[2]), "+f"((d)[3]) \
                 : "r"(a0), "r"(a1), "r"(a2), "r"(a3), "r"(b0), "r"(b1))

// ---------------- concat -> NHWC bf16 hi/lo, 192-ch padded ----------------
__global__ void cat_k(const float* __restrict__ warped, const float* __restrict__ ref,
                      const float* __restrict__ flows)
{
    __shared__ float t[32][33];
    const int hw0 = blockIdx.x * 32;
    const int c0  = blockIdx.y * 32;
    const int b   = blockIdx.z;
    const int tx  = threadIdx.x, ty = threadIdx.y;
#pragma unroll
    for (int i = ty; i < 32; i += 8) {
        int cg = c0 + i;
        float v = 0.f;
        if (cg < 64)        v = warped[((size_t)(b * 64 + cg)) * CH_ + hw0 + tx];
        else if (cg < 128)  v = ref   [((size_t)(b * 64 + cg - 64)) * CH_ + hw0 + tx];
        else if (cg < 130)  v = flows [((size_t)(b * 2  + cg - 128)) * CH_ + hw0 + tx];
        t[i][tx] = v;
    }
    __syncthreads();
#pragma unroll
    for (int i = ty; i < 32; i += 8) {
        float v = t[tx][i];
        __nv_bfloat16 hi = __float2bfloat16(v);
        __nv_bfloat16 lo = __float2bfloat16(v - __bfloat162float(hi));
        size_t o = ((size_t)b * CH_ + hw0 + i) * 192 + c0 + tx;
        g_x1h[o] = hi;
        g_x1l[o] = lo;
    }
}

// ---------------- weight hi/lo split: [oc][ci][k] -> [k][oc][CINP] bf16 ----------------
__global__ void wsplit_k(const float* __restrict__ w, int NOC, int CINR, int CINP,
                         __nv_bfloat16* __restrict__ wh, __nv_bfloat16* __restrict__ wl,
                         int total)
{
    int i = blockIdx.x * blockDim.x + threadIdx.x;
    if (i >= total) return;
    int ci = i % CINP;
    int oc = (i / CINP) % NOC;
    int k  = i / (CINP * NOC);
    float v = (ci < CINR) ? w[((size_t)oc * CINR + ci) * 9 + k] : 0.f;
    __nv_bfloat16 hi = __float2bfloat16(v);
    wh[i] = hi;
    wl[i] = __float2bfloat16(v - __bfloat162float(hi));
}

// ---------------- NCHW -> NHWC repack of nbr features (for dcn) ----------------
__global__ void nhwc_k(const float* __restrict__ x)
{
    __shared__ float t[32][33];
    const int hw0 = blockIdx.x * 32;
    const int c0  = blockIdx.y * 32;
    const int b   = blockIdx.z;
    const int tx  = threadIdx.x, ty = threadIdx.y;
#pragma unroll
    for (int i = ty; i < 32; i += 8)
        t[i][tx] = x[((size_t)(b * 64 + c0 + i)) * CH_ + hw0 + tx];
    __syncthreads();
#pragma unroll
    for (int i = ty; i < 32; i += 8)
        g_xt[((size_t)b * CH_ + hw0 + i) * 64 + c0 + tx] = t[tx][i];
}

// ---------------- mma.sync 3x3 conv, B double-buffered ----------------
// grid: (WW/32, HH/2, BB * (NOCTOT/NOCS)), block = 128
template<int NCI, int SLAST, int NOCS, int NOCTOT, bool OMOUT>
__global__ __launch_bounds__(128)
void mconv_k(const __nv_bfloat16* __restrict__ xh, const __nv_bfloat16* __restrict__ xl,
             const __nv_bfloat16* __restrict__ wh, const __nv_bfloat16* __restrict__ wl,
             const float* __restrict__ bias,
             __nv_bfloat16* __restrict__ yh, __nv_bfloat16* __restrict__ yl,
             float* __restrict__ om)
{
    constexpr int NB = NOCS / 8;
    constexpr int NSL = NOCTOT / NOCS;
    constexpr int XSTR = NCI * 64;
    constexpr unsigned PATCH_HALF = 4 * 34 * 128;     // 17408
    constexpr unsigned B_OFF = 2 * PATCH_HALF;        // 34816
    constexpr unsigned BBUF = (unsigned)NOCS * 256u;  // hi+lo per buffer

    extern __shared__ __align__(128) char smraw[];
    const unsigned sb = smem_u32(smraw);

    const int tid  = threadIdx.x;
    const int w    = tid >> 5;
    const int lane = tid & 31;
    const int b    = blockIdx.z / NSL;
    const int oc0  = (blockIdx.z % NSL) * NOCS;
    const int x0   = blockIdx.x * 32;
    const int y0   = blockIdx.y * 2;

    const __nv_bfloat16* xhb = xh + (size_t)b * CH_ * XSTR;
    const __nv_bfloat16* xlb = xl + (size_t)b * CH_ * XSTR;

    float acc[NB][4];
#pragma unroll
    for (int nb = 0; nb < NB; nb++)
#pragma unroll
        for (int j = 0; j < 4; j++) acc[nb][j] = 0.f;

    const int gid = lane >> 2, tig = lane & 3;
    const int l16 = lane & 15;
    const int lr  = l16 & 7;
    const int lh  = l16 >> 3;
    const int ahalf = lane >> 4;
    const int r = w >> 1, xbase = (w & 1) * 16;
    const int apx0 = (r + 1) * 34 + 1 + xbase + l16;

    auto stage_B = [&](int ch, int tap, int buf) {
        for (int i = tid; i < NOCS * 16; i += 128) {
            int c   = i & 7;
            int row = (i >> 3) % NOCS;
            int hl  = i / (NOCS * 8);
            const __nv_bfloat16* src = (hl ? wl : wh)
                + ((size_t)tap * NOCTOT + oc0 + row) * XSTR + ch * 64 + c * 8;
            unsigned dst = sb + B_OFF + (unsigned)buf * BBUF + (unsigned)hl * (NOCS * 128u)
                         + (unsigned)row * 128u + (unsigned)((c ^ (row & 7)) << 4);
            cpa16(dst, src, true);
        }
    };

    int buf = 0;
    for (int ch = 0; ch < NCI; ch++) {
        if (ch > 0) __syncthreads();  // patch reads of prev chunk done
        // ---- stage patch chunk + first B tile (one group) ----
        for (int i = tid; i < 2176; i += 128) {
            int c   = i & 7;
            int pxl = (i >> 3) % 136;
            int hl  = i / 1088;
            int y = y0 - 1 + pxl / 34;
            int x = x0 - 1 + pxl % 34;
            bool v = (y >= 0) && (y < HH) && (x >= 0) && (x < WW);
            const __nv_bfloat16* src = (hl ? xlb : xhb)
                + (size_t)((v ? y : 0) * WW + (v ? x : 0)) * XSTR + ch * 64 + c * 8;
            unsigned dst = sb + (unsigned)hl * PATCH_HALF + (unsigned)pxl * 128u
                         + (unsigned)((c ^ (pxl & 7)) << 4);
            cpa16(dst, src, v);
        }
        stage_B(ch, 0, buf);
        cpa_commit();

        const int SN = (ch == NCI - 1) ? SLAST : 4;

        for (int tap = 0; tap < 9; tap++) {
            cpa_wait0();
            __syncthreads();                       // B(tap)+patch ready; prior reads done
            if (tap + 1 < 9) {                     // overlap: stage next B while computing
                stage_B(ch, tap + 1, buf ^ 1);
                cpa_commit();
            }

            const int ky = tap / 3 - 1, kx = tap % 3 - 1;
            const int apx = apx0 + ky * 34 + kx;
            const unsigned aline = sb + (unsigned)apx * 128u;
            const int a7 = apx & 7;
            const unsigned bline = sb + B_OFF + (unsigned)buf * BBUF + (unsigned)lr * 128u;

            for (int s = 0; s < SN; s++) {
                uint32_t ah0, ah1, ah2, ah3, al0, al1, al2, al3;
                unsigned achunk = (unsigned)((s * 2 + ahalf) ^ a7) << 4;
                LDSM4(ah0, ah1, ah2, ah3, aline + achunk);
                LDSM4(al0, al1, al2, al3, aline + PATCH_HALF + achunk);
#pragma unroll
                for (int nb = 0; nb < NB; nb++) {
                    uint32_t bh0, bh1, bl0, bl1;
                    unsigned baddr = bline + (unsigned)nb * 1024u
                                   + (unsigned)(((s * 2 + lh) ^ lr) << 4);
                    LDSM2(bh0, bh1, baddr);
                    LDSM2(bl0, bl1, baddr + NOCS * 128u);
                    MMA16816(acc[nb], ah0, ah1, ah2, ah3, bh0, bh1);
                    MMA16816(acc[nb], al0, al1, al2, al3, bh0, bh1);
                    MMA16816(acc[nb], ah0, ah1, ah2, ah3, bl0, bl1);
                }
            }
            buf ^= 1;
        }
    }

    // ---- epilogue ----
    const int ya = y0 + r;
    const int xa = x0 + xbase + gid;
    const int pixA = ya * WW + xa;
    const int pixB = pixA + 8;
    if (!OMOUT) {
        const size_t pa = (size_t)b * CH_ + pixA;
        const size_t pb = pa + 8;
#pragma unroll
        for (int nb = 0; nb < NB; nb++) {
            int oc = nb * 8 + tig * 2;
            float b0 = bias[oc], b1 = bias[oc + 1];
#pragma unroll
            for (int hp = 0; hp < 2; hp++) {
                float v0 = acc[nb][2 * hp + 0] + b0;
                float v1 = acc[nb][2 * hp + 1] + b1;
                v0 = (v0 >= 0.f) ? v0 : 0.1f * v0;
                v1 = (v1 >= 0.f) ? v1 : 0.1f * v1;
                __nv_bfloat16 h0 = __float2bfloat16(v0), h1 = __float2bfloat16(v1);
                __nv_bfloat16 l0 = __float2bfloat16(v0 - __bfloat162float(h0));
                __nv_bfloat16 l1 = __float2bfloat16(v1 - __bfloat162float(h1));
                size_t base = ((hp ? pb : pa)) * 64 + oc;
                ((uint32_t*)yh)[base >> 1] =
                    (uint32_t)__bfloat16_as_ushort(h0) | ((uint32_t)__bfloat16_as_ushort(h1) << 16);
                ((uint32_t*)yl)[base >> 1] =
                    (uint32_t)__bfloat16_as_ushort(l0) | ((uint32_t)__bfloat16_as_ushort(l1) << 16);
            }
        }
    } else {
        // planar NCHW: om[(b*216+oc)*CH_ + pix]
#pragma unroll
        for (int nb = 0; nb < NB; nb++) {
            int oc = oc0 + nb * 8 + tig * 2;
            float b0 = bias[oc], b1 = bias[oc + 1];
            float* pl0 = om + ((size_t)(b * 216 + oc))     * CH_;
            float* pl1 = om + ((size_t)(b * 216 + oc + 1)) * CH_;
            pl0[pixA] = acc[nb][0] + b0;
            pl1[pixA] = acc[nb][1] + b1;
            pl0[pixB] = acc[nb][2] + b0;
            pl1[pixB] = acc[nb][3] + b1;
        }
    }
}

// ---------------- flow-guided DCN + lrelu (NHWC gather + FFMA2, planar om) ----------------
__global__ __launch_bounds__(128, 4)
void dcn_k(const float* __restrict__ flows,
           const float* __restrict__ wdcn,
           const float* __restrict__ bdcn,
           float* __restrict__ out)
{
    const int b  = blockIdx.z;
    const int px = threadIdx.x & 31;
    const int py = threadIdx.x >> 5;
    const int w  = blockIdx.x * 32 + px;
    const int h  = blockIdx.y * 4 + py;
    const int tid = threadIdx.x;

    __shared__ __align__(16) float sW[8][9][64];

    unsigned long long acc[32];
#pragma unroll
    for (int i = 0; i < 32; i++) acc[i] = 0ull;

    const float flowx = flows[((size_t)(b * 2 + 0) * HH + h) * WW + w];
    const float flowy = flows[((size_t)(b * 2 + 1) * HH + h) * WW + w];

    const float* omb = g_om + (size_t)b * 216 * CH_ + (size_t)h * WW + w;  // planar
    const float* xb  = g_xt + (size_t)b * CH_ * 64;

    for (int g = 0; g < 8; g++) {
        __syncthreads();
        for (int i = tid; i < 8 * 9 * 64; i += 128) {
            int oc = i & 63;
            int k  = (i >> 6) % 9;
            int c  = i / (64 * 9);
            sW[c][k][oc] = wdcn[((size_t)oc * 64 + g * 8 + c) * 9 + k];
        }
        __syncthreads();

#pragma unroll
        for (int k = 0; k < 9; k++) {
            const int ky = k / 3 - 1;
            const int kx = k % 3 - 1;
            float oy = omb[(size_t)(2 * (g * 9 + k))     * CH_] + flowy;
            float ox = omb[(size_t)(2 * (g * 9 + k) + 1) * CH_] + flowx;
            float mv = omb[(size_t)(144 + g * 9 + k)     * CH_];
            mv = 1.f / (1.f + __expf(-mv));

            float pyf = (float)(h + ky) + oy;
            float pxf = (float)(w + kx) + ox;
            float y0f = floorf(pyf), x0f = floorf(pxf);
            float wy = pyf - y0f, wx = pxf - x0f;
            int iy0 = (int)y0f, ix0 = (int)x0f;
            int iy1 = iy0 + 1, ix1 = ix0 + 1;
            bool vy0 = (iy0 >= 0) & (iy0 < HH);
            bool vy1 = (iy1 >= 0) & (iy1 < HH);
            bool vx0 = (ix0 >= 0) & (ix0 < WW);
            bool vx1 = (ix1 >= 0) & (ix1 < WW);
            int cy0 = min(max(iy0, 0), HH - 1), cy1 = min(max(iy1, 0), HH - 1);
            int cx0 = min(max(ix0, 0), WW - 1), cx1 = min(max(ix1, 0), WW - 1);
            float w00 = (1.f - wy) * (1.f - wx) * ((vy0 && vx0) ? 1.f : 0.f) * mv;
            float w01 = (1.f - wy) * wx         * ((vy0 && vx1) ? 1.f : 0.f) * mv;
            float w10 = wy * (1.f - wx)         * ((vy1 && vx0) ? 1.f : 0.f) * mv;
            float w11 = wy * wx                 * ((vy1 && vx1) ? 1.f : 0.f) * mv;
            const float* p00 = xb + (size_t)(cy0 * WW + cx0) * 64 + g * 8;
            const float* p01 = xb + (size_t)(cy0 * WW + cx1) * 64 + g * 8;
            const float* p10 = xb + (size_t)(cy1 * WW + cx0) * 64 + g * 8;
            const float* p11 = xb + (size_t)(cy1 * WW + cx1) * 64 + g * 8;

#pragma unroll
            for (int half = 0; half < 2; half++) {
                float4 a00 = ((const float4*)p00)[half];
                float4 a01 = ((const float4*)p01)[half];
                float4 a10 = ((const float4*)p10)[half];
                float4 a11 = ((const float4*)p11)[half];
                float s[4];
                s[0] = a00.x * w00 + a01.x * w01 + a10.x * w10 + a11.x * w11;
                s[1] = a00.y * w00 + a01.y * w01 + a10.y * w10 + a11.y * w11;
                s[2] = a00.z * w00 + a01.z * w01 + a10.z * w10 + a11.z * w11;
                s[3] = a00.w * w00 + a01.w * w01 + a10.w * w10 + a11.w * w11;
#pragma unroll
                for (int cc = 0; cc < 4; cc++) {
                    int c = half * 4 + cc;
                    unsigned long long s2 = pack2(s[cc]);
                    const ulonglong2* w2p = (const ulonglong2*)&sW[c][k][0];
#pragma unroll
                    for (int q = 0; q < 8; q++) {
                        ulonglong2 wp = w2p[q];
                        ffma2(acc[4 * q + 0], s2, wp.x);
                        ffma2(acc[4 * q + 1], s2, wp.y);
                        wp = w2p[q + 8];
                        ffma2(acc[4 * q + 2], s2, wp.x);
                        ffma2(acc[4 * q + 3], s2, wp.y);
                    }
                }
            }
        }
    }

#pragma unroll
    for (int q = 0; q < 8; q++) {
#pragma unroll
        for (int j = 0; j < 2; j++) {
            float2 fA = unpack2(acc[4 * q + 2 * j]);
            float2 fB = unpack2(acc[4 * q + 2 * j + 1]);
            int base = (j == 0) ? (4 * q) : (32 + 4 * q);
            float r0 = fA.x + bdcn[base + 0];
            float r1 = fA.y + bdcn[base + 1];
            float r2 = fB.x + bdcn[base + 2];
            float r3 = fB.y + bdcn[base + 3];
            r0 = (r0 >= 0.f) ? r0 : 0.1f * r0;
            r1 = (r1 >= 0.f) ? r1 : 0.1f * r1;
            r2 = (r2 >= 0.f) ? r2 : 0.1f * r2;
            r3 = (r3 >= 0.f) ? r3 : 0.1f * r3;
            out[((size_t)(b * 64 + base + 0) * HH + h) * WW + w] = r0;
            out[((size_t)(b * 64 + base + 1) * HH + h) * WW + w] = r1;
            out[((size_t)(b * 64 + base + 2) * HH + h) * WW + w] = r2;
            out[((size_t)(b * 64 + base + 3) * HH + h) * WW + w] = r3;
        }
    }
}

// ---------------- launch ----------------
extern "C" void kernel_launch(void* const* d_in, const int* in_sizes, int n_in,
                              void* d_out, int out_size)
{
    const float* nbr    = (const float*)d_in[0];
    const float* warped = (const float*)d_in[1];
    const float* ref    = (const float*)d_in[2];
    const float* flows  = (const float*)d_in[3];
    const float* w1     = (const float*)d_in[4];
    const float* b1     = (const float*)d_in[5];
    const float* w2     = (const float*)d_in[6];
    const float* b2     = (const float*)d_in[7];
    const float* w_om   = (const float*)d_in[8];
    const float* b_om   = (const float*)d_in[9];
    const float* w_dcn  = (const float*)d_in[10];
    const float* b_dcn  = (const float*)d_in[11];
    float* out = (float*)d_out;

    float *p_om;
    __nv_bfloat16 *p_x1h, *p_x1l, *p_x2h, *p_x2l, *p_x3h, *p_x3l;
    __nv_bfloat16 *p_w1h, *p_w1l, *p_w2h, *p_w2l, *p_womh, *p_woml;
    cudaGetSymbolAddress((void**)&p_om,   g_om);
    cudaGetSymbolAddress((void**)&p_x1h,  g_x1h);
    cudaGetSymbolAddress((void**)&p_x1l,  g_x1l);
    cudaGetSymbolAddress((void**)&p_x2h,  g_x2h);
    cudaGetSymbolAddress((void**)&p_x2l,  g_x2l);
    cudaGetSymbolAddress((void**)&p_x3h,  g_x3h);
    cudaGetSymbolAddress((void**)&p_x3l,  g_x3l);
    cudaGetSymbolAddress((void**)&p_w1h,  g_w1h);
    cudaGetSymbolAddress((void**)&p_w1l,  g_w1l);
    cudaGetSymbolAddress((void**)&p_w2h,  g_w2h);
    cudaGetSymbolAddress((void**)&p_w2l,  g_w2l);
    cudaGetSymbolAddress((void**)&p_womh, g_womh);
    cudaGetSymbolAddress((void**)&p_woml, g_woml);

    const int SMEMC = 34816 + 2 * 64 * 256;   // 67584 (conv1 / conv2)
    const int SMEMO = 34816 + 2 * 72 * 256;   // 71680 (conv_om)
    cudaFuncSetAttribute(mconv_k<3, 1, 64, 64,  false>, cudaFuncAttributeMaxDynamicSharedMemorySize, SMEMC);
    cudaFuncSetAttribute(mconv_k<1, 4, 64, 64,  false>, cudaFuncAttributeMaxDynamicSharedMemorySize, SMEMC);
    cudaFuncSetAttribute(mconv_k<1, 4, 72, 216, true >, cudaFuncAttributeMaxDynamicSharedMemorySize, SMEMO);

    // 0. input/weight prep
    {
        dim3 gc(CH_ / 32, 6, BB);
        cat_k<<<gc, dim3(32, 8)>>>(warped, ref, flows);
        int t1 = 9 * 64 * 192;
        wsplit_k<<<(t1 + 255) / 256, 256>>>(w1, 64, 130, 192, p_w1h, p_w1l, t1);
        int t2 = 9 * 64 * 64;
        wsplit_k<<<(t2 + 255) / 256, 256>>>(w2, 64, 64, 64, p_w2h, p_w2l, t2);
        int t3 = 9 * 216 * 64;
        wsplit_k<<<(t3 + 255) / 256, 256>>>(w_om, 216, 64, 64, p_womh, p_woml, t3);
        dim3 gn(CH_ / 32, 2, BB);
        nhwc_k<<<gn, dim3(32, 8)>>>(nbr);
    }
    // 1. conv1 (HMMA): 130(192) -> 64, lrelu
    {
        dim3 grid(WW / 32, HH / 2, BB);
        mconv_k<3, 1, 64, 64, false><<<grid, 128, SMEMC>>>(p_x1h, p_x1l, p_w1h, p_w1l, b1,
                                                           p_x2h, p_x2l, nullptr);
    }
    // 2. conv2 (HMMA): 64 -> 64, lrelu
    {
        dim3 grid(WW / 32, HH / 2, BB);
        mconv_k<1, 4, 64, 64, false><<<grid, 128, SMEMC>>>(p_x2h, p_x2l, p_w2h, p_w2l, b2,
                                                           p_x3h, p_x3l, nullptr);
    }
    // 3. conv_om (HMMA): 64 -> 216 (3 slices of 72), linear, planar fp32
    {
        dim3 grid(WW / 32, HH / 2, BB * 3);
        mconv_k<1, 4, 72, 216, true><<<grid, 128, SMEMO>>>(p_x3h, p_x3l, p_womh, p_woml, b_om,
                                                           nullptr, nullptr, p_om);
    }
    // 4. DCN + lrelu
    {
        dim3 grid(WW / 32, HH / 4, BB);
        dcn_k<<<grid, 128>>>(flows, w_dcn, b_dcn, out);
    }
}

// round 12
// speedup vs baseline: 2.7172x; 1.0210x over previous
#include <cuda_runtime.h>
#include <cuda_bf16.h>
#include <cstdint>

#define HH 192
#define WW 320
#define BB 2
#define CH_ (HH * WW)

// -------- scratch (device globals; no allocations allowed) --------
__device__ float g_xt  [BB * (size_t)CH_ * 64];         // nbr NHWC (dcn)
__device__ __nv_bfloat16 g_x1h[BB * (size_t)CH_ * 192]; // concat in hi (NHWC, pad 192)
__device__ __nv_bfloat16 g_x1l[BB * (size_t)CH_ * 192];
__device__ __nv_bfloat16 g_x2h[BB * (size_t)CH_ * 64];  // conv1 out hi (NHWC)
__device__ __nv_bfloat16 g_x2l[BB * (size_t)CH_ * 64];
__device__ __nv_bfloat16 g_x3h[BB * (size_t)CH_ * 64];  // conv2 out hi
__device__ __nv_bfloat16 g_x3l[BB * (size_t)CH_ * 64];
__device__ float g_om  [BB * 216 * (size_t)CH_];        // conv_om out (PLANAR NCHW)
__device__ __nv_bfloat16 g_w1h[9 * 64 * 192];           // w1 hi [k][oc][192]
__device__ __nv_bfloat16 g_w1l[9 * 64 * 192];
__device__ __nv_bfloat16 g_w2h[9 * 64 * 64];            // w2 hi [k][oc][64]
__device__ __nv_bfloat16 g_w2l[9 * 64 * 64];
__device__ __nv_bfloat16 g_womh[9 * 216 * 64];          // w_om hi [k][oc][64]
__device__ __nv_bfloat16 g_woml[9 * 216 * 64];

// -------- packed f32x2 helpers --------
__device__ __forceinline__ void ffma2(unsigned long long& d,
                                      unsigned long long a,
                                      unsigned long long b) {
    asm("fma.rn.f32x2 %0, %1, %2, %0;" : "+l"(d) : "l"(a), "l"(b));
}
__device__ __forceinline__ unsigned long long pack2(float s) {
    unsigned long long r;
    asm("mov.b64 %0, {%1, %1};" : "=l"(r) : "f"(s));
    return r;
}
__device__ __forceinline__ float2 unpack2(unsigned long long v) {
    float2 f;
    asm("mov.b64 {%0, %1}, %2;" : "=f"(f.x), "=f"(f.y) : "l"(v));
    return f;
}

// -------- cp.async helpers --------
__device__ __forceinline__ void cpa16(unsigned dst, const void* src, bool valid) {
    asm volatile("cp.async.cg.shared.global [%0], [%1], 16, %2;"
                 :: "r"(dst), "l"(src), "r"(valid ? 16u : 0u));
}
__device__ __forceinline__ void cpa_commit() { asm volatile("cp.async.commit_group;"); }
__device__ __forceinline__ void cpa_wait0()  { asm volatile("cp.async.wait_group 0;"); }

__device__ __forceinline__ uint32_t smem_u32(const void* p) {
    uint32_t a;
    asm("{ .reg .u64 t; cvta.to.shared.u64 t, %1; cvt.u32.u64 %0, t; }" : "=r"(a) : "l"(p));
    return a;
}

// -------- mma.sync helpers --------
#define LDSM4(r0, r1, r2, r3, a) \
    asm volatile("ldmatrix.sync.aligned.m8n8.x4.shared.b16 {%0,%1,%2,%3}, [%4];" \
                 : "=r"(r0), "=r"(r1), "=r"(r2), "=r"(r3) : "r"(a))
#define LDSM2(r0, r1, a) \
    asm volatile("ldmatrix.sync.aligned.m8n8.x2.shared.b16 {%0,%1}, [%2];" \
                 : "=r"(r0), "=r"(r1) : "r"(a))
#define MMA16816(d, a0, a1, a2, a3, b0, b1) \
    asm volatile("mma.sync.aligned.m16n8k16.row.col.f32.bf16.bf16.f32 " \
                 "{%0,%1,%2,%3}, {%4,%5,%6,%7}, {%8,%9}, {%0,%1,%2,%3};" \
                 : "+f"((d)[0]), "+f"((d)[1]), "+f"((d)[2]), "+f"((d)[3]) \
                 : "r"(a0), "r"(a1), "r"(a2), "r"(a3), "r"(b0), "r"(b1))

// ---------------- concat -> NHWC bf16 hi/lo, 192-ch padded ----------------
__global__ void cat_k(const float* __restrict__ warped, const float* __restrict__ ref,
                      const float* __restrict__ flows)
{
    __shared__ float t[32][33];
    const int hw0 = blockIdx.x * 32;
    const int c0  = blockIdx.y * 32;
    const int b   = blockIdx.z;
    const int tx  = threadIdx.x, ty = threadIdx.y;
#pragma unroll
    for (int i = ty; i < 32; i += 8) {
        int cg = c0 + i;
        float v = 0.f;
        if (cg < 64)        v = warped[((size_t)(b * 64 + cg)) * CH_ + hw0 + tx];
        else if (cg < 128)  v = ref   [((size_t)(b * 64 + cg - 64)) * CH_ + hw0 + tx];
        else if (cg < 130)  v = flows [((size_t)(b * 2  + cg - 128)) * CH_ + hw0 + tx];
        t[i][tx] = v;
    }
    __syncthreads();
#pragma unroll
    for (int i = ty; i < 32; i += 8) {
        float v = t[tx][i];
        __nv_bfloat16 hi = __float2bfloat16(v);
        __nv_bfloat16 lo = __float2bfloat16(v - __bfloat162float(hi));
        size_t o = ((size_t)b * CH_ + hw0 + i) * 192 + c0 + tx;
        g_x1h[o] = hi;
        g_x1l[o] = lo;
    }
}

// ---------------- weight hi/lo split: [oc][ci][k] -> [k][oc][CINP] bf16 ----------------
__global__ void wsplit_k(const float* __restrict__ w, int NOC, int CINR, int CINP,
                         __nv_bfloat16* __restrict__ wh, __nv_bfloat16* __restrict__ wl,
                         int total)
{
    int i = blockIdx.x * blockDim.x + threadIdx.x;
    if (i >= total) return;
    int ci = i % CINP;
    int oc = (i / CINP) % NOC;
    int k  = i / (CINP * NOC);
    float v = (ci < CINR) ? w[((size_t)oc * CINR + ci) * 9 + k] : 0.f;
    __nv_bfloat16 hi = __float2bfloat16(v);
    wh[i] = hi;
    wl[i] = __float2bfloat16(v - __bfloat162float(hi));
}

// ---------------- NCHW -> NHWC repack of nbr features (for dcn) ----------------
__global__ void nhwc_k(const float* __restrict__ x)
{
    __shared__ float t[32][33];
    const int hw0 = blockIdx.x * 32;
    const int c0  = blockIdx.y * 32;
    const int b   = blockIdx.z;
    const int tx  = threadIdx.x, ty = threadIdx.y;
#pragma unroll
    for (int i = ty; i < 32; i += 8)
        t[i][tx] = x[((size_t)(b * 64 + c0 + i)) * CH_ + hw0 + tx];
    __syncthreads();
#pragma unroll
    for (int i = ty; i < 32; i += 8)
        g_xt[((size_t)b * CH_ + hw0 + i) * 64 + c0 + tx] = t[tx][i];
}

// ---------------- mma.sync 3x3 conv, 4-row tile, B double-buffered ----------------
// block = 256 thr (8 warps), out tile 4 rows x 32 px (M=128). Patch 6x34 px.
// grid: (WW/32, HH/4, BB * (NOCTOT/NOCS))
template<int NCI, int SLAST, int NOCS, int NOCTOT, bool OMOUT>
__global__ __launch_bounds__(256)
void mconv_k(const __nv_bfloat16* __restrict__ xh, const __nv_bfloat16* __restrict__ xl,
             const __nv_bfloat16* __restrict__ wh, const __nv_bfloat16* __restrict__ wl,
             const float* __restrict__ bias,
             __nv_bfloat16* __restrict__ yh, __nv_bfloat16* __restrict__ yl,
             float* __restrict__ om)
{
    constexpr int NB = NOCS / 8;
    constexpr int NSL = NOCTOT / NOCS;
    constexpr int XSTR = NCI * 64;
    constexpr unsigned PATCH_HALF = 6 * 34 * 128;     // 26112
    constexpr unsigned B_OFF = 2 * PATCH_HALF;        // 52224
    constexpr unsigned BBUF = (unsigned)NOCS * 256u;  // hi+lo per buffer

    extern __shared__ __align__(128) char smraw[];
    const unsigned sb = smem_u32(smraw);

    const int tid  = threadIdx.x;
    const int w    = tid >> 5;
    const int lane = tid & 31;
    const int b    = blockIdx.z / NSL;
    const int oc0  = (blockIdx.z % NSL) * NOCS;
    const int x0   = blockIdx.x * 32;
    const int y0   = blockIdx.y * 4;

    const __nv_bfloat16* xhb = xh + (size_t)b * CH_ * XSTR;
    const __nv_bfloat16* xlb = xl + (size_t)b * CH_ * XSTR;

    float acc[NB][4];
#pragma unroll
    for (int nb = 0; nb < NB; nb++)
#pragma unroll
        for (int j = 0; j < 4; j++) acc[nb][j] = 0.f;

    const int gid = lane >> 2, tig = lane & 3;
    const int l16 = lane & 15;
    const int lr  = l16 & 7;
    const int lh  = l16 >> 3;
    const int ahalf = lane >> 4;
    const int r = w >> 1, xbase = (w & 1) * 16;       // r in 0..3
    const int apx0 = (r + 1) * 34 + 1 + xbase + l16;

    auto stage_B = [&](int ch, int tap, int buf) {
        for (int i = tid; i < NOCS * 16; i += 256) {
            int c   = i & 7;
            int row = (i >> 3) % NOCS;
            int hl  = i / (NOCS * 8);
            const __nv_bfloat16* src = (hl ? wl : wh)
                + ((size_t)tap * NOCTOT + oc0 + row) * XSTR + ch * 64 + c * 8;
            unsigned dst = sb + B_OFF + (unsigned)buf * BBUF + (unsigned)hl * (NOCS * 128u)
                         + (unsigned)row * 128u + (unsigned)((c ^ (row & 7)) << 4);
            cpa16(dst, src, true);
        }
    };

    int buf = 0;
    for (int ch = 0; ch < NCI; ch++) {
        if (ch > 0) __syncthreads();  // patch reads of prev chunk done
        // ---- stage patch chunk (6 rows x 34 px x 64 ci, hi+lo) + first B tile ----
        for (int i = tid; i < 3264; i += 256) {
            int c   = i & 7;
            int pxl = (i >> 3) % 204;       // 6*34
            int hl  = i / 1632;
            int y = y0 - 1 + pxl / 34;
            int x = x0 - 1 + pxl % 34;
            bool v = (y >= 0) && (y < HH) && (x >= 0) && (x < WW);
            const __nv_bfloat16* src = (hl ? xlb : xhb)
                + (size_t)((v ? y : 0) * WW + (v ? x : 0)) * XSTR + ch * 64 + c * 8;
            unsigned dst = sb + (unsigned)hl * PATCH_HALF + (unsigned)pxl * 128u
                         + (unsigned)((c ^ (pxl & 7)) << 4);
            cpa16(dst, src, v);
        }
        stage_B(ch, 0, buf);
        cpa_commit();

        const int SN = (ch == NCI - 1) ? SLAST : 4;

        for (int tap = 0; tap < 9; tap++) {
            cpa_wait0();
            __syncthreads();                       // B(tap)+patch ready; prior reads done
            if (tap + 1 < 9) {                     // overlap: stage next B while computing
                stage_B(ch, tap + 1, buf ^ 1);
                cpa_commit();
            }

            const int ky = tap / 3 - 1, kx = tap % 3 - 1;
            const int apx = apx0 + ky * 34 + kx;
            const unsigned aline = sb + (unsigned)apx * 128u;
            const int a7 = apx & 7;
            const unsigned bline = sb + B_OFF + (unsigned)buf * BBUF + (unsigned)lr * 128u;

            for (int s = 0; s < SN; s++) {
                uint32_t ah0, ah1, ah2, ah3, al0, al1, al2, al3;
                unsigned achunk = (unsigned)((s * 2 + ahalf) ^ a7) << 4;
                LDSM4(ah0, ah1, ah2, ah3, aline + achunk);
                LDSM4(al0, al1, al2, al3, aline + PATCH_HALF + achunk);
#pragma unroll
                for (int nb = 0; nb < NB; nb++) {
                    uint32_t bh0, bh1, bl0, bl1;
                    unsigned baddr = bline + (unsigned)nb * 1024u
                                   + (unsigned)(((s * 2 + lh) ^ lr) << 4);
                    LDSM2(bh0, bh1, baddr);
                    LDSM2(bl0, bl1, baddr + NOCS * 128u);
                    MMA16816(acc[nb], ah0, ah1, ah2, ah3, bh0, bh1);
                    MMA16816(acc[nb], al0, al1, al2, al3, bh0, bh1);
                    MMA16816(acc[nb], ah0, ah1, ah2, ah3, bl0, bl1);
                }
            }
            buf ^= 1;
        }
    }

    // ---- epilogue ----
    const int ya = y0 + r;
    const int xa = x0 + xbase + gid;
    const int pixA = ya * WW + xa;
    const int pixB = pixA + 8;
    if (!OMOUT) {
        const size_t pa = (size_t)b * CH_ + pixA;
        const size_t pb = pa + 8;
#pragma unroll
        for (int nb = 0; nb < NB; nb++) {
            int oc = nb * 8 + tig * 2;
            float b0 = bias[oc], b1 = bias[oc + 1];
#pragma unroll
            for (int hp = 0; hp < 2; hp++) {
                float v0 = acc[nb][2 * hp + 0] + b0;
                float v1 = acc[nb][2 * hp + 1] + b1;
                v0 = (v0 >= 0.f) ? v0 : 0.1f * v0;
                v1 = (v1 >= 0.f) ? v1 : 0.1f * v1;
                __nv_bfloat16 h0 = __float2bfloat16(v0), h1 = __float2bfloat16(v1);
                __nv_bfloat16 l0 = __float2bfloat16(v0 - __bfloat162float(h0));
                __nv_bfloat16 l1 = __float2bfloat16(v1 - __bfloat162float(h1));
                size_t base = ((hp ? pb : pa)) * 64 + oc;
                ((uint32_t*)yh)[base >> 1] =
                    (uint32_t)__bfloat16_as_ushort(h0) | ((uint32_t)__bfloat16_as_ushort(h1) << 16);
                ((uint32_t*)yl)[base >> 1] =
                    (uint32_t)__bfloat16_as_ushort(l0) | ((uint32_t)__bfloat16_as_ushort(l1) << 16);
            }
        }
    } else {
        // planar NCHW: om[(b*216+oc)*CH_ + pix]
#pragma unroll
        for (int nb = 0; nb < NB; nb++) {
            int oc = oc0 + nb * 8 + tig * 2;
            float b0 = bias[oc], b1 = bias[oc + 1];
            float* pl0 = om + ((size_t)(b * 216 + oc))     * CH_;
            float* pl1 = om + ((size_t)(b * 216 + oc + 1)) * CH_;
            pl0[pixA] = acc[nb][0] + b0;
            pl1[pixA] = acc[nb][1] + b1;
            pl0[pixB] = acc[nb][2] + b0;
            pl1[pixB] = acc[nb][3] + b1;
        }
    }
}

// ---------------- flow-guided DCN + lrelu (NHWC gather + FFMA2, planar om) ----------------
__global__ __launch_bounds__(128, 4)
void dcn_k(const float* __restrict__ flows,
           const float* __restrict__ wdcn,
           const float* __restrict__ bdcn,
           float* __restrict__ out)
{
    const int b  = blockIdx.z;
    const int px = threadIdx.x & 31;
    const int py = threadIdx.x >> 5;
    const int w  = blockIdx.x * 32 + px;
    const int h  = blockIdx.y * 4 + py;
    const int tid = threadIdx.x;

    __shared__ __align__(16) float sW[8][9][64];

    unsigned long long acc[32];
#pragma unroll
    for (int i = 0; i < 32; i++) acc[i] = 0ull;

    const float flowx = flows[((size_t)(b * 2 + 0) * HH + h) * WW + w];
    const float flowy = flows[((size_t)(b * 2 + 1) * HH + h) * WW + w];

    const float* omb = g_om + (size_t)b * 216 * CH_ + (size_t)h * WW + w;  // planar
    const float* xb  = g_xt + (size_t)b * CH_ * 64;

    for (int g = 0; g < 8; g++) {
        __syncthreads();
        for (int i = tid; i < 8 * 9 * 64; i += 128) {
            int oc = i & 63;
            int k  = (i >> 6) % 9;
            int c  = i / (64 * 9);
            sW[c][k][oc] = wdcn[((size_t)oc * 64 + g * 8 + c) * 9 + k];
        }
        __syncthreads();

#pragma unroll
        for (int k = 0; k < 9; k++) {
            const int ky = k / 3 - 1;
            const int kx = k % 3 - 1;
            float oy = omb[(size_t)(2 * (g * 9 + k))     * CH_] + flowy;
            float ox = omb[(size_t)(2 * (g * 9 + k) + 1) * CH_] + flowx;
            float mv = omb[(size_t)(144 + g * 9 + k)     * CH_];
            mv = 1.f / (1.f + __expf(-mv));

            float pyf = (float)(h + ky) + oy;
            float pxf = (float)(w + kx) + ox;
            float y0f = floorf(pyf), x0f = floorf(pxf);
            float wy = pyf - y0f, wx = pxf - x0f;
            int iy0 = (int)y0f, ix0 = (int)x0f;
            int iy1 = iy0 + 1, ix1 = ix0 + 1;
            bool vy0 = (iy0 >= 0) & (iy0 < HH);
            bool vy1 = (iy1 >= 0) & (iy1 < HH);
            bool vx0 = (ix0 >= 0) & (ix0 < WW);
            bool vx1 = (ix1 >= 0) & (ix1 < WW);
            int cy0 = min(max(iy0, 0), HH - 1), cy1 = min(max(iy1, 0), HH - 1);
            int cx0 = min(max(ix0, 0), WW - 1), cx1 = min(max(ix1, 0), WW - 1);
            float w00 = (1.f - wy) * (1.f - wx) * ((vy0 && vx0) ? 1.f : 0.f) * mv;
            float w01 = (1.f - wy) * wx         * ((vy0 && vx1) ? 1.f : 0.f) * mv;
            float w10 = wy * (1.f - wx)         * ((vy1 && vx0) ? 1.f : 0.f) * mv;
            float w11 = wy * wx                 * ((vy1 && vx1) ? 1.f : 0.f) * mv;
            const float* p00 = xb + (size_t)(cy0 * WW + cx0) * 64 + g * 8;
            const float* p01 = xb + (size_t)(cy0 * WW + cx1) * 64 + g * 8;
            const float* p10 = xb + (size_t)(cy1 * WW + cx0) * 64 + g * 8;
            const float* p11 = xb + (size_t)(cy1 * WW + cx1) * 64 + g * 8;

#pragma unroll
            for (int half = 0; half < 2; half++) {
                float4 a00 = ((const float4*)p00)[half];
                float4 a01 = ((const float4*)p01)[half];
                float4 a10 = ((const float4*)p10)[half];
                float4 a11 = ((const float4*)p11)[half];
                float s[4];
                s[0] = a00.x * w00 + a01.x * w01 + a10.x * w10 + a11.x * w11;
                s[1] = a00.y * w00 + a01.y * w01 + a10.y * w10 + a11.y * w11;
                s[2] = a00.z * w00 + a01.z * w01 + a10.z * w10 + a11.z * w11;
                s[3] = a00.w * w00 + a01.w * w01 + a10.w * w10 + a11.w * w11;
#pragma unroll
                for (int cc = 0; cc < 4; cc++) {
                    int c = half * 4 + cc;
                    unsigned long long s2 = pack2(s[cc]);
                    const ulonglong2* w2p = (const ulonglong2*)&sW[c][k][0];
#pragma unroll
                    for (int q = 0; q < 8; q++) {
                        ulonglong2 wp = w2p[q];
                        ffma2(acc[4 * q + 0], s2, wp.x);
                        ffma2(acc[4 * q + 1], s2, wp.y);
                        wp = w2p[q + 8];
                        ffma2(acc[4 * q + 2], s2, wp.x);
                        ffma2(acc[4 * q + 3], s2, wp.y);
                    }
                }
            }
        }
    }

#pragma unroll
    for (int q = 0; q < 8; q++) {
#pragma unroll
        for (int j = 0; j < 2; j++) {
            float2 fA = unpack2(acc[4 * q + 2 * j]);
            float2 fB = unpack2(acc[4 * q + 2 * j + 1]);
            int base = (j == 0) ? (4 * q) : (32 + 4 * q);
            float r0 = fA.x + bdcn[base + 0];
            float r1 = fA.y + bdcn[base + 1];
            float r2 = fB.x + bdcn[base + 2];
            float r3 = fB.y + bdcn[base + 3];
            r0 = (r0 >= 0.f) ? r0 : 0.1f * r0;
            r1 = (r1 >= 0.f) ? r1 : 0.1f * r1;
            r2 = (r2 >= 0.f) ? r2 : 0.1f * r2;
            r3 = (r3 >= 0.f) ? r3 : 0.1f * r3;
            out[((size_t)(b * 64 + base + 0) * HH + h) * WW + w] = r0;
            out[((size_t)(b * 64 + base + 1) * HH + h) * WW + w] = r1;
            out[((size_t)(b * 64 + base + 2) * HH + h) * WW + w] = r2;
            out[((size_t)(b * 64 + base + 3) * HH + h) * WW + w] = r3;
        }
    }
}

// ---------------- launch ----------------
extern "C" void kernel_launch(void* const* d_in, const int* in_sizes, int n_in,
                              void* d_out, int out_size)
{
    const float* nbr    = (const float*)d_in[0];
    const float* warped = (const float*)d_in[1];
    const float* ref    = (const float*)d_in[2];
    const float* flows  = (const float*)d_in[3];
    const float* w1     = (const float*)d_in[4];
    const float* b1     = (const float*)d_in[5];
    const float* w2     = (const float*)d_in[6];
    const float* b2     = (const float*)d_in[7];
    const float* w_om   = (const float*)d_in[8];
    const float* b_om   = (const float*)d_in[9];
    const float* w_dcn  = (const float*)d_in[10];
    const float* b_dcn  = (const float*)d_in[11];
    float* out = (float*)d_out;

    float *p_om;
    __nv_bfloat16 *p_x1h, *p_x1l, *p_x2h, *p_x2l, *p_x3h, *p_x3l;
    __nv_bfloat16 *p_w1h, *p_w1l, *p_w2h, *p_w2l, *p_womh, *p_woml;
    cudaGetSymbolAddress((void**)&p_om,   g_om);
    cudaGetSymbolAddress((void**)&p_x1h,  g_x1h);
    cudaGetSymbolAddress((void**)&p_x1l,  g_x1l);
    cudaGetSymbolAddress((void**)&p_x2h,  g_x2h);
    cudaGetSymbolAddress((void**)&p_x2l,  g_x2l);
    cudaGetSymbolAddress((void**)&p_x3h,  g_x3h);
    cudaGetSymbolAddress((void**)&p_x3l,  g_x3l);
    cudaGetSymbolAddress((void**)&p_w1h,  g_w1h);
    cudaGetSymbolAddress((void**)&p_w1l,  g_w1l);
    cudaGetSymbolAddress((void**)&p_w2h,  g_w2h);
    cudaGetSymbolAddress((void**)&p_w2l,  g_w2l);
    cudaGetSymbolAddress((void**)&p_womh, g_womh);
    cudaGetSymbolAddress((void**)&p_woml, g_woml);

    const int SMEMC = 52224 + 2 * 64 * 256;   // 84992 (conv1 / conv2)
    const int SMEMO = 52224 + 2 * 72 * 256;   // 89088 (conv_om)
    cudaFuncSetAttribute(mconv_k<3, 1, 64, 64,  false>, cudaFuncAttributeMaxDynamicSharedMemorySize, SMEMC);
    cudaFuncSetAttribute(mconv_k<1, 4, 64, 64,  false>, cudaFuncAttributeMaxDynamicSharedMemorySize, SMEMC);
    cudaFuncSetAttribute(mconv_k<1, 4, 72, 216, true >, cudaFuncAttributeMaxDynamicSharedMemorySize, SMEMO);

    // 0. input/weight prep
    {
        dim3 gc(CH_ / 32, 6, BB);
        cat_k<<<gc, dim3(32, 8)>>>(warped, ref, flows);
        int t1 = 9 * 64 * 192;
        wsplit_k<<<(t1 + 255) / 256, 256>>>(w1, 64, 130, 192, p_w1h, p_w1l, t1);
        int t2 = 9 * 64 * 64;
        wsplit_k<<<(t2 + 255) / 256, 256>>>(w2, 64, 64, 64, p_w2h, p_w2l, t2);
        int t3 = 9 * 216 * 64;
        wsplit_k<<<(t3 + 255) / 256, 256>>>(w_om, 216, 64, 64, p_womh, p_woml, t3);
        dim3 gn(CH_ / 32, 2, BB);
        nhwc_k<<<gn, dim3(32, 8)>>>(nbr);
    }
    // 1. conv1 (HMMA): 130(192) -> 64, lrelu
    {
        dim3 grid(WW / 32, HH / 4, BB);
        mconv_k<3, 1, 64, 64, false><<<grid, 256, SMEMC>>>(p_x1h, p_x1l, p_w1h, p_w1l, b1,
                                                           p_x2h, p_x2l, nullptr);
    }
    // 2. conv2 (HMMA): 64 -> 64, lrelu
    {
        dim3 grid(WW / 32, HH / 4, BB);
        mconv_k<1, 4, 64, 64, false><<<grid, 256, SMEMC>>>(p_x2h, p_x2l, p_w2h, p_w2l, b2,
                                                           p_x3h, p_x3l, nullptr);
    }
    // 3. conv_om (HMMA): 64 -> 216 (3 slices of 72), linear, planar fp32
    {
        dim3 grid(WW / 32, HH / 4, BB * 3);
        mconv_k<1, 4, 72, 216, true><<<grid, 256, SMEMO>>>(p_x3h, p_x3l, p_womh, p_woml, b_om,
                                                           nullptr, nullptr, p_om);
    }
    // 4. DCN + lrelu
    {
        dim3 grid(WW / 32, HH / 4, BB);
        dcn_k<<<grid, 128>>>(flows, w_dcn, b_dcn, out);
    }
}

// round 13
// speedup vs baseline: 2.8487x; 1.0484x over previous
#include <cuda_runtime.h>
#include <cuda_bf16.h>
#include <cstdint>

#define HH 192
#define WW 320
#define BB 2
#define CH_ (HH * WW)

// -------- scratch (device globals; no allocations allowed) --------
__device__ float g_xt  [BB * 8 * (size_t)CH_ * 8];      // nbr, group-planar [b][g][hw][8]
__device__ __nv_bfloat16 g_x1h[BB * (size_t)CH_ * 192]; // concat in hi (NHWC, pad 192)
__device__ __nv_bfloat16 g_x1l[BB * (size_t)CH_ * 192];
__device__ __nv_bfloat16 g_x2h[BB * (size_t)CH_ * 64];  // conv1 out hi (NHWC)
__device__ __nv_bfloat16 g_x2l[BB * (size_t)CH_ * 64];
__device__ __nv_bfloat16 g_x3h[BB * (size_t)CH_ * 64];  // conv2 out hi
__device__ __nv_bfloat16 g_x3l[BB * (size_t)CH_ * 64];
__device__ float g_om  [BB * 216 * (size_t)CH_];        // conv_om out (PLANAR NCHW)
__device__ __nv_bfloat16 g_w1h[9 * 64 * 192];           // w1 hi [k][oc][192]
__device__ __nv_bfloat16 g_w1l[9 * 64 * 192];
__device__ __nv_bfloat16 g_w2h[9 * 64 * 64];            // w2 hi [k][oc][64]
__device__ __nv_bfloat16 g_w2l[9 * 64 * 64];
__device__ __nv_bfloat16 g_womh[9 * 216 * 64];          // w_om hi [k][oc][64]
__device__ __nv_bfloat16 g_woml[9 * 216 * 64];

// -------- packed f32x2 helpers --------
__device__ __forceinline__ void ffma2(unsigned long long& d,
                                      unsigned long long a,
                                      unsigned long long b) {
    asm("fma.rn.f32x2 %0, %1, %2, %0;" : "+l"(d) : "l"(a), "l"(b));
}
__device__ __forceinline__ unsigned long long pack2(float s) {
    unsigned long long r;
    asm("mov.b64 %0, {%1, %1};" : "=l"(r) : "f"(s));
    return r;
}
__device__ __forceinline__ float2 unpack2(unsigned long long v) {
    float2 f;
    asm("mov.b64 {%0, %1}, %2;" : "=f"(f.x), "=f"(f.y) : "l"(v));
    return f;
}

// -------- cp.async helpers --------
__device__ __forceinline__ void cpa16(unsigned dst, const void* src, bool valid) {
    asm volatile("cp.async.cg.shared.global [%0], [%1], 16, %2;"
                 :: "r"(dst), "l"(src), "r"(valid ? 16u : 0u));
}
__device__ __forceinline__ void cpa_commit() { asm volatile("cp.async.commit_group;"); }
__device__ __forceinline__ void cpa_wait0()  { asm volatile("cp.async.wait_group 0;"); }

__device__ __forceinline__ uint32_t smem_u32(const void* p) {
    uint32_t a;
    asm("{ .reg .u64 t; cvta.to.shared.u64 t, %1; cvt.u32.u64 %0, t; }" : "=r"(a) : "l"(p));
    return a;
}

// -------- mma.sync helpers --------
#define LDSM4(r0, r1, r2, r3, a) \
    asm volatile("ldmatrix.sync.aligned.m8n8.x4.shared.b16 {%0,%1,%2,%3}, [%4];" \
                 : "=r"(r0), "=r"(r1), "=r"(r2), "=r"(r3) : "r"(a))
#define LDSM2(r0, r1, a) \
    asm volatile("ldmatrix.sync.aligned.m8n8.x2.shared.b16 {%0,%1}, [%2];" \
                 : "=r"(r0), "=r"(r1) : "r"(a))
#define MMA16816(d, a0, a1, a2, a3, b0, b1) \
    asm volatile("mma.sync.aligned.m16n8k16.row.col.f32.bf16.bf16.f32 " \
                 "{%0,%1,%2,%3}, {%4,%5,%6,%7}, {%8,%9}, {%0,%1,%2,%3};" \
                 : "+f"((d)[0]), "+f"((d)[1]), "+f"((d)[2]), "+f"((d)[3]) \
                 : "r"(a0), "r"(a1), "r"(a2), "r"(a3), "r"(b0), "r"(b1))

// ---------------- concat -> NHWC bf16 hi/lo, 192-ch padded ----------------
__global__ void cat_k(const float* __restrict__ warped, const float* __restrict__ ref,
                      const float* __restrict__ flows)
{
    __shared__ float t[32][33];
    const int hw0 = blockIdx.x * 32;
    const int c0  = blockIdx.y * 32;
    const int b   = blockIdx.z;
    const int tx  = threadIdx.x, ty = threadIdx.y;
#pragma unroll
    for (int i = ty; i < 32; i += 8) {
        int cg = c0 + i;
        float v = 0.f;
        if (cg < 64)        v = warped[((size_t)(b * 64 + cg)) * CH_ + hw0 + tx];
        else if (cg < 128)  v = ref   [((size_t)(b * 64 + cg - 64)) * CH_ + hw0 + tx];
        else if (cg < 130)  v = flows [((size_t)(b * 2  + cg - 128)) * CH_ + hw0 + tx];
        t[i][tx] = v;
    }
    __syncthreads();
#pragma unroll
    for (int i = ty; i < 32; i += 8) {
        float v = t[tx][i];
        __nv_bfloat16 hi = __float2bfloat16(v);
        __nv_bfloat16 lo = __float2bfloat16(v - __bfloat162float(hi));
        size_t o = ((size_t)b * CH_ + hw0 + i) * 192 + c0 + tx;
        g_x1h[o] = hi;
        g_x1l[o] = lo;
    }
}

// ---------------- weight hi/lo split: [oc][ci][k] -> [k][oc][CINP] bf16 ----------------
__global__ void wsplit_k(const float* __restrict__ w, int NOC, int CINR, int CINP,
                         __nv_bfloat16* __restrict__ wh, __nv_bfloat16* __restrict__ wl,
                         int total)
{
    int i = blockIdx.x * blockDim.x + threadIdx.x;
    if (i >= total) return;
    int ci = i % CINP;
    int oc = (i / CINP) % NOC;
    int k  = i / (CINP * NOC);
    float v = (ci < CINR) ? w[((size_t)oc * CINR + ci) * 9 + k] : 0.f;
    __nv_bfloat16 hi = __float2bfloat16(v);
    wh[i] = hi;
    wl[i] = __float2bfloat16(v - __bfloat162float(hi));
}

// ---------------- NCHW -> group-planar [b][g][hw][8] repack (for dcn) ----------------
__global__ void nhwc_k(const float* __restrict__ x)
{
    __shared__ float t[32][33];
    const int hw0 = blockIdx.x * 32;
    const int c0  = blockIdx.y * 32;
    const int b   = blockIdx.z;
    const int tx  = threadIdx.x, ty = threadIdx.y;
#pragma unroll
    for (int i = ty; i < 32; i += 8)
        t[i][tx] = x[((size_t)(b * 64 + c0 + i)) * CH_ + hw0 + tx];
    __syncthreads();
#pragma unroll
    for (int i = ty; i < 32; i += 8) {
        int c = c0 + tx;
        int g = c >> 3, cc = c & 7;
        g_xt[((size_t)(b * 8 + g) * CH_ + hw0 + i) * 8 + cc] = t[tx][i];
    }
}

// ---------------- mma.sync 3x3 conv, 4-row tile, B double-buffered ----------------
// block = 256 thr (8 warps), out tile 4 rows x 32 px (M=128). Patch 6x34 px.
// grid: (WW/32, HH/4, BB * (NOCTOT/NOCS))
template<int NCI, int SLAST, int NOCS, int NOCTOT, bool OMOUT>
__global__ __launch_bounds__(256)
void mconv_k(const __nv_bfloat16* __restrict__ xh, const __nv_bfloat16* __restrict__ xl,
             const __nv_bfloat16* __restrict__ wh, const __nv_bfloat16* __restrict__ wl,
             const float* __restrict__ bias,
             __nv_bfloat16* __restrict__ yh, __nv_bfloat16* __restrict__ yl,
             float* __restrict__ om)
{
    constexpr int NB = NOCS / 8;
    constexpr int NSL = NOCTOT / NOCS;
    constexpr int XSTR = NCI * 64;
    constexpr unsigned PATCH_HALF = 6 * 34 * 128;     // 26112
    constexpr unsigned B_OFF = 2 * PATCH_HALF;        // 52224
    constexpr unsigned BBUF = (unsigned)NOCS * 256u;  // hi+lo per buffer

    extern __shared__ __align__(128) char smraw[];
    const unsigned sb = smem_u32(smraw);

    const int tid  = threadIdx.x;
    const int w    = tid >> 5;
    const int lane = tid & 31;
    const int b    = blockIdx.z / NSL;
    const int oc0  = (blockIdx.z % NSL) * NOCS;
    const int x0   = blockIdx.x * 32;
    const int y0   = blockIdx.y * 4;

    const __nv_bfloat16* xhb = xh + (size_t)b * CH_ * XSTR;
    const __nv_bfloat16* xlb = xl + (size_t)b * CH_ * XSTR;

    float acc[NB][4];
#pragma unroll
    for (int nb = 0; nb < NB; nb++)
#pragma unroll
        for (int j = 0; j < 4; j++) acc[nb][j] = 0.f;

    const int gid = lane >> 2, tig = lane & 3;
    const int l16 = lane & 15;
    const int lr  = l16 & 7;
    const int lh  = l16 >> 3;
    const int ahalf = lane >> 4;
    const int r = w >> 1, xbase = (w & 1) * 16;       // r in 0..3
    const int apx0 = (r + 1) * 34 + 1 + xbase + l16;

    auto stage_B = [&](int ch, int tap, int buf) {
        for (int i = tid; i < NOCS * 16; i += 256) {
            int c   = i & 7;
            int row = (i >> 3) % NOCS;
            int hl  = i / (NOCS * 8);
            const __nv_bfloat16* src = (hl ? wl : wh)
                + ((size_t)tap * NOCTOT + oc0 + row) * XSTR + ch * 64 + c * 8;
            unsigned dst = sb + B_OFF + (unsigned)buf * BBUF + (unsigned)hl * (NOCS * 128u)
                         + (unsigned)row * 128u + (unsigned)((c ^ (row & 7)) << 4);
            cpa16(dst, src, true);
        }
    };

    int buf = 0;
    for (int ch = 0; ch < NCI; ch++) {
        if (ch > 0) __syncthreads();  // patch reads of prev chunk done
        // ---- stage patch chunk (6 rows x 34 px x 64 ci, hi+lo) + first B tile ----
        for (int i = tid; i < 3264; i += 256) {
            int c   = i & 7;
            int pxl = (i >> 3) % 204;       // 6*34
            int hl  = i / 1632;
            int y = y0 - 1 + pxl / 34;
            int x = x0 - 1 + pxl % 34;
            bool v = (y >= 0) && (y < HH) && (x >= 0) && (x < WW);
            const __nv_bfloat16* src = (hl ? xlb : xhb)
                + (size_t)((v ? y : 0) * WW + (v ? x : 0)) * XSTR + ch * 64 + c * 8;
            unsigned dst = sb + (unsigned)hl * PATCH_HALF + (unsigned)pxl * 128u
                         + (unsigned)((c ^ (pxl & 7)) << 4);
            cpa16(dst, src, v);
        }
        stage_B(ch, 0, buf);
        cpa_commit();

        const int SN = (ch == NCI - 1) ? SLAST : 4;

        for (int tap = 0; tap < 9; tap++) {
            cpa_wait0();
            __syncthreads();                       // B(tap)+patch ready; prior reads done
            if (tap + 1 < 9) {                     // overlap: stage next B while computing
                stage_B(ch, tap + 1, buf ^ 1);
                cpa_commit();
            }

            const int ky = tap / 3 - 1, kx = tap % 3 - 1;
            const int apx = apx0 + ky * 34 + kx;
            const unsigned aline = sb + (unsigned)apx * 128u;
            const int a7 = apx & 7;
            const unsigned bline = sb + B_OFF + (unsigned)buf * BBUF + (unsigned)lr * 128u;

            for (int s = 0; s < SN; s++) {
                uint32_t ah0, ah1, ah2, ah3, al0, al1, al2, al3;
                unsigned achunk = (unsigned)((s * 2 + ahalf) ^ a7) << 4;
                LDSM4(ah0, ah1, ah2, ah3, aline + achunk);
                LDSM4(al0, al1, al2, al3, aline + PATCH_HALF + achunk);
#pragma unroll
                for (int nb = 0; nb < NB; nb++) {
                    uint32_t bh0, bh1, bl0, bl1;
                    unsigned baddr = bline + (unsigned)nb * 1024u
                                   + (unsigned)(((s * 2 + lh) ^ lr) << 4);
                    LDSM2(bh0, bh1, baddr);
                    LDSM2(bl0, bl1, baddr + NOCS * 128u);
                    MMA16816(acc[nb], ah0, ah1, ah2, ah3, bh0, bh1);
                    MMA16816(acc[nb], al0, al1, al2, al3, bh0, bh1);
                    MMA16816(acc[nb], ah0, ah1, ah2, ah3, bl0, bl1);
                }
            }
            buf ^= 1;
        }
    }

    // ---- epilogue ----
    const int ya = y0 + r;
    const int xa = x0 + xbase + gid;
    const int pixA = ya * WW + xa;
    const int pixB = pixA + 8;
    if (!OMOUT) {
        const size_t pa = (size_t)b * CH_ + pixA;
        const size_t pb = pa + 8;
#pragma unroll
        for (int nb = 0; nb < NB; nb++) {
            int oc = nb * 8 + tig * 2;
            float b0 = bias[oc], b1 = bias[oc + 1];
#pragma unroll
            for (int hp = 0; hp < 2; hp++) {
                float v0 = acc[nb][2 * hp + 0] + b0;
                float v1 = acc[nb][2 * hp + 1] + b1;
                v0 = (v0 >= 0.f) ? v0 : 0.1f * v0;
                v1 = (v1 >= 0.f) ? v1 : 0.1f * v1;
                __nv_bfloat16 h0 = __float2bfloat16(v0), h1 = __float2bfloat16(v1);
                __nv_bfloat16 l0 = __float2bfloat16(v0 - __bfloat162float(h0));
                __nv_bfloat16 l1 = __float2bfloat16(v1 - __bfloat162float(h1));
                size_t base = ((hp ? pb : pa)) * 64 + oc;
                ((uint32_t*)yh)[base >> 1] =
                    (uint32_t)__bfloat16_as_ushort(h0) | ((uint32_t)__bfloat16_as_ushort(h1) << 16);
                ((uint32_t*)yl)[base >> 1] =
                    (uint32_t)__bfloat16_as_ushort(l0) | ((uint32_t)__bfloat16_as_ushort(l1) << 16);
            }
        }
    } else {
        // planar NCHW: om[(b*216+oc)*CH_ + pix]
#pragma unroll
        for (int nb = 0; nb < NB; nb++) {
            int oc = oc0 + nb * 8 + tig * 2;
            float b0 = bias[oc], b1 = bias[oc + 1];
            float* pl0 = om + ((size_t)(b * 216 + oc))     * CH_;
            float* pl1 = om + ((size_t)(b * 216 + oc + 1)) * CH_;
            pl0[pixA] = acc[nb][0] + b0;
            pl1[pixA] = acc[nb][1] + b1;
            pl0[pixB] = acc[nb][2] + b0;
            pl1[pixB] = acc[nb][3] + b1;
        }
    }
}

// ---------------- flow-guided DCN + lrelu (group-planar gather + FFMA2) ----------------
__global__ __launch_bounds__(128, 4)
void dcn_k(const float* __restrict__ flows,
           const float* __restrict__ wdcn,
           const float* __restrict__ bdcn,
           float* __restrict__ out)
{
    const int b  = blockIdx.z;
    const int px = threadIdx.x & 31;
    const int py = threadIdx.x >> 5;
    const int w  = blockIdx.x * 32 + px;
    const int h  = blockIdx.y * 4 + py;
    const int tid = threadIdx.x;

    __shared__ __align__(16) float sW[8][9][64];

    unsigned long long acc[32];
#pragma unroll
    for (int i = 0; i < 32; i++) acc[i] = 0ull;

    const float flowx = flows[((size_t)(b * 2 + 0) * HH + h) * WW + w];
    const float flowy = flows[((size_t)(b * 2 + 1) * HH + h) * WW + w];

    const float* omb = g_om + (size_t)b * 216 * CH_ + (size_t)h * WW + w;  // planar

    for (int g = 0; g < 8; g++) {
        __syncthreads();
        for (int i = tid; i < 8 * 9 * 64; i += 128) {
            int oc = i & 63;
            int k  = (i >> 6) % 9;
            int c  = i / (64 * 9);
            sW[c][k][oc] = wdcn[((size_t)oc * 64 + g * 8 + c) * 9 + k];
        }
        __syncthreads();

        const float* xg = g_xt + (size_t)(b * 8 + g) * CH_ * 8;   // group plane, 32B/px

#pragma unroll
        for (int k = 0; k < 9; k++) {
            const int ky = k / 3 - 1;
            const int kx = k % 3 - 1;
            float oy = omb[(size_t)(2 * (g * 9 + k))     * CH_] + flowy;
            float ox = omb[(size_t)(2 * (g * 9 + k) + 1) * CH_] + flowx;
            float mv = omb[(size_t)(144 + g * 9 + k)     * CH_];
            mv = 1.f / (1.f + __expf(-mv));

            float pyf = (float)(h + ky) + oy;
            float pxf = (float)(w + kx) + ox;
            float y0f = floorf(pyf), x0f = floorf(pxf);
            float wy = pyf - y0f, wx = pxf - x0f;
            int iy0 = (int)y0f, ix0 = (int)x0f;
            int iy1 = iy0 + 1, ix1 = ix0 + 1;
            bool vy0 = (iy0 >= 0) & (iy0 < HH);
            bool vy1 = (iy1 >= 0) & (iy1 < HH);
            bool vx0 = (ix0 >= 0) & (ix0 < WW);
            bool vx1 = (ix1 >= 0) & (ix1 < WW);
            int cy0 = min(max(iy0, 0), HH - 1), cy1 = min(max(iy1, 0), HH - 1);
            int cx0 = min(max(ix0, 0), WW - 1), cx1 = min(max(ix1, 0), WW - 1);
            float w00 = (1.f - wy) * (1.f - wx) * ((vy0 && vx0) ? 1.f : 0.f) * mv;
            float w01 = (1.f - wy) * wx         * ((vy0 && vx1) ? 1.f : 0.f) * mv;
            float w10 = wy * (1.f - wx)         * ((vy1 && vx0) ? 1.f : 0.f) * mv;
            float w11 = wy * wx                 * ((vy1 && vx1) ? 1.f : 0.f) * mv;
            const float* p00 = xg + (size_t)(cy0 * WW + cx0) * 8;
            const float* p01 = xg + (size_t)(cy0 * WW + cx1) * 8;
            const float* p10 = xg + (size_t)(cy1 * WW + cx0) * 8;
            const float* p11 = xg + (size_t)(cy1 * WW + cx1) * 8;

#pragma unroll
            for (int half = 0; half < 2; half++) {
                float4 a00 = ((const float4*)p00)[half];
                float4 a01 = ((const float4*)p01)[half];
                float4 a10 = ((const float4*)p10)[half];
                float4 a11 = ((const float4*)p11)[half];
                float s[4];
                s[0] = a00.x * w00 + a01.x * w01 + a10.x * w10 + a11.x * w11;
                s[1] = a00.y * w00 + a01.y * w01 + a10.y * w10 + a11.y * w11;
                s[2] = a00.z * w00 + a01.z * w01 + a10.z * w10 + a11.z * w11;
                s[3] = a00.w * w00 + a01.w * w01 + a10.w * w10 + a11.w * w11;
#pragma unroll
                for (int cc = 0; cc < 4; cc++) {
                    int c = half * 4 + cc;
                    unsigned long long s2 = pack2(s[cc]);
                    const ulonglong2* w2p = (const ulonglong2*)&sW[c][k][0];
#pragma unroll
                    for (int q = 0; q < 8; q++) {
                        ulonglong2 wp = w2p[q];
                        ffma2(acc[4 * q + 0], s2, wp.x);
                        ffma2(acc[4 * q + 1], s2, wp.y);
                        wp = w2p[q + 8];
                        ffma2(acc[4 * q + 2], s2, wp.x);
                        ffma2(acc[4 * q + 3], s2, wp.y);
                    }
                }
            }
        }
    }

#pragma unroll
    for (int q = 0; q < 8; q++) {
#pragma unroll
        for (int j = 0; j < 2; j++) {
            float2 fA = unpack2(acc[4 * q + 2 * j]);
            float2 fB = unpack2(acc[4 * q + 2 * j + 1]);
            int base = (j == 0) ? (4 * q) : (32 + 4 * q);
            float r0 = fA.x + bdcn[base + 0];
            float r1 = fA.y + bdcn[base + 1];
            float r2 = fB.x + bdcn[base + 2];
            float r3 = fB.y + bdcn[base + 3];
            r0 = (r0 >= 0.f) ? r0 : 0.1f * r0;
            r1 = (r1 >= 0.f) ? r1 : 0.1f * r1;
            r2 = (r2 >= 0.f) ? r2 : 0.1f * r2;
            r3 = (r3 >= 0.f) ? r3 : 0.1f * r3;
            out[((size_t)(b * 64 + base + 0) * HH + h) * WW + w] = r0;
            out[((size_t)(b * 64 + base + 1) * HH + h) * WW + w] = r1;
            out[((size_t)(b * 64 + base + 2) * HH + h) * WW + w] = r2;
            out[((size_t)(b * 64 + base + 3) * HH + h) * WW + w] = r3;
        }
    }
}

// ---------------- launch ----------------
extern "C" void kernel_launch(void* const* d_in, const int* in_sizes, int n_in,
                              void* d_out, int out_size)
{
    const float* nbr    = (const float*)d_in[0];
    const float* warped = (const float*)d_in[1];
    const float* ref    = (const float*)d_in[2];
    const float* flows  = (const float*)d_in[3];
    const float* w1     = (const float*)d_in[4];
    const float* b1     = (const float*)d_in[5];
    const float* w2     = (const float*)d_in[6];
    const float* b2     = (const float*)d_in[7];
    const float* w_om   = (const float*)d_in[8];
    const float* b_om   = (const float*)d_in[9];
    const float* w_dcn  = (const float*)d_in[10];
    const float* b_dcn  = (const float*)d_in[11];
    float* out = (float*)d_out;

    float *p_om;
    __nv_bfloat16 *p_x1h, *p_x1l, *p_x2h, *p_x2l, *p_x3h, *p_x3l;
    __nv_bfloat16 *p_w1h, *p_w1l, *p_w2h, *p_w2l, *p_womh, *p_woml;
    cudaGetSymbolAddress((void**)&p_om,   g_om);
    cudaGetSymbolAddress((void**)&p_x1h,  g_x1h);
    cudaGetSymbolAddress((void**)&p_x1l,  g_x1l);
    cudaGetSymbolAddress((void**)&p_x2h,  g_x2h);
    cudaGetSymbolAddress((void**)&p_x2l,  g_x2l);
    cudaGetSymbolAddress((void**)&p_x3h,  g_x3h);
    cudaGetSymbolAddress((void**)&p_x3l,  g_x3l);
    cudaGetSymbolAddress((void**)&p_w1h,  g_w1h);
    cudaGetSymbolAddress((void**)&p_w1l,  g_w1l);
    cudaGetSymbolAddress((void**)&p_w2h,  g_w2h);
    cudaGetSymbolAddress((void**)&p_w2l,  g_w2l);
    cudaGetSymbolAddress((void**)&p_womh, g_womh);
    cudaGetSymbolAddress((void**)&p_woml, g_woml);

    const int SMEMC = 52224 + 2 * 64 * 256;   // 84992 (conv1 / conv2)
    const int SMEMO = 52224 + 2 * 72 * 256;   // 89088 (conv_om)
    cudaFuncSetAttribute(mconv_k<3, 1, 64, 64,  false>, cudaFuncAttributeMaxDynamicSharedMemorySize, SMEMC);
    cudaFuncSetAttribute(mconv_k<1, 4, 64, 64,  false>, cudaFuncAttributeMaxDynamicSharedMemorySize, SMEMC);
    cudaFuncSetAttribute(mconv_k<1, 4, 72, 216, true >, cudaFuncAttributeMaxDynamicSharedMemorySize, SMEMO);

    // 0. input/weight prep
    {
        dim3 gc(CH_ / 32, 6, BB);
        cat_k<<<gc, dim3(32, 8)>>>(warped, ref, flows);
        int t1 = 9 * 64 * 192;
        wsplit_k<<<(t1 + 255) / 256, 256>>>(w1, 64, 130, 192, p_w1h, p_w1l, t1);
        int t2 = 9 * 64 * 64;
        wsplit_k<<<(t2 + 255) / 256, 256>>>(w2, 64, 64, 64, p_w2h, p_w2l, t2);
        int t3 = 9 * 216 * 64;
        wsplit_k<<<(t3 + 255) / 256, 256>>>(w_om, 216, 64, 64, p_womh, p_woml, t3);
        dim3 gn(CH_ / 32, 2, BB);
        nhwc_k<<<gn, dim3(32, 8)>>>(nbr);
    }
    // 1. conv1 (HMMA): 130(192) -> 64, lrelu
    {
        dim3 grid(WW / 32, HH / 4, BB);
        mconv_k<3, 1, 64, 64, false><<<grid, 256, SMEMC>>>(p_x1h, p_x1l, p_w1h, p_w1l, b1,
                                                           p_x2h, p_x2l, nullptr);
    }
    // 2. conv2 (HMMA): 64 -> 64, lrelu
    {
        dim3 grid(WW / 32, HH / 4, BB);
        mconv_k<1, 4, 64, 64, false><<<grid, 256, SMEMC>>>(p_x2h, p_x2l, p_w2h, p_w2l, b2,
                                                           p_x3h, p_x3l, nullptr);
    }
    // 3. conv_om (HMMA): 64 -> 216 (3 slices of 72), linear, planar fp32
    {
        dim3 grid(WW / 32, HH / 4, BB * 3);
        mconv_k<1, 4, 72, 216, true><<<grid, 256, SMEMO>>>(p_x3h, p_x3l, p_womh, p_woml, b_om,
                                                           nullptr, nullptr, p_om);
    }
    // 4. DCN + lrelu
    {
        dim3 grid(WW / 32, HH / 4, BB);
        dcn_k<<<grid, 128>>>(flows, w_dcn, b_dcn, out);
    }
}

// round 14
// speedup vs baseline: 3.2798x; 1.1513x over previous
#include <cuda_runtime.h>
#include <cuda_fp16.h>
#include <cstdint>

#define HH 192
#define WW 320
#define BB 2
#define CH_ (HH * WW)

// -------- scratch (device globals; no allocations allowed) --------
__device__ float g_xt  [BB * 8 * (size_t)CH_ * 8];      // nbr, group-planar [b][g][hw][8]
__device__ __half g_x1h[BB * (size_t)CH_ * 192];        // concat in hi (NHWC, pad 192)
__device__ __half g_x1l[BB * (size_t)CH_ * 192];
__device__ __half g_x2h[BB * (size_t)CH_ * 64];         // conv1 out hi (NHWC)
__device__ __half g_x2l[BB * (size_t)CH_ * 64];
__device__ __half g_x3h[BB * (size_t)CH_ * 64];         // conv2 out hi
__device__ __half g_x3l[BB * (size_t)CH_ * 64];
__device__ float g_om  [BB * 216 * (size_t)CH_];        // conv_om out (PLANAR NCHW)
__device__ __half g_w1 [9 * 64 * 192];                  // w1 fp16 [k][oc][192]
__device__ __half g_w2 [9 * 64 * 64];                   // w2 fp16 [k][oc][64]
__device__ __half g_wom[9 * 216 * 64];                  // w_om fp16 [k][oc][64]

// -------- packed f32x2 helpers --------
__device__ __forceinline__ void ffma2(unsigned long long& d,
                                      unsigned long long a,
                                      unsigned long long b) {
    asm("fma.rn.f32x2 %0, %1, %2, %0;" : "+l"(d) : "l"(a), "l"(b));
}
__device__ __forceinline__ unsigned long long pack2(float s) {
    unsigned long long r;
    asm("mov.b64 %0, {%1, %1};" : "=l"(r) : "f"(s));
    return r;
}
__device__ __forceinline__ float2 unpack2(unsigned long long v) {
    float2 f;
    asm("mov.b64 {%0, %1}, %2;" : "=f"(f.x), "=f"(f.y) : "l"(v));
    return f;
}

// -------- cp.async helpers --------
__device__ __forceinline__ void cpa16(unsigned dst, const void* src, bool valid) {
    asm volatile("cp.async.cg.shared.global [%0], [%1], 16, %2;"
                 :: "r"(dst), "l"(src), "r"(valid ? 16u : 0u));
}
__device__ __forceinline__ void cpa_commit() { asm volatile("cp.async.commit_group;"); }
__device__ __forceinline__ void cpa_wait0()  { asm volatile("cp.async.wait_group 0;"); }

__device__ __forceinline__ uint32_t smem_u32(const void* p) {
    uint32_t a;
    asm("{ .reg .u64 t; cvta.to.shared.u64 t, %1; cvt.u32.u64 %0, t; }" : "=r"(a) : "l"(p));
    return a;
}

// -------- mma.sync helpers (fp16 in, fp32 accum) --------
#define LDSM4(r0, r1, r2, r3, a) \
    asm volatile("ldmatrix.sync.aligned.m8n8.x4.shared.b16 {%0,%1,%2,%3}, [%4];" \
                 : "=r"(r0), "=r"(r1), "=r"(r2), "=r"(r3) : "r"(a))
#define LDSM2(r0, r1, a) \
    asm volatile("ldmatrix.sync.aligned.m8n8.x2.shared.b16 {%0,%1}, [%2];" \
                 : "=r"(r0), "=r"(r1) : "r"(a))
#define MMA16816(d, a0, a1, a2, a3, b0, b1) \
    asm volatile("mma.sync.aligned.m16n8k16.row.col.f32.f16.f16.f32 " \
                 "{%0,%1,%2,%3}, {%4,%5,%6,%7}, {%8,%9}, {%0,%1,%2,%3};" \
                 : "+f"((d)[0]), "+f"((d)[1]), "+f"((d)[2]), "+f"((d)[3]) \
                 : "r"(a0), "r"(a1), "r"(a2), "r"(a3), "r"(b0), "r"(b1))

// ---------------- concat -> NHWC fp16 hi/lo, 192-ch padded ----------------
__global__ void cat_k(const float* __restrict__ warped, const float* __restrict__ ref,
                      const float* __restrict__ flows)
{
    __shared__ float t[32][33];
    const int hw0 = blockIdx.x * 32;
    const int c0  = blockIdx.y * 32;
    const int b   = blockIdx.z;
    const int tx  = threadIdx.x, ty = threadIdx.y;
#pragma unroll
    for (int i = ty; i < 32; i += 8) {
        int cg = c0 + i;
        float v = 0.f;
        if (cg < 64)        v = warped[((size_t)(b * 64 + cg)) * CH_ + hw0 + tx];
        else if (cg < 128)  v = ref   [((size_t)(b * 64 + cg - 64)) * CH_ + hw0 + tx];
        else if (cg < 130)  v = flows [((size_t)(b * 2  + cg - 128)) * CH_ + hw0 + tx];
        t[i][tx] = v;
    }
    __syncthreads();
#pragma unroll
    for (int i = ty; i < 32; i += 8) {
        float v = t[tx][i];
        __half hi = __float2half(v);
        __half lo = __float2half(v - __half2float(hi));
        size_t o = ((size_t)b * CH_ + hw0 + i) * 192 + c0 + tx;
        g_x1h[o] = hi;
        g_x1l[o] = lo;
    }
}

// ---------------- weight fp16 convert: [oc][ci][k] -> [k][oc][CINP] ----------------
__global__ void wcvt_k(const float* __restrict__ w, int NOC, int CINR, int CINP,
                       __half* __restrict__ wh, int total)
{
    int i = blockIdx.x * blockDim.x + threadIdx.x;
    if (i >= total) return;
    int ci = i % CINP;
    int oc = (i / CINP) % NOC;
    int k  = i / (CINP * NOC);
    float v = (ci < CINR) ? w[((size_t)oc * CINR + ci) * 9 + k] : 0.f;
    wh[i] = __float2half(v);
}

// ---------------- NCHW -> group-planar [b][g][hw][8] repack (for dcn) ----------------
__global__ void nhwc_k(const float* __restrict__ x)
{
    __shared__ float t[32][33];
    const int hw0 = blockIdx.x * 32;
    const int c0  = blockIdx.y * 32;
    const int b   = blockIdx.z;
    const int tx  = threadIdx.x, ty = threadIdx.y;
#pragma unroll
    for (int i = ty; i < 32; i += 8)
        t[i][tx] = x[((size_t)(b * 64 + c0 + i)) * CH_ + hw0 + tx];
    __syncthreads();
#pragma unroll
    for (int i = ty; i < 32; i += 8) {
        int c = c0 + tx;
        int g = c >> 3, cc = c & 7;
        g_xt[((size_t)(b * 8 + g) * CH_ + hw0 + i) * 8 + cc] = t[tx][i];
    }
}

// ---------------- mma.sync fp16 3x3 conv, 4-row tile, B double-buffered ----------------
// block = 256 thr (8 warps), out tile 4 rows x 32 px (M=128). Patch 6x34 px.
// Products: xh*w + xl*w (weights single fp16).
// grid: (WW/32, HH/4, BB * (NOCTOT/NOCS))
template<int NCI, int SLAST, int NOCS, int NOCTOT, bool OMOUT>
__global__ __launch_bounds__(256)
void mconv_k(const __half* __restrict__ xh, const __half* __restrict__ xl,
             const __half* __restrict__ wgt,
             const float* __restrict__ bias,
             __half* __restrict__ yh, __half* __restrict__ yl,
             float* __restrict__ om)
{
    constexpr int NB = NOCS / 8;
    constexpr int NSL = NOCTOT / NOCS;
    constexpr int XSTR = NCI * 64;
    constexpr unsigned PATCH_HALF = 6 * 34 * 128;     // 26112
    constexpr unsigned B_OFF = 2 * PATCH_HALF;        // 52224
    constexpr unsigned BBUF = (unsigned)NOCS * 128u;  // single-precision-set buffer

    extern __shared__ __align__(128) char smraw[];
    const unsigned sb = smem_u32(smraw);

    const int tid  = threadIdx.x;
    const int w    = tid >> 5;
    const int lane = tid & 31;
    const int b    = blockIdx.z / NSL;
    const int oc0  = (blockIdx.z % NSL) * NOCS;
    const int x0   = blockIdx.x * 32;
    const int y0   = blockIdx.y * 4;

    const __half* xhb = xh + (size_t)b * CH_ * XSTR;
    const __half* xlb = xl + (size_t)b * CH_ * XSTR;

    float acc[NB][4];
#pragma unroll
    for (int nb = 0; nb < NB; nb++)
#pragma unroll
        for (int j = 0; j < 4; j++) acc[nb][j] = 0.f;

    const int gid = lane >> 2, tig = lane & 3;
    const int l16 = lane & 15;
    const int lr  = l16 & 7;
    const int lh  = l16 >> 3;
    const int ahalf = lane >> 4;
    const int r = w >> 1, xbase = (w & 1) * 16;       // r in 0..3
    const int apx0 = (r + 1) * 34 + 1 + xbase + l16;

    auto stage_B = [&](int ch, int tap, int buf) {
        for (int i = tid; i < NOCS * 8; i += 256) {
            int c   = i & 7;
            int row = i >> 3;
            const __half* src = wgt
                + ((size_t)tap * NOCTOT + oc0 + row) * XSTR + ch * 64 + c * 8;
            unsigned dst = sb + B_OFF + (unsigned)buf * BBUF
                         + (unsigned)row * 128u + (unsigned)((c ^ (row & 7)) << 4);
            cpa16(dst, src, true);
        }
    };

    int buf = 0;
    for (int ch = 0; ch < NCI; ch++) {
        if (ch > 0) __syncthreads();  // patch reads of prev chunk done
        // ---- stage patch chunk (6 rows x 34 px x 64 ci, hi+lo) + first B tile ----
        for (int i = tid; i < 3264; i += 256) {
            int c   = i & 7;
            int pxl = (i >> 3) % 204;       // 6*34
            int hl  = i / 1632;
            int y = y0 - 1 + pxl / 34;
            int x = x0 - 1 + pxl % 34;
            bool v = (y >= 0) && (y < HH) && (x >= 0) && (x < WW);
            const __half* src = (hl ? xlb : xhb)
                + (size_t)((v ? y : 0) * WW + (v ? x : 0)) * XSTR + ch * 64 + c * 8;
            unsigned dst = sb + (unsigned)hl * PATCH_HALF + (unsigned)pxl * 128u
                         + (unsigned)((c ^ (pxl & 7)) << 4);
            cpa16(dst, src, v);
        }
        stage_B(ch, 0, buf);
        cpa_commit();

        const int SN = (ch == NCI - 1) ? SLAST : 4;

        for (int tap = 0; tap < 9; tap++) {
            cpa_wait0();
            __syncthreads();                       // B(tap)+patch ready; prior reads done
            if (tap + 1 < 9) {                     // overlap: stage next B while computing
                stage_B(ch, tap + 1, buf ^ 1);
                cpa_commit();
            }

            const int ky = tap / 3 - 1, kx = tap % 3 - 1;
            const int apx = apx0 + ky * 34 + kx;
            const unsigned aline = sb + (unsigned)apx * 128u;
            const int a7 = apx & 7;
            const unsigned bline = sb + B_OFF + (unsigned)buf * BBUF + (unsigned)lr * 128u;

            for (int s = 0; s < SN; s++) {
                uint32_t ah0, ah1, ah2, ah3, al0, al1, al2, al3;
                unsigned achunk = (unsigned)((s * 2 + ahalf) ^ a7) << 4;
                LDSM4(ah0, ah1, ah2, ah3, aline + achunk);
                LDSM4(al0, al1, al2, al3, aline + PATCH_HALF + achunk);
#pragma unroll
                for (int nb = 0; nb < NB; nb++) {
                    uint32_t bh0, bh1;
                    unsigned baddr = bline + (unsigned)nb * 1024u
                                   + (unsigned)(((s * 2 + lh) ^ lr) << 4);
                    LDSM2(bh0, bh1, baddr);
                    MMA16816(acc[nb], ah0, ah1, ah2, ah3, bh0, bh1);
                    MMA16816(acc[nb], al0, al1, al2, al3, bh0, bh1);
                }
            }
            buf ^= 1;
        }
    }

    // ---- epilogue ----
    const int ya = y0 + r;
    const int xa = x0 + xbase + gid;
    const int pixA = ya * WW + xa;
    const int pixB = pixA + 8;
    if (!OMOUT) {
        const size_t pa = (size_t)b * CH_ + pixA;
        const size_t pb = pa + 8;
#pragma unroll
        for (int nb = 0; nb < NB; nb++) {
            int oc = nb * 8 + tig * 2;
            float b0 = bias[oc], b1 = bias[oc + 1];
#pragma unroll
            for (int hp = 0; hp < 2; hp++) {
                float v0 = acc[nb][2 * hp + 0] + b0;
                float v1 = acc[nb][2 * hp + 1] + b1;
                v0 = (v0 >= 0.f) ? v0 : 0.1f * v0;
                v1 = (v1 >= 0.f) ? v1 : 0.1f * v1;
                __half h0 = __float2half(v0), h1 = __float2half(v1);
                __half l0 = __float2half(v0 - __half2float(h0));
                __half l1 = __float2half(v1 - __half2float(h1));
                size_t base = ((hp ? pb : pa)) * 64 + oc;
                ((uint32_t*)yh)[base >> 1] =
                    (uint32_t)__half_as_ushort(h0) | ((uint32_t)__half_as_ushort(h1) << 16);
                ((uint32_t*)yl)[base >> 1] =
                    (uint32_t)__half_as_ushort(l0) | ((uint32_t)__half_as_ushort(l1) << 16);
            }
        }
    } else {
        // planar NCHW: om[(b*216+oc)*CH_ + pix]
#pragma unroll
        for (int nb = 0; nb < NB; nb++) {
            int oc = oc0 + nb * 8 + tig * 2;
            float b0 = bias[oc], b1 = bias[oc + 1];
            float* pl0 = om + ((size_t)(b * 216 + oc))     * CH_;
            float* pl1 = om + ((size_t)(b * 216 + oc + 1)) * CH_;
            pl0[pixA] = acc[nb][0] + b0;
            pl1[pixA] = acc[nb][1] + b1;
            pl0[pixB] = acc[nb][2] + b0;
            pl1[pixB] = acc[nb][3] + b1;
        }
    }
}

// ---------------- flow-guided DCN + lrelu (group-planar gather + FFMA2) ----------------
__global__ __launch_bounds__(128, 4)
void dcn_k(const float* __restrict__ flows,
           const float* __restrict__ wdcn,
           const float* __restrict__ bdcn,
           float* __restrict__ out)
{
    const int b  = blockIdx.z;
    const int px = threadIdx.x & 31;
    const int py = threadIdx.x >> 5;
    const int w  = blockIdx.x * 32 + px;
    const int h  = blockIdx.y * 4 + py;
    const int tid = threadIdx.x;

    __shared__ __align__(16) float sW[8][9][64];

    unsigned long long acc[32];
#pragma unroll
    for (int i = 0; i < 32; i++) acc[i] = 0ull;

    const float flowx = flows[((size_t)(b * 2 + 0) * HH + h) * WW + w];
    const float flowy = flows[((size_t)(b * 2 + 1) * HH + h) * WW + w];

    const float* omb = g_om + (size_t)b * 216 * CH_ + (size_t)h * WW + w;  // planar

    for (int g = 0; g < 8; g++) {
        __syncthreads();
        for (int i = tid; i < 8 * 9 * 64; i += 128) {
            int oc = i & 63;
            int k  = (i >> 6) % 9;
            int c  = i / (64 * 9);
            sW[c][k][oc] = wdcn[((size_t)oc * 64 + g * 8 + c) * 9 + k];
        }
        __syncthreads();

        const float* xg = g_xt + (size_t)(b * 8 + g) * CH_ * 8;   // group plane, 32B/px

#pragma unroll
        for (int k = 0; k < 9; k++) {
            const int ky = k / 3 - 1;
            const int kx = k % 3 - 1;
            float oy = omb[(size_t)(2 * (g * 9 + k))     * CH_] + flowy;
            float ox = omb[(size_t)(2 * (g * 9 + k) + 1) * CH_] + flowx;
            float mv = omb[(size_t)(144 + g * 9 + k)     * CH_];
            mv = 1.f / (1.f + __expf(-mv));

            float pyf = (float)(h + ky) + oy;
            float pxf = (float)(w + kx) + ox;
            float y0f = floorf(pyf), x0f = floorf(pxf);
            float wy = pyf - y0f, wx = pxf - x0f;
            int iy0 = (int)y0f, ix0 = (int)x0f;
            int iy1 = iy0 + 1, ix1 = ix0 + 1;
            bool vy0 = (iy0 >= 0) & (iy0 < HH);
            bool vy1 = (iy1 >= 0) & (iy1 < HH);
            bool vx0 = (ix0 >= 0) & (ix0 < WW);
            bool vx1 = (ix1 >= 0) & (ix1 < WW);
            int cy0 = min(max(iy0, 0), HH - 1), cy1 = min(max(iy1, 0), HH - 1);
            int cx0 = min(max(ix0, 0), WW - 1), cx1 = min(max(ix1, 0), WW - 1);
            float w00 = (1.f - wy) * (1.f - wx) * ((vy0 && vx0) ? 1.f : 0.f) * mv;
            float w01 = (1.f - wy) * wx         * ((vy0 && vx1) ? 1.f : 0.f) * mv;
            float w10 = wy * (1.f - wx)         * ((vy1 && vx0) ? 1.f : 0.f) * mv;
            float w11 = wy * wx                 * ((vy1 && vx1) ? 1.f : 0.f) * mv;
            const float* p00 = xg + (size_t)(cy0 * WW + cx0) * 8;
            const float* p01 = xg + (size_t)(cy0 * WW + cx1) * 8;
            const float* p10 = xg + (size_t)(cy1 * WW + cx0) * 8;
            const float* p11 = xg + (size_t)(cy1 * WW + cx1) * 8;

#pragma unroll
            for (int half = 0; half < 2; half++) {
                float4 a00 = ((const float4*)p00)[half];
                float4 a01 = ((const float4*)p01)[half];
                float4 a10 = ((const float4*)p10)[half];
                float4 a11 = ((const float4*)p11)[half];
                float s[4];
                s[0] = a00.x * w00 + a01.x * w01 + a10.x * w10 + a11.x * w11;
                s[1] = a00.y * w00 + a01.y * w01 + a10.y * w10 + a11.y * w11;
                s[2] = a00.z * w00 + a01.z * w01 + a10.z * w10 + a11.z * w11;
                s[3] = a00.w * w00 + a01.w * w01 + a10.w * w10 + a11.w * w11;
#pragma unroll
                for (int cc = 0; cc < 4; cc++) {
                    int c = half * 4 + cc;
                    unsigned long long s2 = pack2(s[cc]);
                    const ulonglong2* w2p = (const ulonglong2*)&sW[c][k][0];
#pragma unroll
                    for (int q = 0; q < 8; q++) {
                        ulonglong2 wp = w2p[q];
                        ffma2(acc[4 * q + 0], s2, wp.x);
                        ffma2(acc[4 * q + 1], s2, wp.y);
                        wp = w2p[q + 8];
                        ffma2(acc[4 * q + 2], s2, wp.x);
                        ffma2(acc[4 * q + 3], s2, wp.y);
                    }
                }
            }
        }
    }

#pragma unroll
    for (int q = 0; q < 8; q++) {
#pragma unroll
        for (int j = 0; j < 2; j++) {
            float2 fA = unpack2(acc[4 * q + 2 * j]);
            float2 fB = unpack2(acc[4 * q + 2 * j + 1]);
            int base = (j == 0) ? (4 * q) : (32 + 4 * q);
            float r0 = fA.x + bdcn[base + 0];
            float r1 = fA.y + bdcn[base + 1];
            float r2 = fB.x + bdcn[base + 2];
            float r3 = fB.y + bdcn[base + 3];
            r0 = (r0 >= 0.f) ? r0 : 0.1f * r0;
            r1 = (r1 >= 0.f) ? r1 : 0.1f * r1;
            r2 = (r2 >= 0.f) ? r2 : 0.1f * r2;
            r3 = (r3 >= 0.f) ? r3 : 0.1f * r3;
            out[((size_t)(b * 64 + base + 0) * HH + h) * WW + w] = r0;
            out[((size_t)(b * 64 + base + 1) * HH + h) * WW + w] = r1;
            out[((size_t)(b * 64 + base + 2) * HH + h) * WW + w] = r2;
            out[((size_t)(b * 64 + base + 3) * HH + h) * WW + w] = r3;
        }
    }
}

// ---------------- launch ----------------
extern "C" void kernel_launch(void* const* d_in, const int* in_sizes, int n_in,
                              void* d_out, int out_size)
{
    const float* nbr    = (const float*)d_in[0];
    const float* warped = (const float*)d_in[1];
    const float* ref    = (const float*)d_in[2];
    const float* flows  = (const float*)d_in[3];
    const float* w1     = (const float*)d_in[4];
    const float* b1     = (const float*)d_in[5];
    const float* w2     = (const float*)d_in[6];
    const float* b2     = (const float*)d_in[7];
    const float* w_om   = (const float*)d_in[8];
    const float* b_om   = (const float*)d_in[9];
    const float* w_dcn  = (const float*)d_in[10];
    const float* b_dcn  = (const float*)d_in[11];
    float* out = (float*)d_out;

    float *p_om;
    __half *p_x1h, *p_x1l, *p_x2h, *p_x2l, *p_x3h, *p_x3l;
    __half *p_w1, *p_w2, *p_wom;
    cudaGetSymbolAddress((void**)&p_om,   g_om);
    cudaGetSymbolAddress((void**)&p_x1h,  g_x1h);
    cudaGetSymbolAddress((void**)&p_x1l,  g_x1l);
    cudaGetSymbolAddress((void**)&p_x2h,  g_x2h);
    cudaGetSymbolAddress((void**)&p_x2l,  g_x2l);
    cudaGetSymbolAddress((void**)&p_x3h,  g_x3h);
    cudaGetSymbolAddress((void**)&p_x3l,  g_x3l);
    cudaGetSymbolAddress((void**)&p_w1,   g_w1);
    cudaGetSymbolAddress((void**)&p_w2,   g_w2);
    cudaGetSymbolAddress((void**)&p_wom,  g_wom);

    const int SMEMC = 52224 + 2 * 64 * 128;   // 68608 (conv1 / conv2)
    const int SMEMO = 52224 + 2 * 72 * 128;   // 70656 (conv_om)
    cudaFuncSetAttribute(mconv_k<3, 1, 64, 64,  false>, cudaFuncAttributeMaxDynamicSharedMemorySize, SMEMC);
    cudaFuncSetAttribute(mconv_k<1, 4, 64, 64,  false>, cudaFuncAttributeMaxDynamicSharedMemorySize, SMEMC);
    cudaFuncSetAttribute(mconv_k<1, 4, 72, 216, true >, cudaFuncAttributeMaxDynamicSharedMemorySize, SMEMO);

    // 0. input/weight prep
    {
        dim3 gc(CH_ / 32, 6, BB);
        cat_k<<<gc, dim3(32, 8)>>>(warped, ref, flows);
        int t1 = 9 * 64 * 192;
        wcvt_k<<<(t1 + 255) / 256, 256>>>(w1, 64, 130, 192, p_w1, t1);
        int t2 = 9 * 64 * 64;
        wcvt_k<<<(t2 + 255) / 256, 256>>>(w2, 64, 64, 64, p_w2, t2);
        int t3 = 9 * 216 * 64;
        wcvt_k<<<(t3 + 255) / 256, 256>>>(w_om, 216, 64, 64, p_wom, t3);
        dim3 gn(CH_ / 32, 2, BB);
        nhwc_k<<<gn, dim3(32, 8)>>>(nbr);
    }
    // 1. conv1 (HMMA fp16): 130(192) -> 64, lrelu
    {
        dim3 grid(WW / 32, HH / 4, BB);
        mconv_k<3, 1, 64, 64, false><<<grid, 256, SMEMC>>>(p_x1h, p_x1l, p_w1, b1,
                                                           p_x2h, p_x2l, nullptr);
    }
    // 2. conv2 (HMMA fp16): 64 -> 64, lrelu
    {
        dim3 grid(WW / 32, HH / 4, BB);
        mconv_k<1, 4, 64, 64, false><<<grid, 256, SMEMC>>>(p_x2h, p_x2l, p_w2, b2,
                                                           p_x3h, p_x3l, nullptr);
    }
    // 3. conv_om (HMMA fp16): 64 -> 216 (3 slices of 72), linear, planar fp32
    {
        dim3 grid(WW / 32, HH / 4, BB * 3);
        mconv_k<1, 4, 72, 216, true><<<grid, 256, SMEMO>>>(p_x3h, p_x3l, p_wom, b_om,
                                                           nullptr, nullptr, p_om);
    }
    // 4. DCN + lrelu
    {
        dim3 grid(WW / 32, HH / 4, BB);
        dcn_k<<<grid, 128>>>(flows, w_dcn, b_dcn, out);
    }
}

// round 15
// speedup vs baseline: 4.9240x; 1.5013x over previous
#include <cuda_runtime.h>
#include <cuda_fp16.h>
#include <cstdint>

#define HH 192
#define WW 320
#define BB 2
#define CH_ (HH * WW)

// -------- scratch (device globals; no allocations allowed) --------
__device__ float g_xt  [BB * 8 * (size_t)CH_ * 8];      // nbr, group-planar [b][g][hw][8]
__device__ __half g_x1h[BB * (size_t)CH_ * 192];        // concat in hi (NHWC, pad 192)
__device__ __half g_x1l[BB * (size_t)CH_ * 192];
__device__ __half g_x2h[BB * (size_t)CH_ * 64];         // conv1 out hi (NHWC)
__device__ __half g_x2l[BB * (size_t)CH_ * 64];
__device__ __half g_x3h[BB * (size_t)CH_ * 64];         // conv2 out hi
__device__ __half g_x3l[BB * (size_t)CH_ * 64];
__device__ float g_om  [BB * 216 * (size_t)CH_];        // conv_om out (PLANAR NCHW)
__device__ __half g_w1 [9 * 64 * 192];                  // w1 fp16 [k][oc][192]
__device__ __half g_w2 [9 * 64 * 64];                   // w2 fp16 [k][oc][64]
__device__ __half g_wom[9 * 216 * 64];                  // w_om fp16 [k][oc][64]
__device__ __half g_wd [9 * 64 * 64];                   // w_dcn fp16 [k][oc][64]

// -------- cp.async helpers --------
__device__ __forceinline__ void cpa16(unsigned dst, const void* src, bool valid) {
    asm volatile("cp.async.cg.shared.global [%0], [%1], 16, %2;"
                 :: "r"(dst), "l"(src), "r"(valid ? 16u : 0u));
}
__device__ __forceinline__ void cpa_commit() { asm volatile("cp.async.commit_group;"); }
__device__ __forceinline__ void cpa_wait0()  { asm volatile("cp.async.wait_group 0;"); }

__device__ __forceinline__ uint32_t smem_u32(const void* p) {
    uint32_t a;
    asm("{ .reg .u64 t; cvta.to.shared.u64 t, %1; cvt.u32.u64 %0, t; }" : "=r"(a) : "l"(p));
    return a;
}

// -------- mma.sync helpers (fp16 in, fp32 accum) --------
#define LDSM4(r0, r1, r2, r3, a) \
    asm volatile("ldmatrix.sync.aligned.m8n8.x4.shared.b16 {%0,%1,%2,%3}, [%4];" \
                 : "=r"(r0), "=r"(r1), "=r"(r2), "=r"(r3) : "r"(a))
#define LDSM2(r0, r1, a) \
    asm volatile("ldmatrix.sync.aligned.m8n8.x2.shared.b16 {%0,%1}, [%2];" \
                 : "=r"(r0), "=r"(r1) : "r"(a))
#define MMA16816(d, a0, a1, a2, a3, b0, b1) \
    asm volatile("mma.sync.aligned.m16n8k16.row.col.f32.f16.f16.f32 " \
                 "{%0,%1,%2,%3}, {%4,%5,%6,%7}, {%8,%9}, {%0,%1,%2,%3};" \
                 : "+f"((d)[0]), "+f"((d)[1]), "+f"((d)[2]), "+f"((d)[3]) \
                 : "r"(a0), "r"(a1), "r"(a2), "r"(a3), "r"(b0), "r"(b1))

// ---------------- concat -> NHWC fp16 hi/lo, 192-ch padded ----------------
__global__ void cat_k(const float* __restrict__ warped, const float* __restrict__ ref,
                      const float* __restrict__ flows)
{
    __shared__ float t[32][33];
    const int hw0 = blockIdx.x * 32;
    const int c0  = blockIdx.y * 32;
    const int b   = blockIdx.z;
    const int tx  = threadIdx.x, ty = threadIdx.y;
#pragma unroll
    for (int i = ty; i < 32; i += 8) {
        int cg = c0 + i;
        float v = 0.f;
        if (cg < 64)        v = warped[((size_t)(b * 64 + cg)) * CH_ + hw0 + tx];
        else if (cg < 128)  v = ref   [((size_t)(b * 64 + cg - 64)) * CH_ + hw0 + tx];
        else if (cg < 130)  v = flows [((size_t)(b * 2  + cg - 128)) * CH_ + hw0 + tx];
        t[i][tx] = v;
    }
    __syncthreads();
#pragma unroll
    for (int i = ty; i < 32; i += 8) {
        float v = t[tx][i];
        __half hi = __float2half(v);
        __half lo = __float2half(v - __half2float(hi));
        size_t o = ((size_t)b * CH_ + hw0 + i) * 192 + c0 + tx;
        g_x1h[o] = hi;
        g_x1l[o] = lo;
    }
}

// ---------------- weight fp16 convert: [oc][ci][k] -> [k][oc][CINP] ----------------
__global__ void wcvt_k(const float* __restrict__ w, int NOC, int CINR, int CINP,
                       __half* __restrict__ wh, int total)
{
    int i = blockIdx.x * blockDim.x + threadIdx.x;
    if (i >= total) return;
    int ci = i % CINP;
    int oc = (i / CINP) % NOC;
    int k  = i / (CINP * NOC);
    float v = (ci < CINR) ? w[((size_t)oc * CINR + ci) * 9 + k] : 0.f;
    wh[i] = __float2half(v);
}

// ---------------- NCHW -> group-planar [b][g][hw][8] repack (for dcn) ----------------
__global__ void nhwc_k(const float* __restrict__ x)
{
    __shared__ float t[32][33];
    const int hw0 = blockIdx.x * 32;
    const int c0  = blockIdx.y * 32;
    const int b   = blockIdx.z;
    const int tx  = threadIdx.x, ty = threadIdx.y;
#pragma unroll
    for (int i = ty; i < 32; i += 8)
        t[i][tx] = x[((size_t)(b * 64 + c0 + i)) * CH_ + hw0 + tx];
    __syncthreads();
#pragma unroll
    for (int i = ty; i < 32; i += 8) {
        int c = c0 + tx;
        int g = c >> 3, cc = c & 7;
        g_xt[((size_t)(b * 8 + g) * CH_ + hw0 + i) * 8 + cc] = t[tx][i];
    }
}

// ---------------- mma.sync fp16 3x3 conv, 4-row tile, B double-buffered ----------------
template<int NCI, int SLAST, int NOCS, int NOCTOT, bool OMOUT>
__global__ __launch_bounds__(256)
void mconv_k(const __half* __restrict__ xh, const __half* __restrict__ xl,
             const __half* __restrict__ wgt,
             const float* __restrict__ bias,
             __half* __restrict__ yh, __half* __restrict__ yl,
             float* __restrict__ om)
{
    constexpr int NB = NOCS / 8;
    constexpr int NSL = NOCTOT / NOCS;
    constexpr int XSTR = NCI * 64;
    constexpr unsigned PATCH_HALF = 6 * 34 * 128;     // 26112
    constexpr unsigned B_OFF = 2 * PATCH_HALF;        // 52224
    constexpr unsigned BBUF = (unsigned)NOCS * 128u;

    extern __shared__ __align__(128) char smraw[];
    const unsigned sb = smem_u32(smraw);

    const int tid  = threadIdx.x;
    const int w    = tid >> 5;
    const int lane = tid & 31;
    const int b    = blockIdx.z / NSL;
    const int oc0  = (blockIdx.z % NSL) * NOCS;
    const int x0   = blockIdx.x * 32;
    const int y0   = blockIdx.y * 4;

    const __half* xhb = xh + (size_t)b * CH_ * XSTR;
    const __half* xlb = xl + (size_t)b * CH_ * XSTR;

    float acc[NB][4];
#pragma unroll
    for (int nb = 0; nb < NB; nb++)
#pragma unroll
        for (int j = 0; j < 4; j++) acc[nb][j] = 0.f;

    const int gid = lane >> 2, tig = lane & 3;
    const int l16 = lane & 15;
    const int lr  = l16 & 7;
    const int lh  = l16 >> 3;
    const int ahalf = lane >> 4;
    const int r = w >> 1, xbase = (w & 1) * 16;
    const int apx0 = (r + 1) * 34 + 1 + xbase + l16;

    auto stage_B = [&](int ch, int tap, int buf) {
        for (int i = tid; i < NOCS * 8; i += 256) {
            int c   = i & 7;
            int row = i >> 3;
            const __half* src = wgt
                + ((size_t)tap * NOCTOT + oc0 + row) * XSTR + ch * 64 + c * 8;
            unsigned dst = sb + B_OFF + (unsigned)buf * BBUF
                         + (unsigned)row * 128u + (unsigned)((c ^ (row & 7)) << 4);
            cpa16(dst, src, true);
        }
    };

    int buf = 0;
    for (int ch = 0; ch < NCI; ch++) {
        if (ch > 0) __syncthreads();
        for (int i = tid; i < 3264; i += 256) {
            int c   = i & 7;
            int pxl = (i >> 3) % 204;
            int hl  = i / 1632;
            int y = y0 - 1 + pxl / 34;
            int x = x0 - 1 + pxl % 34;
            bool v = (y >= 0) && (y < HH) && (x >= 0) && (x < WW);
            const __half* src = (hl ? xlb : xhb)
                + (size_t)((v ? y : 0) * WW + (v ? x : 0)) * XSTR + ch * 64 + c * 8;
            unsigned dst = sb + (unsigned)hl * PATCH_HALF + (unsigned)pxl * 128u
                         + (unsigned)((c ^ (pxl & 7)) << 4);
            cpa16(dst, src, v);
        }
        stage_B(ch, 0, buf);
        cpa_commit();

        const int SN = (ch == NCI - 1) ? SLAST : 4;

        for (int tap = 0; tap < 9; tap++) {
            cpa_wait0();
            __syncthreads();
            if (tap + 1 < 9) {
                stage_B(ch, tap + 1, buf ^ 1);
                cpa_commit();
            }

            const int ky = tap / 3 - 1, kx = tap % 3 - 1;
            const int apx = apx0 + ky * 34 + kx;
            const unsigned aline = sb + (unsigned)apx * 128u;
            const int a7 = apx & 7;
            const unsigned bline = sb + B_OFF + (unsigned)buf * BBUF + (unsigned)lr * 128u;

            for (int s = 0; s < SN; s++) {
                uint32_t ah0, ah1, ah2, ah3, al0, al1, al2, al3;
                unsigned achunk = (unsigned)((s * 2 + ahalf) ^ a7) << 4;
                LDSM4(ah0, ah1, ah2, ah3, aline + achunk);
                LDSM4(al0, al1, al2, al3, aline + PATCH_HALF + achunk);
#pragma unroll
                for (int nb = 0; nb < NB; nb++) {
                    uint32_t bh0, bh1;
                    unsigned baddr = bline + (unsigned)nb * 1024u
                                   + (unsigned)(((s * 2 + lh) ^ lr) << 4);
                    LDSM2(bh0, bh1, baddr);
                    MMA16816(acc[nb], ah0, ah1, ah2, ah3, bh0, bh1);
                    MMA16816(acc[nb], al0, al1, al2, al3, bh0, bh1);
                }
            }
            buf ^= 1;
        }
    }

    const int ya = y0 + r;
    const int xa = x0 + xbase + gid;
    const int pixA = ya * WW + xa;
    const int pixB = pixA + 8;
    if (!OMOUT) {
        const size_t pa = (size_t)b * CH_ + pixA;
        const size_t pb = pa + 8;
#pragma unroll
        for (int nb = 0; nb < NB; nb++) {
            int oc = nb * 8 + tig * 2;
            float b0 = bias[oc], b1 = bias[oc + 1];
#pragma unroll
            for (int hp = 0; hp < 2; hp++) {
                float v0 = acc[nb][2 * hp + 0] + b0;
                float v1 = acc[nb][2 * hp + 1] + b1;
                v0 = (v0 >= 0.f) ? v0 : 0.1f * v0;
                v1 = (v1 >= 0.f) ? v1 : 0.1f * v1;
                __half h0 = __float2half(v0), h1 = __float2half(v1);
                __half l0 = __float2half(v0 - __half2float(h0));
                __half l1 = __float2half(v1 - __half2float(h1));
                size_t base = ((hp ? pb : pa)) * 64 + oc;
                ((uint32_t*)yh)[base >> 1] =
                    (uint32_t)__half_as_ushort(h0) | ((uint32_t)__half_as_ushort(h1) << 16);
                ((uint32_t*)yl)[base >> 1] =
                    (uint32_t)__half_as_ushort(l0) | ((uint32_t)__half_as_ushort(l1) << 16);
            }
        }
    } else {
#pragma unroll
        for (int nb = 0; nb < NB; nb++) {
            int oc = oc0 + nb * 8 + tig * 2;
            float b0 = bias[oc], b1 = bias[oc + 1];
            float* pl0 = om + ((size_t)(b * 216 + oc))     * CH_;
            float* pl1 = om + ((size_t)(b * 216 + oc + 1)) * CH_;
            pl0[pixA] = acc[nb][0] + b0;
            pl1[pixA] = acc[nb][1] + b1;
            pl0[pixB] = acc[nb][2] + b0;
            pl1[pixB] = acc[nb][3] + b1;
        }
    }
}

// ---------------- DCN via HMMA: per tap, gather A[128px][64ch] then MMA ----------------
// block = 256 (8 warps), tile 4 rows x 32 px. grid: (WW/32, HH/4, BB)
__global__ __launch_bounds__(256)
void dcn_mma_k(const float* __restrict__ flows,
               const __half* __restrict__ wd,     // fp16 [k][oc][64]
               const float* __restrict__ bdcn,
               float* __restrict__ out)
{
    constexpr unsigned A_LO = 16384;        // A_HI at 0
    constexpr unsigned B_OFF = 32768;
    constexpr unsigned BBUF = 8192;

    extern __shared__ __align__(128) char smraw[];
    const unsigned sb = smem_u32(smraw);
    __shared__ float sFlow[2][128];

    const int tid  = threadIdx.x;
    const int w    = tid >> 5;
    const int lane = tid & 31;
    const int b    = blockIdx.z;
    const int x0   = blockIdx.x * 32;
    const int y0   = blockIdx.y * 4;

    if (tid < 128) {
        int pix = (y0 + (tid >> 5)) * WW + x0 + (tid & 31);
        sFlow[0][tid] = flows[((size_t)(b * 2 + 0)) * CH_ + pix];
        sFlow[1][tid] = flows[((size_t)(b * 2 + 1)) * CH_ + pix];
    }

    float acc[8][4];
#pragma unroll
    for (int nb = 0; nb < 8; nb++)
#pragma unroll
        for (int j = 0; j < 4; j++) acc[nb][j] = 0.f;

    const int gid = lane >> 2, tig = lane & 3;
    const int l16 = lane & 15;
    const int lr  = l16 & 7;
    const int lh  = l16 >> 3;
    const int ahalf = lane >> 4;
    const int r = w >> 1, xbase = (w & 1) * 16;
    const int arow = r * 32 + xbase + l16;
    const unsigned aline = sb + (unsigned)arow * 128u;
    const int a7 = arow & 7;

    const float* omb0 = g_om + (size_t)b * 216 * CH_;
    const float* xtb  = g_xt + (size_t)b * 8 * CH_ * 8;

    auto stage_B = [&](int tap, int buf) {
        for (int i = tid; i < 512; i += 256) {
            int c = i & 7, row = i >> 3;
            const __half* src = wd + ((size_t)tap * 64 + row) * 64 + c * 8;
            unsigned dst = sb + B_OFF + (unsigned)buf * BBUF
                         + (unsigned)row * 128u + (unsigned)((c ^ (row & 7)) << 4);
            cpa16(dst, src, true);
        }
    };

    stage_B(0, 0);
    cpa_commit();
    __syncthreads();   // sFlow ready

    int buf = 0;
    for (int tap = 0; tap < 9; tap++) {
        if (tap > 0) __syncthreads();   // prev MMA reads of A done
        const int ky = tap / 3 - 1, kx = tap % 3 - 1;

        // ---- build A: 1024 (px, g) samples, fp16 hi/lo, swizzled ----
#pragma unroll
        for (int j = 0; j < 4; j++) {
            int i  = tid + 256 * j;
            int px = i & 127, g = i >> 7;      // j in 0..3 -> g in {0,1}? i up to 1023 -> g 0..7? i>>7: 0..7. ok
            int row = px >> 5, col = px & 31;
            int h = y0 + row, x = x0 + col;
            int pix = h * WW + x;
            float oy = omb0[(size_t)(2 * (g * 9 + tap))     * CH_ + pix] + sFlow[1][px];
            float ox = omb0[(size_t)(2 * (g * 9 + tap) + 1) * CH_ + pix] + sFlow[0][px];
            float mraw = omb0[(size_t)(144 + g * 9 + tap)   * CH_ + pix];
            float mv = 1.f / (1.f + __expf(-mraw));

            float pyf = (float)(h + ky) + oy;
            float pxf = (float)(x + kx) + ox;
            float y0f = floorf(pyf), x0f = floorf(pxf);
            float wy = pyf - y0f, wx = pxf - x0f;
            int iy0 = (int)y0f, ix0 = (int)x0f;
            int iy1 = iy0 + 1, ix1 = ix0 + 1;
            bool vy0 = (iy0 >= 0) & (iy0 < HH);
            bool vy1 = (iy1 >= 0) & (iy1 < HH);
            bool vx0 = (ix0 >= 0) & (ix0 < WW);
            bool vx1 = (ix1 >= 0) & (ix1 < WW);
            int cy0 = min(max(iy0, 0), HH - 1), cy1 = min(max(iy1, 0), HH - 1);
            int cx0 = min(max(ix0, 0), WW - 1), cx1 = min(max(ix1, 0), WW - 1);
            float w00 = (1.f - wy) * (1.f - wx) * ((vy0 && vx0) ? 1.f : 0.f) * mv;
            float w01 = (1.f - wy) * wx         * ((vy0 && vx1) ? 1.f : 0.f) * mv;
            float w10 = wy * (1.f - wx)         * ((vy1 && vx0) ? 1.f : 0.f) * mv;
            float w11 = wy * wx                 * ((vy1 && vx1) ? 1.f : 0.f) * mv;
            const float* xg = xtb + (size_t)g * CH_ * 8;
            const float* p00 = xg + (size_t)(cy0 * WW + cx0) * 8;
            const float* p01 = xg + (size_t)(cy0 * WW + cx1) * 8;
            const float* p10 = xg + (size_t)(cy1 * WW + cx0) * 8;
            const float* p11 = xg + (size_t)(cy1 * WW + cx1) * 8;

            float s[8];
#pragma unroll
            for (int half = 0; half < 2; half++) {
                float4 a00 = ((const float4*)p00)[half];
                float4 a01 = ((const float4*)p01)[half];
                float4 a10 = ((const float4*)p10)[half];
                float4 a11 = ((const float4*)p11)[half];
                s[half * 4 + 0] = a00.x * w00 + a01.x * w01 + a10.x * w10 + a11.x * w11;
                s[half * 4 + 1] = a00.y * w00 + a01.y * w01 + a10.y * w10 + a11.y * w11;
                s[half * 4 + 2] = a00.z * w00 + a01.z * w01 + a10.z * w10 + a11.z * w11;
                s[half * 4 + 3] = a00.w * w00 + a01.w * w01 + a10.w * w10 + a11.w * w11;
            }
            uint32_t uh[4], ul[4];
#pragma unroll
            for (int q = 0; q < 4; q++) {
                __half h0 = __float2half(s[2 * q]);
                __half h1 = __float2half(s[2 * q + 1]);
                __half l0 = __float2half(s[2 * q]     - __half2float(h0));
                __half l1 = __float2half(s[2 * q + 1] - __half2float(h1));
                uh[q] = (uint32_t)__half_as_ushort(h0) | ((uint32_t)__half_as_ushort(h1) << 16);
                ul[q] = (uint32_t)__half_as_ushort(l0) | ((uint32_t)__half_as_ushort(l1) << 16);
            }
            unsigned off = (unsigned)px * 128u + (unsigned)((g ^ (px & 7)) << 4);
            *(uint4*)(smraw + off)        = make_uint4(uh[0], uh[1], uh[2], uh[3]);
            *(uint4*)(smraw + A_LO + off) = make_uint4(ul[0], ul[1], ul[2], ul[3]);
        }
        cpa_wait0();
        __syncthreads();      // A built + B(tap) arrived
        if (tap < 8) {
            stage_B(tap + 1, buf ^ 1);
            cpa_commit();
        }

        const unsigned bline = sb + B_OFF + (unsigned)buf * BBUF + (unsigned)lr * 128u;
#pragma unroll
        for (int s = 0; s < 4; s++) {
            uint32_t ah0, ah1, ah2, ah3, al0, al1, al2, al3;
            unsigned achunk = (unsigned)((s * 2 + ahalf) ^ a7) << 4;
            LDSM4(ah0, ah1, ah2, ah3, aline + achunk);
            LDSM4(al0, al1, al2, al3, aline + A_LO + achunk);
#pragma unroll
            for (int nb = 0; nb < 8; nb++) {
                uint32_t bh0, bh1;
                unsigned baddr = bline + (unsigned)nb * 1024u
                               + (unsigned)(((s * 2 + lh) ^ lr) << 4);
                LDSM2(bh0, bh1, baddr);
                MMA16816(acc[nb], ah0, ah1, ah2, ah3, bh0, bh1);
                MMA16816(acc[nb], al0, al1, al2, al3, bh0, bh1);
            }
        }
        buf ^= 1;
    }

    // ---- epilogue: lrelu + planar NCHW out ----
    const int pixA = (y0 + r) * WW + x0 + xbase + gid;
    const int pixB = pixA + 8;
#pragma unroll
    for (int nb = 0; nb < 8; nb++) {
        int oc = nb * 8 + tig * 2;
        float b0 = bdcn[oc], b1 = bdcn[oc + 1];
        float* pl0 = out + ((size_t)(b * 64 + oc))     * CH_;
        float* pl1 = out + ((size_t)(b * 64 + oc + 1)) * CH_;
        float v;
        v = acc[nb][0] + b0; pl0[pixA] = (v >= 0.f) ? v : 0.1f * v;
        v = acc[nb][1] + b1; pl1[pixA] = (v >= 0.f) ? v : 0.1f * v;
        v = acc[nb][2] + b0; pl0[pixB] = (v >= 0.f) ? v : 0.1f * v;
        v = acc[nb][3] + b1; pl1[pixB] = (v >= 0.f) ? v : 0.1f * v;
    }
}

// ---------------- launch ----------------
extern "C" void kernel_launch(void* const* d_in, const int* in_sizes, int n_in,
                              void* d_out, int out_size)
{
    const float* nbr    = (const float*)d_in[0];
    const float* warped = (const float*)d_in[1];
    const float* ref    = (const float*)d_in[2];
    const float* flows  = (const float*)d_in[3];
    const float* w1     = (const float*)d_in[4];
    const float* b1     = (const float*)d_in[5];
    const float* w2     = (const float*)d_in[6];
    const float* b2     = (const float*)d_in[7];
    const float* w_om   = (const float*)d_in[8];
    const float* b_om   = (const float*)d_in[9];
    const float* w_dcn  = (const float*)d_in[10];
    const float* b_dcn  = (const float*)d_in[11];
    float* out = (float*)d_out;

    float *p_om;
    __half *p_x1h, *p_x1l, *p_x2h, *p_x2l, *p_x3h, *p_x3l;
    __half *p_w1, *p_w2, *p_wom, *p_wd;
    cudaGetSymbolAddress((void**)&p_om,   g_om);
    cudaGetSymbolAddress((void**)&p_x1h,  g_x1h);
    cudaGetSymbolAddress((void**)&p_x1l,  g_x1l);
    cudaGetSymbolAddress((void**)&p_x2h,  g_x2h);
    cudaGetSymbolAddress((void**)&p_x2l,  g_x2l);
    cudaGetSymbolAddress((void**)&p_x3h,  g_x3h);
    cudaGetSymbolAddress((void**)&p_x3l,  g_x3l);
    cudaGetSymbolAddress((void**)&p_w1,   g_w1);
    cudaGetSymbolAddress((void**)&p_w2,   g_w2);
    cudaGetSymbolAddress((void**)&p_wom,  g_wom);
    cudaGetSymbolAddress((void**)&p_wd,   g_wd);

    const int SMEMC = 52224 + 2 * 64 * 128;   // 68608 (conv1 / conv2)
    const int SMEMO = 52224 + 2 * 72 * 128;   // 70656 (conv_om)
    const int SMEMD = 32768 + 2 * 8192;       // 49152 (dcn)
    cudaFuncSetAttribute(mconv_k<3, 1, 64, 64,  false>, cudaFuncAttributeMaxDynamicSharedMemorySize, SMEMC);
    cudaFuncSetAttribute(mconv_k<1, 4, 64, 64,  false>, cudaFuncAttributeMaxDynamicSharedMemorySize, SMEMC);
    cudaFuncSetAttribute(mconv_k<1, 4, 72, 216, true >, cudaFuncAttributeMaxDynamicSharedMemorySize, SMEMO);
    cudaFuncSetAttribute(dcn_mma_k, cudaFuncAttributeMaxDynamicSharedMemorySize, SMEMD);

    // 0. input/weight prep
    {
        dim3 gc(CH_ / 32, 6, BB);
        cat_k<<<gc, dim3(32, 8)>>>(warped, ref, flows);
        int t1 = 9 * 64 * 192;
        wcvt_k<<<(t1 + 255) / 256, 256>>>(w1, 64, 130, 192, p_w1, t1);
        int t2 = 9 * 64 * 64;
        wcvt_k<<<(t2 + 255) / 256, 256>>>(w2, 64, 64, 64, p_w2, t2);
        int t3 = 9 * 216 * 64;
        wcvt_k<<<(t3 + 255) / 256, 256>>>(w_om, 216, 64, 64, p_wom, t3);
        int t4 = 9 * 64 * 64;
        wcvt_k<<<(t4 + 255) / 256, 256>>>(w_dcn, 64, 64, 64, p_wd, t4);
        dim3 gn(CH_ / 32, 2, BB);
        nhwc_k<<<gn, dim3(32, 8)>>>(nbr);
    }
    // 1. conv1 (HMMA fp16): 130(192) -> 64, lrelu
    {
        dim3 grid(WW / 32, HH / 4, BB);
        mconv_k<3, 1, 64, 64, false><<<grid, 256, SMEMC>>>(p_x1h, p_x1l, p_w1, b1,
                                                           p_x2h, p_x2l, nullptr);
    }
    // 2. conv2 (HMMA fp16): 64 -> 64, lrelu
    {
        dim3 grid(WW / 32, HH / 4, BB);
        mconv_k<1, 4, 64, 64, false><<<grid, 256, SMEMC>>>(p_x2h, p_x2l, p_w2, b2,
                                                           p_x3h, p_x3l, nullptr);
    }
    // 3. conv_om (HMMA fp16): 64 -> 216 (3 slices of 72), linear, planar fp32
    {
        dim3 grid(WW / 32, HH / 4, BB * 3);
        mconv_k<1, 4, 72, 216, true><<<grid, 256, SMEMO>>>(p_x3h, p_x3l, p_wom, b_om,
                                                           nullptr, nullptr, p_om);
    }
    // 4. DCN (HMMA) + lrelu
    {
        dim3 grid(WW / 32, HH / 4, BB);
        dcn_mma_k<<<grid, 256, SMEMD>>>(flows, p_wd, b_dcn, out);
    }
}

// round 16
// speedup vs baseline: 6.5114x; 1.3224x over previous
#include <cuda_runtime.h>
#include <cuda_fp16.h>
#include <cstdint>

#define HH 192
#define WW 320
#define BB 2
#define CH_ (HH * WW)

// -------- scratch (device globals; no allocations allowed) --------
__device__ float g_xt  [BB * 8 * (size_t)CH_ * 8];      // nbr, group-planar [b][g][hw][8]
__device__ __half g_x1 [BB * (size_t)CH_ * 192];        // concat in (NHWC, pad 192)
__device__ __half g_x2 [BB * (size_t)CH_ * 64];         // conv1 out (NHWC)
__device__ __half g_x3 [BB * (size_t)CH_ * 64];         // conv2 out
__device__ float g_om  [BB * 216 * (size_t)CH_];        // conv_om out (PLANAR NCHW)
__device__ __half g_w1 [9 * 64 * 192];                  // w1 fp16 [k][oc][192]
__device__ __half g_w2 [9 * 64 * 64];                   // w2 fp16 [k][oc][64]
__device__ __half g_wom[9 * 216 * 64];                  // w_om fp16 [k][oc][64]
__device__ __half g_wd [9 * 64 * 64];                   // w_dcn fp16 [k][oc][64]

// -------- cp.async helpers --------
__device__ __forceinline__ void cpa16(unsigned dst, const void* src, bool valid) {
    asm volatile("cp.async.cg.shared.global [%0], [%1], 16, %2;"
                 :: "r"(dst), "l"(src), "r"(valid ? 16u : 0u));
}
__device__ __forceinline__ void cpa_commit() { asm volatile("cp.async.commit_group;"); }
__device__ __forceinline__ void cpa_wait0()  { asm volatile("cp.async.wait_group 0;"); }

__device__ __forceinline__ uint32_t smem_u32(const void* p) {
    uint32_t a;
    asm("{ .reg .u64 t; cvta.to.shared.u64 t, %1; cvt.u32.u64 %0, t; }" : "=r"(a) : "l"(p));
    return a;
}

// -------- mma.sync helpers (fp16 in, fp32 accum) --------
#define LDSM4(r0, r1, r2, r3, a) \
    asm volatile("ldmatrix.sync.aligned.m8n8.x4.shared.b16 {%0,%1,%2,%3}, [%4];" \
                 : "=r"(r0), "=r"(r1), "=r"(r2), "=r"(r3) : "r"(a))
#define LDSM2(r0, r1, a) \
    asm volatile("ldmatrix.sync.aligned.m8n8.x2.shared.b16 {%0,%1}, [%2];" \
                 : "=r"(r0), "=r"(r1) : "r"(a))
#define MMA16816(d, a0, a1, a2, a3, b0, b1) \
    asm volatile("mma.sync.aligned.m16n8k16.row.col.f32.f16.f16.f32 " \
                 "{%0,%1,%2,%3}, {%4,%5,%6,%7}, {%8,%9}, {%0,%1,%2,%3};" \
                 : "+f"((d)[0]), "+f"((d)[1]), "+f"((d)[2]), "+f"((d)[3]) \
                 : "r"(a0), "r"(a1), "r"(a2), "r"(a3), "r"(b0), "r"(b1))

// ---------------- concat -> NHWC fp16, 192-ch padded ----------------
__global__ void cat_k(const float* __restrict__ warped, const float* __restrict__ ref,
                      const float* __restrict__ flows)
{
    __shared__ float t[32][33];
    const int hw0 = blockIdx.x * 32;
    const int c0  = blockIdx.y * 32;
    const int b   = blockIdx.z;
    const int tx  = threadIdx.x, ty = threadIdx.y;
#pragma unroll
    for (int i = ty; i < 32; i += 8) {
        int cg = c0 + i;
        float v = 0.f;
        if (cg < 64)        v = warped[((size_t)(b * 64 + cg)) * CH_ + hw0 + tx];
        else if (cg < 128)  v = ref   [((size_t)(b * 64 + cg - 64)) * CH_ + hw0 + tx];
        else if (cg < 130)  v = flows [((size_t)(b * 2  + cg - 128)) * CH_ + hw0 + tx];
        t[i][tx] = v;
    }
    __syncthreads();
#pragma unroll
    for (int i = ty; i < 32; i += 8) {
        size_t o = ((size_t)b * CH_ + hw0 + i) * 192 + c0 + tx;
        g_x1[o] = __float2half(t[tx][i]);
    }
}

// ---------------- weight fp16 convert: [oc][ci][k] -> [k][oc][CINP] ----------------
__global__ void wcvt_k(const float* __restrict__ w, int NOC, int CINR, int CINP,
                       __half* __restrict__ wh, int total)
{
    int i = blockIdx.x * blockDim.x + threadIdx.x;
    if (i >= total) return;
    int ci = i % CINP;
    int oc = (i / CINP) % NOC;
    int k  = i / (CINP * NOC);
    float v = (ci < CINR) ? w[((size_t)oc * CINR + ci) * 9 + k] : 0.f;
    wh[i] = __float2half(v);
}

// ---------------- NCHW -> group-planar [b][g][hw][8] repack (for dcn) ----------------
__global__ void nhwc_k(const float* __restrict__ x)
{
    __shared__ float t[32][33];
    const int hw0 = blockIdx.x * 32;
    const int c0  = blockIdx.y * 32;
    const int b   = blockIdx.z;
    const int tx  = threadIdx.x, ty = threadIdx.y;
#pragma unroll
    for (int i = ty; i < 32; i += 8)
        t[i][tx] = x[((size_t)(b * 64 + c0 + i)) * CH_ + hw0 + tx];
    __syncthreads();
#pragma unroll
    for (int i = ty; i < 32; i += 8) {
        int c = c0 + tx;
        int g = c >> 3, cc = c & 7;
        g_xt[((size_t)(b * 8 + g) * CH_ + hw0 + i) * 8 + cc] = t[tx][i];
    }
}

// ---------------- mma.sync fp16 3x3 conv, 4-row tile, B double-buffered ----------------
// block = 256 thr (8 warps), out tile 4 rows x 32 px (M=128). Patch 6x34 px.
// grid: (WW/32, HH/4, BB * (NOCTOT/NOCS))
template<int NCI, int SLAST, int NOCS, int NOCTOT, bool OMOUT>
__global__ __launch_bounds__(256)
void mconv_k(const __half* __restrict__ xin,
             const __half* __restrict__ wgt,
             const float* __restrict__ bias,
             __half* __restrict__ yout,
             float* __restrict__ om)
{
    constexpr int NB = NOCS / 8;
    constexpr int NSL = NOCTOT / NOCS;
    constexpr int XSTR = NCI * 64;
    constexpr unsigned PATCH = 6 * 34 * 128;          // 26112
    constexpr unsigned B_OFF = PATCH;
    constexpr unsigned BBUF = (unsigned)NOCS * 128u;

    extern __shared__ __align__(128) char smraw[];
    const unsigned sb = smem_u32(smraw);

    const int tid  = threadIdx.x;
    const int w    = tid >> 5;
    const int lane = tid & 31;
    const int b    = blockIdx.z / NSL;
    const int oc0  = (blockIdx.z % NSL) * NOCS;
    const int x0   = blockIdx.x * 32;
    const int y0   = blockIdx.y * 4;

    const __half* xb = xin + (size_t)b * CH_ * XSTR;

    float acc[NB][4];
#pragma unroll
    for (int nb = 0; nb < NB; nb++)
#pragma unroll
        for (int j = 0; j < 4; j++) acc[nb][j] = 0.f;

    const int gid = lane >> 2, tig = lane & 3;
    const int l16 = lane & 15;
    const int lr  = l16 & 7;
    const int lh  = l16 >> 3;
    const int ahalf = lane >> 4;
    const int r = w >> 1, xbase = (w & 1) * 16;
    const int apx0 = (r + 1) * 34 + 1 + xbase + l16;

    auto stage_B = [&](int ch, int tap, int buf) {
        for (int i = tid; i < NOCS * 8; i += 256) {
            int c   = i & 7;
            int row = i >> 3;
            const __half* src = wgt
                + ((size_t)tap * NOCTOT + oc0 + row) * XSTR + ch * 64 + c * 8;
            unsigned dst = sb + B_OFF + (unsigned)buf * BBUF
                         + (unsigned)row * 128u + (unsigned)((c ^ (row & 7)) << 4);
            cpa16(dst, src, true);
        }
    };

    int buf = 0;
    for (int ch = 0; ch < NCI; ch++) {
        if (ch > 0) __syncthreads();
        // ---- stage patch chunk (6 rows x 34 px x 64 ci) + first B tile ----
        for (int i = tid; i < 1632; i += 256) {
            int c   = i & 7;
            int pxl = i >> 3;               // 0..203
            int y = y0 - 1 + pxl / 34;
            int x = x0 - 1 + pxl % 34;
            bool v = (y >= 0) && (y < HH) && (x >= 0) && (x < WW);
            const __half* src = xb
                + (size_t)((v ? y : 0) * WW + (v ? x : 0)) * XSTR + ch * 64 + c * 8;
            unsigned dst = sb + (unsigned)pxl * 128u
                         + (unsigned)((c ^ (pxl & 7)) << 4);
            cpa16(dst, src, v);
        }
        stage_B(ch, 0, buf);
        cpa_commit();

        const int SN = (ch == NCI - 1) ? SLAST : 4;

        for (int tap = 0; tap < 9; tap++) {
            cpa_wait0();
            __syncthreads();
            if (tap + 1 < 9) {
                stage_B(ch, tap + 1, buf ^ 1);
                cpa_commit();
            }

            const int ky = tap / 3 - 1, kx = tap % 3 - 1;
            const int apx = apx0 + ky * 34 + kx;
            const unsigned aline = sb + (unsigned)apx * 128u;
            const int a7 = apx & 7;
            const unsigned bline = sb + B_OFF + (unsigned)buf * BBUF + (unsigned)lr * 128u;

            for (int s = 0; s < SN; s++) {
                uint32_t ah0, ah1, ah2, ah3;
                unsigned achunk = (unsigned)((s * 2 + ahalf) ^ a7) << 4;
                LDSM4(ah0, ah1, ah2, ah3, aline + achunk);
#pragma unroll
                for (int nb = 0; nb < NB; nb++) {
                    uint32_t bh0, bh1;
                    unsigned baddr = bline + (unsigned)nb * 1024u
                                   + (unsigned)(((s * 2 + lh) ^ lr) << 4);
                    LDSM2(bh0, bh1, baddr);
                    MMA16816(acc[nb], ah0, ah1, ah2, ah3, bh0, bh1);
                }
            }
            buf ^= 1;
        }
    }

    // ---- epilogue ----
    const int ya = y0 + r;
    const int xa = x0 + xbase + gid;
    const int pixA = ya * WW + xa;
    const int pixB = pixA + 8;
    if (!OMOUT) {
        const size_t pa = (size_t)b * CH_ + pixA;
        const size_t pb = pa + 8;
#pragma unroll
        for (int nb = 0; nb < NB; nb++) {
            int oc = nb * 8 + tig * 2;
            float b0 = bias[oc], b1 = bias[oc + 1];
#pragma unroll
            for (int hp = 0; hp < 2; hp++) {
                float v0 = acc[nb][2 * hp + 0] + b0;
                float v1 = acc[nb][2 * hp + 1] + b1;
                v0 = (v0 >= 0.f) ? v0 : 0.1f * v0;
                v1 = (v1 >= 0.f) ? v1 : 0.1f * v1;
                __half h0 = __float2half(v0), h1 = __float2half(v1);
                size_t base = ((hp ? pb : pa)) * 64 + oc;
                ((uint32_t*)yout)[base >> 1] =
                    (uint32_t)__half_as_ushort(h0) | ((uint32_t)__half_as_ushort(h1) << 16);
            }
        }
    } else {
        // planar NCHW: om[(b*216+oc)*CH_ + pix]
#pragma unroll
        for (int nb = 0; nb < NB; nb++) {
            int oc = oc0 + nb * 8 + tig * 2;
            float b0 = bias[oc], b1 = bias[oc + 1];
            float* pl0 = om + ((size_t)(b * 216 + oc))     * CH_;
            float* pl1 = om + ((size_t)(b * 216 + oc + 1)) * CH_;
            pl0[pixA] = acc[nb][0] + b0;
            pl1[pixA] = acc[nb][1] + b1;
            pl0[pixB] = acc[nb][2] + b0;
            pl1[pixB] = acc[nb][3] + b1;
        }
    }
}

// ---------------- DCN via HMMA: per tap, gather A[128px][64ch] then MMA ----------------
// block = 256 (8 warps), tile 4 rows x 32 px. grid: (WW/32, HH/4, BB)
__global__ __launch_bounds__(256)
void dcn_mma_k(const float* __restrict__ flows,
               const __half* __restrict__ wd,     // fp16 [k][oc][64]
               const float* __restrict__ bdcn,
               float* __restrict__ out)
{
    constexpr unsigned B_OFF = 16384;      // A at 0 (128 rows x 128B)
    constexpr unsigned BBUF = 8192;

    extern __shared__ __align__(128) char smraw[];
    const unsigned sb = smem_u32(smraw);
    __shared__ float sFlow[2][128];

    const int tid  = threadIdx.x;
    const int w    = tid >> 5;
    const int lane = tid & 31;
    const int b    = blockIdx.z;
    const int x0   = blockIdx.x * 32;
    const int y0   = blockIdx.y * 4;

    if (tid < 128) {
        int pix = (y0 + (tid >> 5)) * WW + x0 + (tid & 31);
        sFlow[0][tid] = flows[((size_t)(b * 2 + 0)) * CH_ + pix];
        sFlow[1][tid] = flows[((size_t)(b * 2 + 1)) * CH_ + pix];
    }

    float acc[8][4];
#pragma unroll
    for (int nb = 0; nb < 8; nb++)
#pragma unroll
        for (int j = 0; j < 4; j++) acc[nb][j] = 0.f;

    const int gid = lane >> 2, tig = lane & 3;
    const int l16 = lane & 15;
    const int lr  = l16 & 7;
    const int lh  = l16 >> 3;
    const int ahalf = lane >> 4;
    const int r = w >> 1, xbase = (w & 1) * 16;
    const int arow = r * 32 + xbase + l16;
    const unsigned aline = sb + (unsigned)arow * 128u;
    const int a7 = arow & 7;

    const float* omb0 = g_om + (size_t)b * 216 * CH_;
    const float* xtb  = g_xt + (size_t)b * 8 * CH_ * 8;

    auto stage_B = [&](int tap, int buf) {
        for (int i = tid; i < 512; i += 256) {
            int c = i & 7, row = i >> 3;
            const __half* src = wd + ((size_t)tap * 64 + row) * 64 + c * 8;
            unsigned dst = sb + B_OFF + (unsigned)buf * BBUF
                         + (unsigned)row * 128u + (unsigned)((c ^ (row & 7)) << 4);
            cpa16(dst, src, true);
        }
    };

    stage_B(0, 0);
    cpa_commit();
    __syncthreads();   // sFlow ready

    int buf = 0;
    for (int tap = 0; tap < 9; tap++) {
        if (tap > 0) __syncthreads();   // prev MMA reads of A done
        const int ky = tap / 3 - 1, kx = tap % 3 - 1;

        // ---- build A: 1024 (px, g) samples, fp16, swizzled ----
#pragma unroll
        for (int j = 0; j < 4; j++) {
            int i  = tid + 256 * j;
            int px = i & 127, g = i >> 7;
            int row = px >> 5, col = px & 31;
            int h = y0 + row, x = x0 + col;
            int pix = h * WW + x;
            float oy = omb0[(size_t)(2 * (g * 9 + tap))     * CH_ + pix] + sFlow[1][px];
            float ox = omb0[(size_t)(2 * (g * 9 + tap) + 1) * CH_ + pix] + sFlow[0][px];
            float mraw = omb0[(size_t)(144 + g * 9 + tap)   * CH_ + pix];
            float mv = 1.f / (1.f + __expf(-mraw));

            float pyf = (float)(h + ky) + oy;
            float pxf = (float)(x + kx) + ox;
            float y0f = floorf(pyf), x0f = floorf(pxf);
            float wy = pyf - y0f, wx = pxf - x0f;
            int iy0 = (int)y0f, ix0 = (int)x0f;
            int iy1 = iy0 + 1, ix1 = ix0 + 1;
            bool vy0 = (iy0 >= 0) & (iy0 < HH);
            bool vy1 = (iy1 >= 0) & (iy1 < HH);
            bool vx0 = (ix0 >= 0) & (ix0 < WW);
            bool vx1 = (ix1 >= 0) & (ix1 < WW);
            int cy0 = min(max(iy0, 0), HH - 1), cy1 = min(max(iy1, 0), HH - 1);
            int cx0 = min(max(ix0, 0), WW - 1), cx1 = min(max(ix1, 0), WW - 1);
            float w00 = (1.f - wy) * (1.f - wx) * ((vy0 && vx0) ? 1.f : 0.f) * mv;
            float w01 = (1.f - wy) * wx         * ((vy0 && vx1) ? 1.f : 0.f) * mv;
            float w10 = wy * (1.f - wx)         * ((vy1 && vx0) ? 1.f : 0.f) * mv;
            float w11 = wy * wx                 * ((vy1 && vx1) ? 1.f : 0.f) * mv;
            const float* xg = xtb + (size_t)g * CH_ * 8;
            const float* p00 = xg + (size_t)(cy0 * WW + cx0) * 8;
            const float* p01 = xg + (size_t)(cy0 * WW + cx1) * 8;
            const float* p10 = xg + (size_t)(cy1 * WW + cx0) * 8;
            const float* p11 = xg + (size_t)(cy1 * WW + cx1) * 8;

            uint32_t uh[4];
#pragma unroll
            for (int half = 0; half < 2; half++) {
                float4 a00 = ((const float4*)p00)[half];
                float4 a01 = ((const float4*)p01)[half];
                float4 a10 = ((const float4*)p10)[half];
                float4 a11 = ((const float4*)p11)[half];
                float s0 = a00.x * w00 + a01.x * w01 + a10.x * w10 + a11.x * w11;
                float s1 = a00.y * w00 + a01.y * w01 + a10.y * w10 + a11.y * w11;
                float s2 = a00.z * w00 + a01.z * w01 + a10.z * w10 + a11.z * w11;
                float s3 = a00.w * w00 + a01.w * w01 + a10.w * w10 + a11.w * w11;
                __half h0 = __float2half(s0), h1 = __float2half(s1);
                __half h2 = __float2half(s2), h3 = __float2half(s3);
                uh[half * 2 + 0] = (uint32_t)__half_as_ushort(h0) | ((uint32_t)__half_as_ushort(h1) << 16);
                uh[half * 2 + 1] = (uint32_t)__half_as_ushort(h2) | ((uint32_t)__half_as_ushort(h3) << 16);
            }
            unsigned off = (unsigned)px * 128u + (unsigned)((g ^ (px & 7)) << 4);
            *(uint4*)(smraw + off) = make_uint4(uh[0], uh[1], uh[2], uh[3]);
        }
        cpa_wait0();
        __syncthreads();      // A built + B(tap) arrived
        if (tap < 8) {
            stage_B(tap + 1, buf ^ 1);
            cpa_commit();
        }

        const unsigned bline = sb + B_OFF + (unsigned)buf * BBUF + (unsigned)lr * 128u;
#pragma unroll
        for (int s = 0; s < 4; s++) {
            uint32_t ah0, ah1, ah2, ah3;
            unsigned achunk = (unsigned)((s * 2 + ahalf) ^ a7) << 4;
            LDSM4(ah0, ah1, ah2, ah3, aline + achunk);
#pragma unroll
            for (int nb = 0; nb < 8; nb++) {
                uint32_t bh0, bh1;
                unsigned baddr = bline + (unsigned)nb * 1024u
                               + (unsigned)(((s * 2 + lh) ^ lr) << 4);
                LDSM2(bh0, bh1, baddr);
                MMA16816(acc[nb], ah0, ah1, ah2, ah3, bh0, bh1);
            }
        }
        buf ^= 1;
    }

    // ---- epilogue: lrelu + planar NCHW out ----
    const int pixA = (y0 + r) * WW + x0 + xbase + gid;
    const int pixB = pixA + 8;
#pragma unroll
    for (int nb = 0; nb < 8; nb++) {
        int oc = nb * 8 + tig * 2;
        float b0 = bdcn[oc], b1 = bdcn[oc + 1];
        float* pl0 = out + ((size_t)(b * 64 + oc))     * CH_;
        float* pl1 = out + ((size_t)(b * 64 + oc + 1)) * CH_;
        float v;
        v = acc[nb][0] + b0; pl0[pixA] = (v >= 0.f) ? v : 0.1f * v;
        v = acc[nb][1] + b1; pl1[pixA] = (v >= 0.f) ? v : 0.1f * v;
        v = acc[nb][2] + b0; pl0[pixB] = (v >= 0.f) ? v : 0.1f * v;
        v = acc[nb][3] + b1; pl1[pixB] = (v >= 0.f) ? v : 0.1f * v;
    }
}

// ---------------- launch ----------------
extern "C" void kernel_launch(void* const* d_in, const int* in_sizes, int n_in,
                              void* d_out, int out_size)
{
    const float* nbr    = (const float*)d_in[0];
    const float* warped = (const float*)d_in[1];
    const float* ref    = (const float*)d_in[2];
    const float* flows  = (const float*)d_in[3];
    const float* w1     = (const float*)d_in[4];
    const float* b1     = (const float*)d_in[5];
    const float* w2     = (const float*)d_in[6];
    const float* b2     = (const float*)d_in[7];
    const float* w_om   = (const float*)d_in[8];
    const float* b_om   = (const float*)d_in[9];
    const float* w_dcn  = (const float*)d_in[10];
    const float* b_dcn  = (const float*)d_in[11];
    float* out = (float*)d_out;

    float *p_om;
    __half *p_x1, *p_x2, *p_x3, *p_w1, *p_w2, *p_wom, *p_wd;
    cudaGetSymbolAddress((void**)&p_om,  g_om);
    cudaGetSymbolAddress((void**)&p_x1,  g_x1);
    cudaGetSymbolAddress((void**)&p_x2,  g_x2);
    cudaGetSymbolAddress((void**)&p_x3,  g_x3);
    cudaGetSymbolAddress((void**)&p_w1,  g_w1);
    cudaGetSymbolAddress((void**)&p_w2,  g_w2);
    cudaGetSymbolAddress((void**)&p_wom, g_wom);
    cudaGetSymbolAddress((void**)&p_wd,  g_wd);

    const int SMEMC = 26112 + 2 * 64 * 128;   // 42496 (conv1 / conv2)
    const int SMEMO = 26112 + 2 * 72 * 128;   // 44544 (conv_om)
    const int SMEMD = 16384 + 2 * 8192;       // 32768 (dcn)
    cudaFuncSetAttribute(mconv_k<3, 1, 64, 64,  false>, cudaFuncAttributeMaxDynamicSharedMemorySize, SMEMC);
    cudaFuncSetAttribute(mconv_k<1, 4, 64, 64,  false>, cudaFuncAttributeMaxDynamicSharedMemorySize, SMEMC);
    cudaFuncSetAttribute(mconv_k<1, 4, 72, 216, true >, cudaFuncAttributeMaxDynamicSharedMemorySize, SMEMO);
    cudaFuncSetAttribute(dcn_mma_k, cudaFuncAttributeMaxDynamicSharedMemorySize, SMEMD);

    // 0. input/weight prep
    {
        dim3 gc(CH_ / 32, 6, BB);
        cat_k<<<gc, dim3(32, 8)>>>(warped, ref, flows);
        int t1 = 9 * 64 * 192;
        wcvt_k<<<(t1 + 255) / 256, 256>>>(w1, 64, 130, 192, p_w1, t1);
        int t2 = 9 * 64 * 64;
        wcvt_k<<<(t2 + 255) / 256, 256>>>(w2, 64, 64, 64, p_w2, t2);
        int t3 = 9 * 216 * 64;
        wcvt_k<<<(t3 + 255) / 256, 256>>>(w_om, 216, 64, 64, p_wom, t3);
        int t4 = 9 * 64 * 64;
        wcvt_k<<<(t4 + 255) / 256, 256>>>(w_dcn, 64, 64, 64, p_wd, t4);
        dim3 gn(CH_ / 32, 2, BB);
        nhwc_k<<<gn, dim3(32, 8)>>>(nbr);
    }
    // 1. conv1 (HMMA fp16): 130(192) -> 64, lrelu
    {
        dim3 grid(WW / 32, HH / 4, BB);
        mconv_k<3, 1, 64, 64, false><<<grid, 256, SMEMC>>>(p_x1, p_w1, b1, p_x2, nullptr);
    }
    // 2. conv2 (HMMA fp16): 64 -> 64, lrelu
    {
        dim3 grid(WW / 32, HH / 4, BB);
        mconv_k<1, 4, 64, 64, false><<<grid, 256, SMEMC>>>(p_x2, p_w2, b2, p_x3, nullptr);
    }
    // 3. conv_om (HMMA fp16): 64 -> 216 (3 slices of 72), linear, planar fp32
    {
        dim3 grid(WW / 32, HH / 4, BB * 3);
        mconv_k<1, 4, 72, 216, true><<<grid, 256, SMEMO>>>(p_x3, p_wom, b_om, nullptr, p_om);
    }
    // 4. DCN (HMMA) + lrelu
    {
        dim3 grid(WW / 32, HH / 4, BB);
        dcn_mma_k<<<grid, 256, SMEMD>>>(flows, p_wd, b_dcn, out);
    }
}

// round 17
// speedup vs baseline: 6.8131x; 1.0463x over previous
#include <cuda_runtime.h>
#include <cuda_fp16.h>
#include <cstdint>

#define HH 192
#define WW 320
#define BB 2
#define CH_ (HH * WW)

// -------- scratch (device globals; no allocations allowed) --------
__device__ float g_xt  [BB * 8 * (size_t)CH_ * 8];      // nbr, group-planar [b][g][hw][8]
__device__ __half g_x1 [BB * (size_t)CH_ * 192];        // concat in (NHWC, pad 192)
__device__ __half g_x2 [BB * (size_t)CH_ * 64];         // conv1 out (NHWC)
__device__ __half g_x3 [BB * (size_t)CH_ * 64];         // conv2 out
__device__ float g_om  [BB * 216 * (size_t)CH_];        // conv_om out (PLANAR NCHW)
__device__ __half g_w1 [9 * 64 * 192];                  // w1 fp16 [k][oc][192]
__device__ __half g_w2 [9 * 64 * 64];                   // w2 fp16 [k][oc][64]
__device__ __half g_wom[9 * 216 * 64];                  // w_om fp16 [k][oc][64]
__device__ __half g_wd [9 * 64 * 64];                   // w_dcn fp16 [k][oc][64]

// -------- cp.async helpers --------
__device__ __forceinline__ void cpa16(unsigned dst, const void* src, bool valid) {
    asm volatile("cp.async.cg.shared.global [%0], [%1], 16, %2;"
                 :: "r"(dst), "l"(src), "r"(valid ? 16u : 0u));
}
__device__ __forceinline__ void cpa_commit() { asm volatile("cp.async.commit_group;"); }
__device__ __forceinline__ void cpa_wait0()  { asm volatile("cp.async.wait_group 0;"); }

__device__ __forceinline__ uint32_t smem_u32(const void* p) {
    uint32_t a;
    asm("{ .reg .u64 t; cvta.to.shared.u64 t, %1; cvt.u32.u64 %0, t; }" : "=r"(a) : "l"(p));
    return a;
}

// -------- mma.sync helpers (fp16 in, fp32 accum) --------
#define LDSM4(r0, r1, r2, r3, a) \
    asm volatile("ldmatrix.sync.aligned.m8n8.x4.shared.b16 {%0,%1,%2,%3}, [%4];" \
                 : "=r"(r0), "=r"(r1), "=r"(r2), "=r"(r3) : "r"(a))
#define LDSM2(r0, r1, a) \
    asm volatile("ldmatrix.sync.aligned.m8n8.x2.shared.b16 {%0,%1}, [%2];" \
                 : "=r"(r0), "=r"(r1) : "r"(a))
#define MMA16816(d, a0, a1, a2, a3, b0, b1) \
    asm volatile("mma.sync.aligned.m16n8k16.row.col.f32.f16.f16.f32 " \
                 "{%0,%1,%2,%3}, {%4,%5,%6,%7}, {%8,%9}, {%0,%1,%2,%3};" \
                 : "+f"((d)[0]), "+f"((d)[1]), "+f"((d)[2]), "+f"((d)[3]) \
                 : "r"(a0), "r"(a1), "r"(a2), "r"(a3), "r"(b0), "r"(b1))

// ---------------- concat -> NHWC fp16, 192-ch padded ----------------
__global__ void cat_k(const float* __restrict__ warped, const float* __restrict__ ref,
                      const float* __restrict__ flows)
{
    __shared__ float t[32][33];
    const int hw0 = blockIdx.x * 32;
    const int c0  = blockIdx.y * 32;
    const int b   = blockIdx.z;
    const int tx  = threadIdx.x, ty = threadIdx.y;
#pragma unroll
    for (int i = ty; i < 32; i += 8) {
        int cg = c0 + i;
        float v = 0.f;
        if (cg < 64)        v = warped[((size_t)(b * 64 + cg)) * CH_ + hw0 + tx];
        else if (cg < 128)  v = ref   [((size_t)(b * 64 + cg - 64)) * CH_ + hw0 + tx];
        else if (cg < 130)  v = flows [((size_t)(b * 2  + cg - 128)) * CH_ + hw0 + tx];
        t[i][tx] = v;
    }
    __syncthreads();
#pragma unroll
    for (int i = ty; i < 32; i += 8) {
        size_t o = ((size_t)b * CH_ + hw0 + i) * 192 + c0 + tx;
        g_x1[o] = __float2half(t[tx][i]);
    }
}

// ---------------- weight fp16 convert: [oc][ci][k] -> [k][oc][CINP] ----------------
__global__ void wcvt_k(const float* __restrict__ w, int NOC, int CINR, int CINP,
                       __half* __restrict__ wh, int total)
{
    int i = blockIdx.x * blockDim.x + threadIdx.x;
    if (i >= total) return;
    int ci = i % CINP;
    int oc = (i / CINP) % NOC;
    int k  = i / (CINP * NOC);
    float v = (ci < CINR) ? w[((size_t)oc * CINR + ci) * 9 + k] : 0.f;
    wh[i] = __float2half(v);
}

// ---------------- NCHW -> group-planar [b][g][hw][8] repack (for dcn) ----------------
__global__ void nhwc_k(const float* __restrict__ x)
{
    __shared__ float t[32][33];
    const int hw0 = blockIdx.x * 32;
    const int c0  = blockIdx.y * 32;
    const int b   = blockIdx.z;
    const int tx  = threadIdx.x, ty = threadIdx.y;
#pragma unroll
    for (int i = ty; i < 32; i += 8)
        t[i][tx] = x[((size_t)(b * 64 + c0 + i)) * CH_ + hw0 + tx];
    __syncthreads();
#pragma unroll
    for (int i = ty; i < 32; i += 8) {
        int c = c0 + tx;
        int g = c >> 3, cc = c & 7;
        g_xt[((size_t)(b * 8 + g) * CH_ + hw0 + i) * 8 + cc] = t[tx][i];
    }
}

// ---------------- mma.sync fp16 3x3 conv, 4x64 tile, B double-buffered ----------------
// block = 256 thr (8 warps); each warp: 32 px = two 16-px M-strips sharing B frags.
// Patch 6x66 px. grid: (WW/64, HH/4, BB * (NOCTOT/NOCS))
template<int NCI, int SLAST, int NOCS, int NOCTOT, bool OMOUT>
__global__ __launch_bounds__(256, 2)
void mconv_k(const __half* __restrict__ xin,
             const __half* __restrict__ wgt,
             const float* __restrict__ bias,
             __half* __restrict__ yout,
             float* __restrict__ om)
{
    constexpr int NB = NOCS / 8;
    constexpr int NSL = NOCTOT / NOCS;
    constexpr int XSTR = NCI * 64;
    constexpr unsigned PATCH = 6 * 66 * 128;          // 50688
    constexpr unsigned B_OFF = PATCH;
    constexpr unsigned BBUF = (unsigned)NOCS * 128u;

    extern __shared__ __align__(128) char smraw[];
    const unsigned sb = smem_u32(smraw);

    const int tid  = threadIdx.x;
    const int w    = tid >> 5;
    const int lane = tid & 31;
    const int b    = blockIdx.z / NSL;
    const int oc0  = (blockIdx.z % NSL) * NOCS;
    const int x0   = blockIdx.x * 64;
    const int y0   = blockIdx.y * 4;

    const __half* xb = xin + (size_t)b * CH_ * XSTR;

    float acc[2][NB][4];
#pragma unroll
    for (int m = 0; m < 2; m++)
#pragma unroll
        for (int nb = 0; nb < NB; nb++)
#pragma unroll
            for (int j = 0; j < 4; j++) acc[m][nb][j] = 0.f;

    const int gid = lane >> 2, tig = lane & 3;
    const int l16 = lane & 15;
    const int lr  = l16 & 7;
    const int lh  = l16 >> 3;
    const int ahalf = lane >> 4;
    const int r = w >> 1, xs = (w & 1) * 32;
    const int apx0 = (r + 1) * 66 + 1 + xs + l16;     // m=0 strip; m=1 adds 16

    auto stage_B = [&](int ch, int tap, int buf) {
        for (int i = tid; i < NOCS * 8; i += 256) {
            int c   = i & 7;
            int row = i >> 3;
            const __half* src = wgt
                + ((size_t)tap * NOCTOT + oc0 + row) * XSTR + ch * 64 + c * 8;
            unsigned dst = sb + B_OFF + (unsigned)buf * BBUF
                         + (unsigned)row * 128u + (unsigned)((c ^ (row & 7)) << 4);
            cpa16(dst, src, true);
        }
    };

    int buf = 0;
    for (int ch = 0; ch < NCI; ch++) {
        if (ch > 0) __syncthreads();
        // ---- stage patch chunk (6 rows x 66 px x 64 ci) + first B tile ----
        for (int i = tid; i < 3168; i += 256) {
            int c   = i & 7;
            int pxl = i >> 3;               // 0..395
            int y = y0 - 1 + pxl / 66;
            int x = x0 - 1 + pxl % 66;
            bool v = (y >= 0) && (y < HH) && (x >= 0) && (x < WW);
            const __half* src = xb
                + (size_t)((v ? y : 0) * WW + (v ? x : 0)) * XSTR + ch * 64 + c * 8;
            unsigned dst = sb + (unsigned)pxl * 128u
                         + (unsigned)((c ^ (pxl & 7)) << 4);
            cpa16(dst, src, v);
        }
        stage_B(ch, 0, buf);
        cpa_commit();

        const int SN = (ch == NCI - 1) ? SLAST : 4;

        for (int tap = 0; tap < 9; tap++) {
            cpa_wait0();
            __syncthreads();
            if (tap + 1 < 9) {
                stage_B(ch, tap + 1, buf ^ 1);
                cpa_commit();
            }

            const int ky = tap / 3 - 1, kx = tap % 3 - 1;
            const int apxA = apx0 + ky * 66 + kx;
            const int apxB = apxA + 16;
            const unsigned alineA = sb + (unsigned)apxA * 128u;
            const unsigned alineB = sb + (unsigned)apxB * 128u;
            const int a7A = apxA & 7, a7B = apxB & 7;
            const unsigned bline = sb + B_OFF + (unsigned)buf * BBUF + (unsigned)lr * 128u;

            for (int s = 0; s < SN; s++) {
                uint32_t aA0, aA1, aA2, aA3, aB0, aB1, aB2, aB3;
                int sc = s * 2 + ahalf;
                LDSM4(aA0, aA1, aA2, aA3, alineA + (unsigned)((sc ^ a7A) << 4));
                LDSM4(aB0, aB1, aB2, aB3, alineB + (unsigned)((sc ^ a7B) << 4));
#pragma unroll
                for (int nb = 0; nb < NB; nb++) {
                    uint32_t bh0, bh1;
                    unsigned baddr = bline + (unsigned)nb * 1024u
                                   + (unsigned)(((s * 2 + lh) ^ lr) << 4);
                    LDSM2(bh0, bh1, baddr);
                    MMA16816(acc[0][nb], aA0, aA1, aA2, aA3, bh0, bh1);
                    MMA16816(acc[1][nb], aB0, aB1, aB2, aB3, bh0, bh1);
                }
            }
            buf ^= 1;
        }
    }

    // ---- epilogue ----
    const int ya = y0 + r;
#pragma unroll
    for (int m = 0; m < 2; m++) {
        const int xa = x0 + xs + m * 16 + gid;
        const int pixA = ya * WW + xa;
        const int pixB = pixA + 8;
        if (!OMOUT) {
            const size_t pa = (size_t)b * CH_ + pixA;
            const size_t pb = pa + 8;
#pragma unroll
            for (int nb = 0; nb < NB; nb++) {
                int oc = nb * 8 + tig * 2;
                float b0 = bias[oc], b1 = bias[oc + 1];
#pragma unroll
                for (int hp = 0; hp < 2; hp++) {
                    float v0 = acc[m][nb][2 * hp + 0] + b0;
                    float v1 = acc[m][nb][2 * hp + 1] + b1;
                    v0 = (v0 >= 0.f) ? v0 : 0.1f * v0;
                    v1 = (v1 >= 0.f) ? v1 : 0.1f * v1;
                    __half h0 = __float2half(v0), h1 = __float2half(v1);
                    size_t base = ((hp ? pb : pa)) * 64 + oc;
                    ((uint32_t*)yout)[base >> 1] =
                        (uint32_t)__half_as_ushort(h0) | ((uint32_t)__half_as_ushort(h1) << 16);
                }
            }
        } else {
#pragma unroll
            for (int nb = 0; nb < NB; nb++) {
                int oc = oc0 + nb * 8 + tig * 2;
                float b0 = bias[oc], b1 = bias[oc + 1];
                float* pl0 = om + ((size_t)(b * 216 + oc))     * CH_;
                float* pl1 = om + ((size_t)(b * 216 + oc + 1)) * CH_;
                pl0[pixA] = acc[m][nb][0] + b0;
                pl1[pixA] = acc[m][nb][1] + b1;
                pl0[pixB] = acc[m][nb][2] + b0;
                pl1[pixB] = acc[m][nb][3] + b1;
            }
        }
    }
}

// ---------------- DCN via HMMA, 4x64 tile ----------------
// block = 256 (8 warps), each warp 32 px (two M-strips). grid: (WW/64, HH/4, BB)
__global__ __launch_bounds__(256, 2)
void dcn_mma_k(const float* __restrict__ flows,
               const __half* __restrict__ wd,     // fp16 [k][oc][64]
               const float* __restrict__ bdcn,
               float* __restrict__ out)
{
    constexpr unsigned B_OFF = 32768;      // A at 0 (256 rows x 128B)
    constexpr unsigned BBUF = 8192;

    extern __shared__ __align__(128) char smraw[];
    const unsigned sb = smem_u32(smraw);
    __shared__ float sFlow[2][256];

    const int tid  = threadIdx.x;
    const int w    = tid >> 5;
    const int lane = tid & 31;
    const int b    = blockIdx.z;
    const int x0   = blockIdx.x * 64;
    const int y0   = blockIdx.y * 4;

    {
        int pix = (y0 + (tid >> 6)) * WW + x0 + (tid & 63);
        sFlow[0][tid] = flows[((size_t)(b * 2 + 0)) * CH_ + pix];
        sFlow[1][tid] = flows[((size_t)(b * 2 + 1)) * CH_ + pix];
    }

    float acc[2][8][4];
#pragma unroll
    for (int m = 0; m < 2; m++)
#pragma unroll
        for (int nb = 0; nb < 8; nb++)
#pragma unroll
            for (int j = 0; j < 4; j++) acc[m][nb][j] = 0.f;

    const int gid = lane >> 2, tig = lane & 3;
    const int l16 = lane & 15;
    const int lr  = l16 & 7;
    const int lh  = l16 >> 3;
    const int ahalf = lane >> 4;
    const int r = w >> 1, xs = (w & 1) * 32;
    const int arowA = r * 64 + xs + l16;
    const int arowB = arowA + 16;
    const unsigned alineA = sb + (unsigned)arowA * 128u;
    const unsigned alineB = sb + (unsigned)arowB * 128u;
    const int a7A = arowA & 7, a7B = arowB & 7;

    const float* omb0 = g_om + (size_t)b * 216 * CH_;
    const float* xtb  = g_xt + (size_t)b * 8 * CH_ * 8;

    auto stage_B = [&](int tap, int buf) {
        for (int i = tid; i < 512; i += 256) {
            int c = i & 7, row = i >> 3;
            const __half* src = wd + ((size_t)tap * 64 + row) * 64 + c * 8;
            unsigned dst = sb + B_OFF + (unsigned)buf * BBUF
                         + (unsigned)row * 128u + (unsigned)((c ^ (row & 7)) << 4);
            cpa16(dst, src, true);
        }
    };

    stage_B(0, 0);
    cpa_commit();
    __syncthreads();   // sFlow ready

    int buf = 0;
    for (int tap = 0; tap < 9; tap++) {
        if (tap > 0) __syncthreads();   // prev MMA reads of A done
        const int ky = tap / 3 - 1, kx = tap % 3 - 1;

        // ---- build A: 2048 (px, g) samples, fp16, swizzled ----
#pragma unroll
        for (int j = 0; j < 8; j++) {
            int i  = tid + 256 * j;
            int px = i & 255, g = i >> 8;
            int row = px >> 6, col = px & 63;
            int h = y0 + row, x = x0 + col;
            int pix = h * WW + x;
            float oy = omb0[(size_t)(2 * (g * 9 + tap))     * CH_ + pix] + sFlow[1][px];
            float ox = omb0[(size_t)(2 * (g * 9 + tap) + 1) * CH_ + pix] + sFlow[0][px];
            float mraw = omb0[(size_t)(144 + g * 9 + tap)   * CH_ + pix];
            float mv = 1.f / (1.f + __expf(-mraw));

            float pyf = (float)(h + ky) + oy;
            float pxf = (float)(x + kx) + ox;
            float y0f = floorf(pyf), x0f = floorf(pxf);
            float wy = pyf - y0f, wx = pxf - x0f;
            int iy0 = (int)y0f, ix0 = (int)x0f;
            int iy1 = iy0 + 1, ix1 = ix0 + 1;
            bool vy0 = (iy0 >= 0) & (iy0 < HH);
            bool vy1 = (iy1 >= 0) & (iy1 < HH);
            bool vx0 = (ix0 >= 0) & (ix0 < WW);
            bool vx1 = (ix1 >= 0) & (ix1 < WW);
            int cy0 = min(max(iy0, 0), HH - 1), cy1 = min(max(iy1, 0), HH - 1);
            int cx0 = min(max(ix0, 0), WW - 1), cx1 = min(max(ix1, 0), WW - 1);
            float w00 = (1.f - wy) * (1.f - wx) * ((vy0 && vx0) ? 1.f : 0.f) * mv;
            float w01 = (1.f - wy) * wx         * ((vy0 && vx1) ? 1.f : 0.f) * mv;
            float w10 = wy * (1.f - wx)         * ((vy1 && vx0) ? 1.f : 0.f) * mv;
            float w11 = wy * wx                 * ((vy1 && vx1) ? 1.f : 0.f) * mv;
            const float* xg = xtb + (size_t)g * CH_ * 8;
            const float* p00 = xg + (size_t)(cy0 * WW + cx0) * 8;
            const float* p01 = xg + (size_t)(cy0 * WW + cx1) * 8;
            const float* p10 = xg + (size_t)(cy1 * WW + cx0) * 8;
            const float* p11 = xg + (size_t)(cy1 * WW + cx1) * 8;

            uint32_t uh[4];
#pragma unroll
            for (int half = 0; half < 2; half++) {
                float4 a00 = ((const float4*)p00)[half];
                float4 a01 = ((const float4*)p01)[half];
                float4 a10 = ((const float4*)p10)[half];
                float4 a11 = ((const float4*)p11)[half];
                float s0 = a00.x * w00 + a01.x * w01 + a10.x * w10 + a11.x * w11;
                float s1 = a00.y * w00 + a01.y * w01 + a10.y * w10 + a11.y * w11;
                float s2 = a00.z * w00 + a01.z * w01 + a10.z * w10 + a11.z * w11;
                float s3 = a00.w * w00 + a01.w * w01 + a10.w * w10 + a11.w * w11;
                __half h0 = __float2half(s0), h1 = __float2half(s1);
                __half h2 = __float2half(s2), h3 = __float2half(s3);
                uh[half * 2 + 0] = (uint32_t)__half_as_ushort(h0) | ((uint32_t)__half_as_ushort(h1) << 16);
                uh[half * 2 + 1] = (uint32_t)__half_as_ushort(h2) | ((uint32_t)__half_as_ushort(h3) << 16);
            }
            unsigned off = (unsigned)px * 128u + (unsigned)((g ^ (px & 7)) << 4);
            *(uint4*)(smraw + off) = make_uint4(uh[0], uh[1], uh[2], uh[3]);
        }
        cpa_wait0();
        __syncthreads();      // A built + B(tap) arrived
        if (tap < 8) {
            stage_B(tap + 1, buf ^ 1);
            cpa_commit();
        }

        const unsigned bline = sb + B_OFF + (unsigned)buf * BBUF + (unsigned)lr * 128u;
#pragma unroll
        for (int s = 0; s < 4; s++) {
            uint32_t aA0, aA1, aA2, aA3, aB0, aB1, aB2, aB3;
            int sc = s * 2 + ahalf;
            LDSM4(aA0, aA1, aA2, aA3, alineA + (unsigned)((sc ^ a7A) << 4));
            LDSM4(aB0, aB1, aB2, aB3, alineB + (unsigned)((sc ^ a7B) << 4));
#pragma unroll
            for (int nb = 0; nb < 8; nb++) {
                uint32_t bh0, bh1;
                unsigned baddr = bline + (unsigned)nb * 1024u
                               + (unsigned)(((s * 2 + lh) ^ lr) << 4);
                LDSM2(bh0, bh1, baddr);
                MMA16816(acc[0][nb], aA0, aA1, aA2, aA3, bh0, bh1);
                MMA16816(acc[1][nb], aB0, aB1, aB2, aB3, bh0, bh1);
            }
        }
        buf ^= 1;
    }

    // ---- epilogue: lrelu + planar NCHW out ----
#pragma unroll
    for (int m = 0; m < 2; m++) {
        const int pixA = (y0 + r) * WW + x0 + xs + m * 16 + gid;
        const int pixB = pixA + 8;
#pragma unroll
        for (int nb = 0; nb < 8; nb++) {
            int oc = nb * 8 + tig * 2;
            float b0 = bdcn[oc], b1 = bdcn[oc + 1];
            float* pl0 = out + ((size_t)(b * 64 + oc))     * CH_;
            float* pl1 = out + ((size_t)(b * 64 + oc + 1)) * CH_;
            float v;
            v = acc[m][nb][0] + b0; pl0[pixA] = (v >= 0.f) ? v : 0.1f * v;
            v = acc[m][nb][1] + b1; pl1[pixA] = (v >= 0.f) ? v : 0.1f * v;
            v = acc[m][nb][2] + b0; pl0[pixB] = (v >= 0.f) ? v : 0.1f * v;
            v = acc[m][nb][3] + b1; pl1[pixB] = (v >= 0.f) ? v : 0.1f * v;
        }
    }
}

// ---------------- launch ----------------
extern "C" void kernel_launch(void* const* d_in, const int* in_sizes, int n_in,
                              void* d_out, int out_size)
{
    const float* nbr    = (const float*)d_in[0];
    const float* warped = (const float*)d_in[1];
    const float* ref    = (const float*)d_in[2];
    const float* flows  = (const float*)d_in[3];
    const float* w1     = (const float*)d_in[4];
    const float* b1     = (const float*)d_in[5];
    const float* w2     = (const float*)d_in[6];
    const float* b2     = (const float*)d_in[7];
    const float* w_om   = (const float*)d_in[8];
    const float* b_om   = (const float*)d_in[9];
    const float* w_dcn  = (const float*)d_in[10];
    const float* b_dcn  = (const float*)d_in[11];
    float* out = (float*)d_out;

    float *p_om;
    __half *p_x1, *p_x2, *p_x3, *p_w1, *p_w2, *p_wom, *p_wd;
    cudaGetSymbolAddress((void**)&p_om,  g_om);
    cudaGetSymbolAddress((void**)&p_x1,  g_x1);
    cudaGetSymbolAddress((void**)&p_x2,  g_x2);
    cudaGetSymbolAddress((void**)&p_x3,  g_x3);
    cudaGetSymbolAddress((void**)&p_w1,  g_w1);
    cudaGetSymbolAddress((void**)&p_w2,  g_w2);
    cudaGetSymbolAddress((void**)&p_wom, g_wom);
    cudaGetSymbolAddress((void**)&p_wd,  g_wd);

    const int SMEMC = 50688 + 2 * 64 * 128;   // 67072 (conv1 / conv2)
    const int SMEMO = 50688 + 2 * 72 * 128;   // 69120 (conv_om)
    const int SMEMD = 32768 + 2 * 8192;       // 49152 (dcn)
    cudaFuncSetAttribute(mconv_k<3, 1, 64, 64,  false>, cudaFuncAttributeMaxDynamicSharedMemorySize, SMEMC);
    cudaFuncSetAttribute(mconv_k<1, 4, 64, 64,  false>, cudaFuncAttributeMaxDynamicSharedMemorySize, SMEMC);
    cudaFuncSetAttribute(mconv_k<1, 4, 72, 216, true >, cudaFuncAttributeMaxDynamicSharedMemorySize, SMEMO);
    cudaFuncSetAttribute(dcn_mma_k, cudaFuncAttributeMaxDynamicSharedMemorySize, SMEMD);

    // 0. input/weight prep
    {
        dim3 gc(CH_ / 32, 6, BB);
        cat_k<<<gc, dim3(32, 8)>>>(warped, ref, flows);
        int t1 = 9 * 64 * 192;
        wcvt_k<<<(t1 + 255) / 256, 256>>>(w1, 64, 130, 192, p_w1, t1);
        int t2 = 9 * 64 * 64;
        wcvt_k<<<(t2 + 255) / 256, 256>>>(w2, 64, 64, 64, p_w2, t2);
        int t3 = 9 * 216 * 64;
        wcvt_k<<<(t3 + 255) / 256, 256>>>(w_om, 216, 64, 64, p_wom, t3);
        int t4 = 9 * 64 * 64;
        wcvt_k<<<(t4 + 255) / 256, 256>>>(w_dcn, 64, 64, 64, p_wd, t4);
        dim3 gn(CH_ / 32, 2, BB);
        nhwc_k<<<gn, dim3(32, 8)>>>(nbr);
    }
    // 1. conv1 (HMMA fp16): 130(192) -> 64, lrelu
    {
        dim3 grid(WW / 64, HH / 4, BB);
        mconv_k<3, 1, 64, 64, false><<<grid, 256, SMEMC>>>(p_x1, p_w1, b1, p_x2, nullptr);
    }
    // 2. conv2 (HMMA fp16): 64 -> 64, lrelu
    {
        dim3 grid(WW / 64, HH / 4, BB);
        mconv_k<1, 4, 64, 64, false><<<grid, 256, SMEMC>>>(p_x2, p_w2, b2, p_x3, nullptr);
    }
    // 3. conv_om (HMMA fp16): 64 -> 216 (3 slices of 72), linear, planar fp32
    {
        dim3 grid(WW / 64, HH / 4, BB * 3);
        mconv_k<1, 4, 72, 216, true><<<grid, 256, SMEMO>>>(p_x3, p_wom, b_om, nullptr, p_om);
    }
    // 4. DCN (HMMA) + lrelu
    {
        dim3 grid(WW / 64, HH / 4, BB);
        dcn_mma_k<<<grid, 256, SMEMD>>>(flows, p_wd, b_dcn, out);
    }
}